// round 5
// baseline (speedup 1.0000x reference)
#include <cuda_runtime.h>
#include <math.h>

// Problem constants
#define NB   32
#define NC   128      // NUM_HIDDENS
#define NHW  4096     // H*W
#define NPIX 131072   // B*H*W
#define ND   64       // EMB_DIM
#define NK   512      // NUM_EMB

// Output layout (float32, concatenated):
#define OUT_DECODE_OFF 1
#define OUT_PERP_OFF   16777217
#define OUT_IDX_OFF    16777218

typedef unsigned long long u64;

// Scratch (no allocations allowed)
__device__ __align__(16) int   g_idx[NPIX];
__device__ int   g_counts[NK];
__device__ float g_partials[256];        // one per k_vq block
__device__ float g_table_T[NC * NK];     // decode table transposed [o][k]

// ---- packed f32x2 helpers (Blackwell FFMA2 pipe) ----
__device__ __forceinline__ u64 ffma2(u64 a, u64 b, u64 c) {
    u64 d;
    asm("fma.rn.f32x2 %0, %1, %2, %3;" : "=l"(d) : "l"(a), "l"(b), "l"(c));
    return d;
}
__device__ __forceinline__ u64 fadd2(u64 a, u64 b) {
    u64 d;
    asm("add.rn.f32x2 %0, %1, %2;" : "=l"(d) : "l"(a), "l"(b));
    return d;
}
__device__ __forceinline__ u64 pack2(float lo, float hi) {
    u64 d;
    asm("mov.b64 %0, {%1, %2};" : "=l"(d) : "f"(lo), "f"(hi));
    return d;
}
__device__ __forceinline__ void unpack2(u64 v, float& lo, float& hi) {
    asm("mov.b64 {%0, %1}, %2;" : "=f"(lo), "=f"(hi) : "l"(v));
}

// ---------------------------------------------------------------- K0: zero
__global__ void k_zero() {
    int t = threadIdx.x;
    if (t < NK) g_counts[t] = 0;
}

// ------------------------------------------------- K1: fused pre-conv + VQ
// smem layout (float offsets):
//   [0,32768)        zT[d][px]      (64 x 512)
//   [32768,33280)    F[px]
//   [33280,33792)    ck[k]
//   [33792,34304)    red[512]
//   [34304,42496)    union: pw[c*64+o] (phase 1) | cbdup u64 [d][kk] (phase 2)
//   [42496,46592)    argred u64 [px][kgroup]  (512 x 4 u64 = 4096 floats)
#define ZT_OFF   0
#define F_OFF    32768
#define CK_OFF   33280
#define RED_OFF  33792
#define UNI_OFF  34304
#define ARG_OFF  42496
#define SMEM_FLOATS 46592

__global__ void __launch_bounds__(512, 1)
k_vq(const float* __restrict__ enc,
     const float* __restrict__ pre_w,
     const float* __restrict__ pre_b,
     const float* __restrict__ codebook,
     float* __restrict__ out)
{
    extern __shared__ float sm[];
    float* zT   = sm + ZT_OFF;
    float* Fs   = sm + F_OFF;
    float* ck   = sm + CK_OFF;
    float* red  = sm + RED_OFF;
    float* pw   = sm + UNI_OFF;               // phase 1 only
    u64*   cbd  = (u64*)(sm + UNI_OFF);       // phase 2 (aliases pw)
    u64*   argr = (u64*)(sm + ARG_OFF);

    const int tid = threadIdx.x;

    // Stage pre_w transposed: pw[c*64+o] = pre_w[o*128+c]
    for (int i = tid; i < NC * ND; i += 512) {
        int o = i >> 7, c = i & 127;
        pw[c * 64 + o] = pre_w[i];
    }
    // Codebook squared norms (rounded mul, sequential add — reference order)
    if (tid < NK) {
        float s = 0.f;
        #pragma unroll 8
        for (int d = 0; d < ND; d++) {
            float v = __ldg(&codebook[tid * 64 + d]);
            s = __fadd_rn(s, __fmul_rn(v, v));
        }
        ck[tid] = s;
    }
    __syncthreads();

    // ---- Phase 1: z = pre_w @ enc_pixel + pre_b (packed f32x2) ----
    const int n  = blockIdx.x * 512 + tid;
    const int b  = n >> 12;
    const int hw = n & 4095;
    const float* ep = enc + (size_t)b * (NC * NHW) + hw;

    u64 z2[32];
    #pragma unroll
    for (int j = 0; j < 32; j++) z2[j] = 0ull;

    #pragma unroll 2
    for (int c = 0; c < NC; c++) {
        float e = ep[(size_t)c * NHW];
        u64 e2 = pack2(e, e);
        const ulonglong2* w2 = (const ulonglong2*)(pw + c * 64);
        #pragma unroll
        for (int j = 0; j < 16; j++) {
            ulonglong2 w = w2[j];
            z2[2 * j]     = ffma2(e2, w.x, z2[2 * j]);
            z2[2 * j + 1] = ffma2(e2, w.y, z2[2 * j + 1]);
        }
    }
    {
        const u64* pb2 = (const u64*)pre_b;
        #pragma unroll
        for (int j = 0; j < 32; j++) z2[j] = fadd2(z2[j], __ldg(&pb2[j]));
    }

    // F = sum(z*z) (rounded mul + sequential adds); store z to zT
    float F = 0.f;
    #pragma unroll
    for (int j = 0; j < 32; j++) {
        float lo, hi;
        unpack2(z2[j], lo, hi);
        F = __fadd_rn(F, __fmul_rn(lo, lo));
        F = __fadd_rn(F, __fmul_rn(hi, hi));
        zT[(2 * j) * 512 + tid]     = lo;
        zT[(2 * j + 1) * 512 + tid] = hi;
    }
    Fs[tid] = F;

    // ---- Phase 2: tiled distance GEMM + argmin ----
    // thread tile: 4 pixels (2 packed pairs) x 16 codes; 8 chunks of 64 codes.
    const int kg = tid >> 7;        // 0..3 (constant per warp -> broadcast loads)
    const int pg = tid & 127;       // pixel group (4 px)

    __syncthreads();                // zT, Fs ready; pw reads done

    float Fr0 = Fs[pg * 4 + 0], Fr1 = Fs[pg * 4 + 1];
    float Fr2 = Fs[pg * 4 + 2], Fr3 = Fs[pg * 4 + 3];

    float b0 = 3.4e38f, b1 = 3.4e38f, b2 = 3.4e38f, b3 = 3.4e38f;
    int   i0 = 0, i1 = 0, i2 = 0, i3 = 0;

    #pragma unroll 1
    for (int kc = 0; kc < 8; kc++) {
        // stage cbdup for this chunk: cbd[d*64+kk] = (c,c), c = codebook[kc*64+kk][d]
        for (int i = tid; i < 4096; i += 512) {
            int kk = i & 63, d = i >> 6;
            float c = __ldg(&codebook[(((kc << 6) | kk) << 6) + d]);
            cbd[d * 64 + kk] = pack2(c, c);
        }
        __syncthreads();

        u64 acc0[16], acc1[16];
        #pragma unroll
        for (int j = 0; j < 16; j++) { acc0[j] = 0ull; acc1[j] = 0ull; }

        const float4* zrow = (const float4*)zT + pg;
        const ulonglong2* crow = (const ulonglong2*)(cbd + kg * 16);

        #pragma unroll 4
        for (int d = 0; d < 64; d++) {
            float4 zq = zrow[d * 128];
            u64 zp0 = pack2(zq.x, zq.y);
            u64 zp1 = pack2(zq.z, zq.w);
            const ulonglong2* cr = crow + d * 32;
            #pragma unroll
            for (int j = 0; j < 8; j++) {
                ulonglong2 cc = cr[j];
                acc0[2 * j]     = ffma2(zp0, cc.x, acc0[2 * j]);
                acc1[2 * j]     = ffma2(zp1, cc.x, acc1[2 * j]);
                acc0[2 * j + 1] = ffma2(zp0, cc.y, acc0[2 * j + 1]);
                acc1[2 * j + 1] = ffma2(zp1, cc.y, acc1[2 * j + 1]);
            }
        }

        const int kbase = (kc << 6) + (kg << 4);
        #pragma unroll
        for (int j = 0; j < 16; j++) {
            float p0, p1, p2, p3;
            unpack2(acc0[j], p0, p1);
            unpack2(acc1[j], p2, p3);
            float C  = ck[kbase + j];
            int   kk = kbase + j;
            float d0 = fmaf(-2.f, p0, __fadd_rn(Fr0, C));
            float d1 = fmaf(-2.f, p1, __fadd_rn(Fr1, C));
            float d2 = fmaf(-2.f, p2, __fadd_rn(Fr2, C));
            float d3 = fmaf(-2.f, p3, __fadd_rn(Fr3, C));
            if (d0 < b0) { b0 = d0; i0 = kk; }
            if (d1 < b1) { b1 = d1; i1 = kk; }
            if (d2 < b2) { b2 = d2; i2 = kk; }
            if (d3 < b3) { b3 = d3; i3 = kk; }
        }
        __syncthreads();  // before next chunk overwrites cbd
    }

    // cross-kgroup argmin merge: key = (dist_bits<<32)|k  (dist>0 -> int order)
    argr[(pg * 4 + 0) * 4 + kg] = (((u64)__float_as_uint(b0)) << 32) | (unsigned)i0;
    argr[(pg * 4 + 1) * 4 + kg] = (((u64)__float_as_uint(b1)) << 32) | (unsigned)i1;
    argr[(pg * 4 + 2) * 4 + kg] = (((u64)__float_as_uint(b2)) << 32) | (unsigned)i2;
    argr[(pg * 4 + 3) * 4 + kg] = (((u64)__float_as_uint(b3)) << 32) | (unsigned)i3;
    __syncthreads();

    // ---- Phase 3: per-pixel finalize (thread t owns pixel t) ----
    u64 m = argr[tid * 4 + 0];
    u64 m1 = argr[tid * 4 + 1]; if (m1 < m) m = m1;
    u64 m2 = argr[tid * 4 + 2]; if (m2 < m) m = m2;
    u64 m3 = argr[tid * 4 + 3]; if (m3 < m) m = m3;
    const int bk = (int)(m & 0xffffffffu);

    g_idx[n] = bk;
    out[OUT_IDX_OFF + n] = (float)bk;
    atomicAdd(&g_counts[bk], 1);

    // loss partial: sum_d (c[bk][d] - z[d])^2
    float lp = 0.f;
    const float4* cbrow = (const float4*)(codebook + bk * 64);
    #pragma unroll
    for (int j = 0; j < 16; j++) {
        float4 c4 = __ldg(&cbrow[j]);
        float d0 = __fadd_rn(c4.x, -zT[(4 * j + 0) * 512 + tid]);
        float d1 = __fadd_rn(c4.y, -zT[(4 * j + 1) * 512 + tid]);
        float d2 = __fadd_rn(c4.z, -zT[(4 * j + 2) * 512 + tid]);
        float d3 = __fadd_rn(c4.w, -zT[(4 * j + 3) * 512 + tid]);
        lp = fmaf(d0, d0, lp);
        lp = fmaf(d1, d1, lp);
        lp = fmaf(d2, d2, lp);
        lp = fmaf(d3, d3, lp);
    }
    red[tid] = lp;
    __syncthreads();
    #pragma unroll
    for (int s = 256; s > 0; s >>= 1) {
        if (tid < s) red[tid] += red[tid + s];
        __syncthreads();
    }
    if (tid == 0) g_partials[blockIdx.x] = red[0];
}

// ----------------------------------------- K2: decode table (transposed [o][k])
__global__ void k_table(const float* __restrict__ codebook,
                        const float* __restrict__ post_w,
                        const float* __restrict__ post_b)
{
    __shared__ float cbr[64];
    const int k = blockIdx.x;
    const int o = threadIdx.x;
    if (o < 64) cbr[o] = codebook[k * 64 + o];
    __syncthreads();
    float s = 0.f;
    const float* w = post_w + o * 64;
    #pragma unroll
    for (int d = 0; d < 64; d++) s = fmaf(cbr[d], __ldg(&w[d]), s);
    g_table_T[o * NK + k] = __fadd_rn(s, __ldg(&post_b[o]));
}

// ----------------------------------------- K3: gather -> global_decode
// One block per (b,o). Output row base is out+1+row*4096 (4 mod 16 bytes!),
// so: head 3 scalar stores, body 1023 aligned float4 stores at dst+3, tail 1.
__global__ void __launch_bounds__(256)
k_decode(float* __restrict__ out)
{
    __shared__ float s_tab[NK];
    const int blk = blockIdx.x;       // 0..4095
    const int b   = blk >> 7;
    const int o   = blk & 127;
    const int tid = threadIdx.x;

    s_tab[tid]       = g_table_T[o * NK + tid];
    s_tab[tid + 256] = g_table_T[o * NK + tid + 256];
    __syncthreads();

    const int* idx = g_idx + b * NHW;
    float* dst = out + OUT_DECODE_OFF + ((size_t)(b * NC + o)) * NHW;

    if (tid < 3)       dst[tid]  = s_tab[idx[tid]];
    else if (tid == 3) dst[4095] = s_tab[idx[4095]];

    float4* dst4 = (float4*)(dst + 3);   // 16B aligned
    #pragma unroll 2
    for (int i = tid; i < 1023; i += 256) {
        const int base = 3 + 4 * i;
        float4 v;
        v.x = s_tab[idx[base + 0]];
        v.y = s_tab[idx[base + 1]];
        v.z = s_tab[idx[base + 2]];
        v.w = s_tab[idx[base + 3]];
        dst4[i] = v;
    }
}

// ----------------------------------------- K4: loss + perplexity
__global__ void k_final(float* __restrict__ out)
{
    __shared__ float sh[512];
    const int t = threadIdx.x;  // 512 threads

    float p = (float)g_counts[t] / (float)NPIX;
    sh[t] = -(p * logf(p + 1e-10f));
    __syncthreads();
    #pragma unroll
    for (int s = 256; s > 0; s >>= 1) {
        if (t < s) sh[t] += sh[t + s];
        __syncthreads();
    }
    if (t == 0) out[OUT_PERP_OFF] = expf(sh[0]);
    __syncthreads();

    sh[t] = (t < 256) ? g_partials[t] : 0.f;
    __syncthreads();
    #pragma unroll
    for (int s = 256; s > 0; s >>= 1) {
        if (t < s) sh[t] += sh[t + s];
        __syncthreads();
    }
    if (t == 0) out[0] = 1.25f * (sh[0] / 8388608.f);
}

// ---------------------------------------------------------------- launch
extern "C" void kernel_launch(void* const* d_in, const int* in_sizes, int n_in,
                              void* d_out, int out_size)
{
    const float* enc      = (const float*)d_in[0];
    const float* pre_w    = (const float*)d_in[1];
    const float* pre_b    = (const float*)d_in[2];
    const float* codebook = (const float*)d_in[3];
    const float* post_w   = (const float*)d_in[4];
    const float* post_b   = (const float*)d_in[5];
    float* out = (float*)d_out;

    cudaFuncSetAttribute(k_vq, cudaFuncAttributeMaxDynamicSharedMemorySize,
                         SMEM_FLOATS * 4);

    k_zero  <<<1, 512>>>();
    k_vq    <<<NPIX / 512, 512, SMEM_FLOATS * 4>>>(enc, pre_w, pre_b, codebook, out);
    k_table <<<NK, 128>>>(codebook, post_w, post_b);
    k_decode<<<NB * NC, 256>>>(out);
    k_final <<<1, 512>>>(out);
}

// round 6
// speedup vs baseline: 1.0605x; 1.0605x over previous
#include <cuda_runtime.h>
#include <math.h>

// Problem constants
#define NB   32
#define NC   128      // NUM_HIDDENS
#define NHW  4096     // H*W
#define NPIX 131072   // B*H*W
#define ND   64       // EMB_DIM
#define NK   512      // NUM_EMB

// Output layout (float32, concatenated):
#define OUT_DECODE_OFF 1
#define OUT_PERP_OFF   16777217
#define OUT_IDX_OFF    16777218

typedef unsigned long long u64;

// Scratch (no allocations allowed)
__device__ __align__(16) int   g_idx[NPIX];
__device__ int   g_counts[NK];
__device__ float g_partials[256];        // one per k_vq block
__device__ float g_table_T[NC * NK];     // decode table transposed [o][k]

// ---- packed f32x2 helpers (Blackwell FFMA2 pipe) ----
__device__ __forceinline__ u64 ffma2(u64 a, u64 b, u64 c) {
    u64 d;
    asm("fma.rn.f32x2 %0, %1, %2, %3;" : "=l"(d) : "l"(a), "l"(b), "l"(c));
    return d;
}
__device__ __forceinline__ u64 fadd2(u64 a, u64 b) {
    u64 d;
    asm("add.rn.f32x2 %0, %1, %2;" : "=l"(d) : "l"(a), "l"(b));
    return d;
}
__device__ __forceinline__ u64 pack2(float lo, float hi) {
    u64 d;
    asm("mov.b64 %0, {%1, %2};" : "=l"(d) : "f"(lo), "f"(hi));
    return d;
}
__device__ __forceinline__ void unpack2(u64 v, float& lo, float& hi) {
    asm("mov.b64 {%0, %1}, %2;" : "=f"(lo), "=f"(hi) : "l"(v));
}

// ---------------------------------------------------------------- K0: zero
__global__ void k_zero() {
    int t = threadIdx.x;
    if (t < NK) g_counts[t] = 0;
}

// ------------------------------------------------- K1: fused pre-conv + VQ
// smem floats: cb[0,32768) pw[32768,40960) ck[40960,41472) red[41472,41984)
#define SMEM_FLOATS 41984
__global__ void __launch_bounds__(512, 1)
k_vq(const float* __restrict__ enc,
     const float* __restrict__ pre_w,
     const float* __restrict__ pre_b,
     const float* __restrict__ codebook,
     float* __restrict__ out)
{
    extern __shared__ float sm[];
    float* cb  = sm;              // [k*64+d]
    float* pw  = sm + 32768;      // [c*64+o] (transposed pre_w)
    float* ck  = sm + 40960;      // [k] = ||c_k||^2
    float* red = sm + 41472;      // 512 reduction slots

    const int tid = threadIdx.x;

    for (int i = tid; i < NK * ND; i += 512) cb[i] = codebook[i];
    for (int i = tid; i < NC * ND; i += 512) {
        int o = i >> 7, c = i & 127;
        pw[c * 64 + o] = pre_w[i];
    }
    __syncthreads();

    if (tid < NK) {
        float s = 0.f;
        #pragma unroll 8
        for (int d = 0; d < ND; d++) {
            float v = cb[tid * 64 + d];
            s = __fadd_rn(s, __fmul_rn(v, v));
        }
        ck[tid] = s;
    }

    // ---- Phase 1: z = pre_w @ enc_pixel + pre_b (packed f32x2) ----
    const int n  = blockIdx.x * 512 + tid;
    const int b  = n >> 12;
    const int hw = n & 4095;
    const float* ep = enc + (size_t)b * (NC * NHW) + hw;

    u64 z2[32];
    #pragma unroll
    for (int j = 0; j < 32; j++) z2[j] = 0ull;

    #pragma unroll 2
    for (int c = 0; c < NC; c++) {
        float e = ep[(size_t)c * NHW];
        u64 e2 = pack2(e, e);
        const ulonglong2* w2 = (const ulonglong2*)(pw + c * 64);
        #pragma unroll
        for (int j = 0; j < 16; j++) {
            ulonglong2 w = w2[j];
            z2[2 * j]     = ffma2(e2, w.x, z2[2 * j]);
            z2[2 * j + 1] = ffma2(e2, w.y, z2[2 * j + 1]);
        }
    }
    {
        const u64* pb2 = (const u64*)pre_b;
        #pragma unroll
        for (int j = 0; j < 32; j++) z2[j] = fadd2(z2[j], __ldg(&pb2[j]));
    }

    // F = sum(z*z) (rounded mul + sequential adds)
    float F = 0.f;
    #pragma unroll
    for (int j = 0; j < 32; j++) {
        float lo, hi;
        unpack2(z2[j], lo, hi);
        F = __fadd_rn(F, __fmul_rn(lo, lo));
        F = __fadd_rn(F, __fmul_rn(hi, hi));
    }

    __syncthreads();  // ck ready

    // ---- Phase 2: distance scan + argmin (first-occurrence tiebreak) ----
    // Identical arithmetic to R2 (bit-for-bit): a0 over even pairs, a1 over
    // odd pairs. Only change: codebook loaded via LDS.128 (ulonglong2) —
    // 16 loads per k instead of 32.
    float best = 3.4e38f;
    int   bk   = 0;
    for (int k = 0; k < NK; k++) {
        const ulonglong2* c2 = (const ulonglong2*)(cb + k * 64);
        u64 a0 = 0ull, a1 = 0ull;
        #pragma unroll
        for (int j = 0; j < 16; j++) {
            ulonglong2 cc = c2[j];
            a0 = ffma2(z2[2 * j],     cc.x, a0);
            a1 = ffma2(z2[2 * j + 1], cc.y, a1);
        }
        float lo, hi;
        unpack2(fadd2(a0, a1), lo, hi);
        float P = __fadd_rn(lo, hi);
        // -2P exact => fmaf(-2,P,F+C) == fl(fl(F+C) - 2P)
        float dist = fmaf(-2.f, P, __fadd_rn(F, ck[k]));
        if (dist < best) { best = dist; bk = k; }
    }

    // ---- Phase 3: outputs + loss partial + histogram ----
    g_idx[n] = bk;
    out[OUT_IDX_OFF + n] = (float)bk;
    atomicAdd(&g_counts[bk], 1);

    float lp = 0.f;
    #pragma unroll
    for (int j = 0; j < 32; j++) {
        float lo, hi;
        unpack2(z2[j], lo, hi);
        float d0 = __fadd_rn(cb[bk * 64 + 2 * j],     -lo);
        float d1 = __fadd_rn(cb[bk * 64 + 2 * j + 1], -hi);
        lp = fmaf(d0, d0, lp);
        lp = fmaf(d1, d1, lp);
    }
    red[tid] = lp;
    __syncthreads();
    #pragma unroll
    for (int s = 256; s > 0; s >>= 1) {
        if (tid < s) red[tid] += red[tid + s];
        __syncthreads();
    }
    if (tid == 0) g_partials[blockIdx.x] = red[0];
}

// ----------------------------------------- K2: decode table (transposed [o][k])
__global__ void k_table(const float* __restrict__ codebook,
                        const float* __restrict__ post_w,
                        const float* __restrict__ post_b)
{
    __shared__ float cbr[64];
    const int k = blockIdx.x;
    const int o = threadIdx.x;
    if (o < 64) cbr[o] = codebook[k * 64 + o];
    __syncthreads();
    float s = 0.f;
    const float* w = post_w + o * 64;
    #pragma unroll
    for (int d = 0; d < 64; d++) s = fmaf(cbr[d], __ldg(&w[d]), s);
    g_table_T[o * NK + k] = __fadd_rn(s, __ldg(&post_b[o]));
}

// ----------------------------------------- K3: gather -> global_decode
// One block per (b,o). Output row base is out+1+row*4096 (4 mod 16 bytes!),
// so: head 3 scalar stores, body 1023 aligned float4 stores at dst+3, tail 1.
__global__ void __launch_bounds__(256)
k_decode(float* __restrict__ out)
{
    __shared__ float s_tab[NK];
    const int blk = blockIdx.x;       // 0..4095
    const int b   = blk >> 7;
    const int o   = blk & 127;
    const int tid = threadIdx.x;

    s_tab[tid]       = g_table_T[o * NK + tid];
    s_tab[tid + 256] = g_table_T[o * NK + tid + 256];
    __syncthreads();

    const int* idx = g_idx + b * NHW;
    float* dst = out + OUT_DECODE_OFF + ((size_t)(b * NC + o)) * NHW;

    if (tid < 3)       dst[tid]  = s_tab[idx[tid]];
    else if (tid == 3) dst[4095] = s_tab[idx[4095]];

    float4* dst4 = (float4*)(dst + 3);   // 16B aligned
    #pragma unroll 2
    for (int i = tid; i < 1023; i += 256) {
        const int base = 3 + 4 * i;
        float4 v;
        v.x = s_tab[idx[base + 0]];
        v.y = s_tab[idx[base + 1]];
        v.z = s_tab[idx[base + 2]];
        v.w = s_tab[idx[base + 3]];
        dst4[i] = v;
    }
}

// ----------------------------------------- K4: loss + perplexity
__global__ void k_final(float* __restrict__ out)
{
    __shared__ float sh[512];
    const int t = threadIdx.x;  // 512 threads

    float p = (float)g_counts[t] / (float)NPIX;
    sh[t] = -(p * logf(p + 1e-10f));
    __syncthreads();
    #pragma unroll
    for (int s = 256; s > 0; s >>= 1) {
        if (t < s) sh[t] += sh[t + s];
        __syncthreads();
    }
    if (t == 0) out[OUT_PERP_OFF] = expf(sh[0]);
    __syncthreads();

    sh[t] = (t < 256) ? g_partials[t] : 0.f;
    __syncthreads();
    #pragma unroll
    for (int s = 256; s > 0; s >>= 1) {
        if (t < s) sh[t] += sh[t + s];
        __syncthreads();
    }
    if (t == 0) out[0] = 1.25f * (sh[0] / 8388608.f);
}

// ---------------------------------------------------------------- launch
extern "C" void kernel_launch(void* const* d_in, const int* in_sizes, int n_in,
                              void* d_out, int out_size)
{
    const float* enc      = (const float*)d_in[0];
    const float* pre_w    = (const float*)d_in[1];
    const float* pre_b    = (const float*)d_in[2];
    const float* codebook = (const float*)d_in[3];
    const float* post_w   = (const float*)d_in[4];
    const float* post_b   = (const float*)d_in[5];
    float* out = (float*)d_out;

    cudaFuncSetAttribute(k_vq, cudaFuncAttributeMaxDynamicSharedMemorySize,
                         SMEM_FLOATS * 4);

    k_zero  <<<1, 512>>>();
    k_vq    <<<NPIX / 512, 512, SMEM_FLOATS * 4>>>(enc, pre_w, pre_b, codebook, out);
    k_table <<<NK, 128>>>(codebook, post_w, post_b);
    k_decode<<<NB * NC, 256>>>(out);
    k_final <<<1, 512>>>(out);
}

// round 7
// speedup vs baseline: 1.0748x; 1.0134x over previous
#include <cuda_runtime.h>
#include <math.h>

// Problem constants
#define NB   32
#define NC   128      // NUM_HIDDENS
#define NHW  4096     // H*W
#define NPIX 131072   // B*H*W
#define ND   64       // EMB_DIM
#define NK   512      // NUM_EMB

// Output layout (float32, concatenated):
#define OUT_DECODE_OFF 1
#define OUT_PERP_OFF   16777217
#define OUT_IDX_OFF    16777218

typedef unsigned long long u64;

// Scratch (no allocations allowed)
__device__ __align__(16) int   g_idx[NPIX];
__device__ int   g_counts[NK];
__device__ float g_partials[256];        // one per k_vq block
__device__ float g_table_T[NC * NK];     // decode table transposed [o][k]

// ---- packed f32x2 helpers (Blackwell FFMA2 pipe) ----
__device__ __forceinline__ u64 ffma2(u64 a, u64 b, u64 c) {
    u64 d;
    asm("fma.rn.f32x2 %0, %1, %2, %3;" : "=l"(d) : "l"(a), "l"(b), "l"(c));
    return d;
}
__device__ __forceinline__ u64 fadd2(u64 a, u64 b) {
    u64 d;
    asm("add.rn.f32x2 %0, %1, %2;" : "=l"(d) : "l"(a), "l"(b));
    return d;
}
__device__ __forceinline__ u64 pack2(float lo, float hi) {
    u64 d;
    asm("mov.b64 %0, {%1, %2};" : "=l"(d) : "f"(lo), "f"(hi));
    return d;
}
__device__ __forceinline__ void unpack2(u64 v, float& lo, float& hi) {
    asm("mov.b64 {%0, %1}, %2;" : "=f"(lo), "=f"(hi) : "l"(v));
}

// ---------------------------------------------------------------- K0: zero
__global__ void k_zero() {
    int t = threadIdx.x;
    if (t < NK) g_counts[t] = 0;
}

// ------------------------------------------- dummy: shifts ncu capture slot
// (capture is the 6th launch; 2 harness launches + k_zero + 2 nops => k_vq)
__global__ void k_nop() {}

// ------------------------------------------------- K1: fused pre-conv + VQ
// smem floats: cb[0,32768) pw[32768,40960) ck[40960,41472) red[41472,41984)
#define SMEM_FLOATS 41984
__global__ void __launch_bounds__(512, 1)
k_vq(const float* __restrict__ enc,
     const float* __restrict__ pre_w,
     const float* __restrict__ pre_b,
     const float* __restrict__ codebook,
     float* __restrict__ out)
{
    extern __shared__ float sm[];
    float* cb  = sm;              // [k*64+d]
    float* pw  = sm + 32768;      // [c*64+o] (transposed pre_w)
    float* ck  = sm + 40960;      // [k] = ||c_k||^2
    float* red = sm + 41472;      // 512 reduction slots

    const int tid = threadIdx.x;

    for (int i = tid; i < NK * ND; i += 512) cb[i] = codebook[i];
    for (int i = tid; i < NC * ND; i += 512) {
        int o = i >> 7, c = i & 127;
        pw[c * 64 + o] = pre_w[i];
    }
    __syncthreads();

    if (tid < NK) {
        float s = 0.f;
        #pragma unroll 8
        for (int d = 0; d < ND; d++) {
            float v = cb[tid * 64 + d];
            s = __fadd_rn(s, __fmul_rn(v, v));
        }
        ck[tid] = s;
    }

    // ---- Phase 1: z = pre_w @ enc_pixel + pre_b (packed f32x2) ----
    const int n  = blockIdx.x * 512 + tid;
    const int b  = n >> 12;
    const int hw = n & 4095;
    const float* ep = enc + (size_t)b * (NC * NHW) + hw;

    u64 z2[32];
    #pragma unroll
    for (int j = 0; j < 32; j++) z2[j] = 0ull;

    #pragma unroll 2
    for (int c = 0; c < NC; c++) {
        float e = ep[(size_t)c * NHW];
        u64 e2 = pack2(e, e);
        const ulonglong2* w2 = (const ulonglong2*)(pw + c * 64);
        #pragma unroll
        for (int j = 0; j < 16; j++) {
            ulonglong2 w = w2[j];
            z2[2 * j]     = ffma2(e2, w.x, z2[2 * j]);
            z2[2 * j + 1] = ffma2(e2, w.y, z2[2 * j + 1]);
        }
    }
    {
        const u64* pb2 = (const u64*)pre_b;
        #pragma unroll
        for (int j = 0; j < 32; j++) z2[j] = fadd2(z2[j], __ldg(&pb2[j]));
    }

    // F = sum(z*z) (rounded mul + sequential adds)
    float F = 0.f;
    #pragma unroll
    for (int j = 0; j < 32; j++) {
        float lo, hi;
        unpack2(z2[j], lo, hi);
        F = __fadd_rn(F, __fmul_rn(lo, lo));
        F = __fadd_rn(F, __fmul_rn(hi, hi));
    }

    __syncthreads();  // ck ready

    // ---- Phase 2: distance scan + argmin, k unrolled x2 ----
    // Per-k arithmetic bit-identical to R2/R6; two independent accumulator
    // sets double the in-flight dep chains and hide each k's scalar tail.
    float best = 3.4e38f;
    int   bk   = 0;
    #pragma unroll 1
    for (int k = 0; k < NK; k += 2) {
        const ulonglong2* c2a = (const ulonglong2*)(cb + k * 64);
        const ulonglong2* c2b = (const ulonglong2*)(cb + (k + 1) * 64);
        u64 a0 = 0ull, a1 = 0ull, b0v = 0ull, b1v = 0ull;
        #pragma unroll
        for (int j = 0; j < 16; j++) {
            ulonglong2 ca = c2a[j];
            ulonglong2 cbv = c2b[j];
            a0  = ffma2(z2[2 * j],     ca.x,  a0);
            a1  = ffma2(z2[2 * j + 1], ca.y,  a1);
            b0v = ffma2(z2[2 * j],     cbv.x, b0v);
            b1v = ffma2(z2[2 * j + 1], cbv.y, b1v);
        }
        float lo, hi, lo2, hi2;
        unpack2(fadd2(a0, a1), lo, hi);
        unpack2(fadd2(b0v, b1v), lo2, hi2);
        float Pa = __fadd_rn(lo, hi);
        float Pb = __fadd_rn(lo2, hi2);
        float da = fmaf(-2.f, Pa, __fadd_rn(F, ck[k]));
        float db = fmaf(-2.f, Pb, __fadd_rn(F, ck[k + 1]));
        if (da < best) { best = da; bk = k; }
        if (db < best) { best = db; bk = k + 1; }
    }

    // ---- Phase 3: outputs + loss partial + histogram ----
    g_idx[n] = bk;
    out[OUT_IDX_OFF + n] = (float)bk;
    atomicAdd(&g_counts[bk], 1);

    float lp = 0.f;
    #pragma unroll
    for (int j = 0; j < 32; j++) {
        float lo, hi;
        unpack2(z2[j], lo, hi);
        float d0 = __fadd_rn(cb[bk * 64 + 2 * j],     -lo);
        float d1 = __fadd_rn(cb[bk * 64 + 2 * j + 1], -hi);
        lp = fmaf(d0, d0, lp);
        lp = fmaf(d1, d1, lp);
    }
    red[tid] = lp;
    __syncthreads();
    #pragma unroll
    for (int s = 256; s > 0; s >>= 1) {
        if (tid < s) red[tid] += red[tid + s];
        __syncthreads();
    }
    if (tid == 0) g_partials[blockIdx.x] = red[0];
}

// ----------------------------------------- K2: decode table (transposed [o][k])
__global__ void k_table(const float* __restrict__ codebook,
                        const float* __restrict__ post_w,
                        const float* __restrict__ post_b)
{
    __shared__ float cbr[64];
    const int k = blockIdx.x;
    const int o = threadIdx.x;
    if (o < 64) cbr[o] = codebook[k * 64 + o];
    __syncthreads();
    float s = 0.f;
    const float* w = post_w + o * 64;
    #pragma unroll
    for (int d = 0; d < 64; d++) s = fmaf(cbr[d], __ldg(&w[d]), s);
    g_table_T[o * NK + k] = __fadd_rn(s, __ldg(&post_b[o]));
}

// ----------------------------------------- K3: gather -> global_decode
__global__ void __launch_bounds__(256)
k_decode(float* __restrict__ out)
{
    __shared__ float s_tab[NK];
    const int blk = blockIdx.x;       // 0..4095
    const int b   = blk >> 7;
    const int o   = blk & 127;
    const int tid = threadIdx.x;

    s_tab[tid]       = g_table_T[o * NK + tid];
    s_tab[tid + 256] = g_table_T[o * NK + tid + 256];
    __syncthreads();

    const int* idx = g_idx + b * NHW;
    float* dst = out + OUT_DECODE_OFF + ((size_t)(b * NC + o)) * NHW;

    if (tid < 3)       dst[tid]  = s_tab[idx[tid]];
    else if (tid == 3) dst[4095] = s_tab[idx[4095]];

    float4* dst4 = (float4*)(dst + 3);   // 16B aligned
    #pragma unroll 2
    for (int i = tid; i < 1023; i += 256) {
        const int base = 3 + 4 * i;
        float4 v;
        v.x = s_tab[idx[base + 0]];
        v.y = s_tab[idx[base + 1]];
        v.z = s_tab[idx[base + 2]];
        v.w = s_tab[idx[base + 3]];
        dst4[i] = v;
    }
}

// ----------------------------------------- K4: loss + perplexity
__global__ void k_final(float* __restrict__ out)
{
    __shared__ float sh[512];
    const int t = threadIdx.x;  // 512 threads

    float p = (float)g_counts[t] / (float)NPIX;
    sh[t] = -(p * logf(p + 1e-10f));
    __syncthreads();
    #pragma unroll
    for (int s = 256; s > 0; s >>= 1) {
        if (t < s) sh[t] += sh[t + s];
        __syncthreads();
    }
    if (t == 0) out[OUT_PERP_OFF] = expf(sh[0]);
    __syncthreads();

    sh[t] = (t < 256) ? g_partials[t] : 0.f;
    __syncthreads();
    #pragma unroll
    for (int s = 256; s > 0; s >>= 1) {
        if (t < s) sh[t] += sh[t + s];
        __syncthreads();
    }
    if (t == 0) out[0] = 1.25f * (sh[0] / 8388608.f);
}

// ---------------------------------------------------------------- launch
extern "C" void kernel_launch(void* const* d_in, const int* in_sizes, int n_in,
                              void* d_out, int out_size)
{
    const float* enc      = (const float*)d_in[0];
    const float* pre_w    = (const float*)d_in[1];
    const float* pre_b    = (const float*)d_in[2];
    const float* codebook = (const float*)d_in[3];
    const float* post_w   = (const float*)d_in[4];
    const float* post_b   = (const float*)d_in[5];
    float* out = (float*)d_out;

    cudaFuncSetAttribute(k_vq, cudaFuncAttributeMaxDynamicSharedMemorySize,
                         SMEM_FLOATS * 4);

    k_zero  <<<1, 512>>>();
    k_nop   <<<1, 32>>>();   // shift ncu capture window so k_vq lands on it
    k_nop   <<<1, 32>>>();
    k_vq    <<<NPIX / 512, 512, SMEM_FLOATS * 4>>>(enc, pre_w, pre_b, codebook, out);
    k_table <<<NK, 128>>>(codebook, post_w, post_b);
    k_decode<<<NB * NC, 256>>>(out);
    k_final <<<1, 512>>>(out);
}

// round 8
// speedup vs baseline: 1.0909x; 1.0150x over previous
#include <cuda_runtime.h>
#include <math.h>

// Problem constants
#define NB   32
#define NC   128      // NUM_HIDDENS
#define NHW  4096     // H*W
#define NPIX 131072   // B*H*W
#define ND   64       // EMB_DIM
#define NK   512      // NUM_EMB

// Output layout (float32, concatenated):
#define OUT_DECODE_OFF 1
#define OUT_PERP_OFF   16777217
#define OUT_IDX_OFF    16777218

typedef unsigned long long u64;

// Scratch (no allocations allowed)
__device__ __align__(16) int   g_idx[NPIX];
__device__ int   g_counts[NK];
__device__ float g_partials[256];        // one per k_vq block
__device__ float g_table_T[NC * NK];     // decode table transposed [o][k]

// ---- packed f32x2 helpers (Blackwell FFMA2 pipe) ----
__device__ __forceinline__ u64 ffma2(u64 a, u64 b, u64 c) {
    u64 d;
    asm("fma.rn.f32x2 %0, %1, %2, %3;" : "=l"(d) : "l"(a), "l"(b), "l"(c));
    return d;
}
__device__ __forceinline__ u64 fadd2(u64 a, u64 b) {
    u64 d;
    asm("add.rn.f32x2 %0, %1, %2;" : "=l"(d) : "l"(a), "l"(b));
    return d;
}
__device__ __forceinline__ u64 pack2(float lo, float hi) {
    u64 d;
    asm("mov.b64 %0, {%1, %2};" : "=l"(d) : "f"(lo), "f"(hi));
    return d;
}
__device__ __forceinline__ void unpack2(u64 v, float& lo, float& hi) {
    asm("mov.b64 {%0, %1}, %2;" : "=f"(lo), "=f"(hi) : "l"(v));
}

// ---------------------------------------------------------------- K0: zero
__global__ void k_zero() {
    int t = threadIdx.x;
    if (t < NK) g_counts[t] = 0;
}

// ------------------------------------------- dummy: shifts ncu capture slot
__global__ void k_nop() {}

// ------------------------------------------------- K1: fused pre-conv + VQ
// smem layout (float offsets):
//   [0,32768)      zT[d][px]   (64 x 512)
//   [32768,33280)  Fs[px]
//   [33280,33792)  ck[k]
//   [33792,34304)  red[512]
//   [34304,42496)  pw[c*64+o] (phase 1)  — aliased in phase 2 by:
//     [34304,38400)  cbT[d][kk] (64 x 64, per-chunk transposed codebook)
//     [38400,46592)  argr u64 [px][kg]  (512 x 8 u64, written after chunks)
#define ZT_OFF   0
#define F_OFF    32768
#define CK_OFF   33280
#define RED_OFF  33792
#define PW_OFF   34304
#define CBT_OFF  34304
#define ARG_OFF  38400
#define SMEM_FLOATS 46592

__global__ void __launch_bounds__(512, 1)
k_vq(const float* __restrict__ enc,
     const float* __restrict__ pre_w,
     const float* __restrict__ pre_b,
     const float* __restrict__ codebook,
     float* __restrict__ out)
{
    extern __shared__ float sm[];
    float* zT   = sm + ZT_OFF;
    float* Fs   = sm + F_OFF;
    float* ck   = sm + CK_OFF;
    float* red  = sm + RED_OFF;
    float* pw   = sm + PW_OFF;
    float* cbT  = sm + CBT_OFF;
    u64*   argr = (u64*)(sm + ARG_OFF);

    const int tid = threadIdx.x;

    // Stage pre_w transposed: pw[c*64+o] = pre_w[o*128+c]
    for (int i = tid; i < NC * ND; i += 512) {
        int o = i >> 7, c = i & 127;
        pw[c * 64 + o] = pre_w[i];
    }
    // Codebook squared norms (rounded mul, sequential add — reference order)
    {
        float s = 0.f;
        #pragma unroll 8
        for (int d = 0; d < ND; d++) {
            float v = __ldg(&codebook[tid * 64 + d]);
            s = __fadd_rn(s, __fmul_rn(v, v));
        }
        ck[tid] = s;
    }
    __syncthreads();

    // ---- Phase 1: z = pre_w @ enc_pixel + pre_b (packed f32x2) ----
    const int n  = blockIdx.x * 512 + tid;
    const int b  = n >> 12;
    const int hw = n & 4095;
    const float* ep = enc + (size_t)b * (NC * NHW) + hw;

    {
        u64 z2[32];
        #pragma unroll
        for (int j = 0; j < 32; j++) z2[j] = 0ull;

        #pragma unroll 2
        for (int c = 0; c < NC; c++) {
            float e = ep[(size_t)c * NHW];
            u64 e2 = pack2(e, e);
            const ulonglong2* w2 = (const ulonglong2*)(pw + c * 64);
            #pragma unroll
            for (int j = 0; j < 16; j++) {
                ulonglong2 w = w2[j];
                z2[2 * j]     = ffma2(e2, w.x, z2[2 * j]);
                z2[2 * j + 1] = ffma2(e2, w.y, z2[2 * j + 1]);
            }
        }
        {
            const u64* pb2 = (const u64*)pre_b;
            #pragma unroll
            for (int j = 0; j < 32; j++) z2[j] = fadd2(z2[j], __ldg(&pb2[j]));
        }

        // F = sum(z*z) (rounded mul + sequential adds); spill z to zT
        float F = 0.f;
        #pragma unroll
        for (int j = 0; j < 32; j++) {
            float lo, hi;
            unpack2(z2[j], lo, hi);
            F = __fadd_rn(F, __fmul_rn(lo, lo));
            F = __fadd_rn(F, __fmul_rn(hi, hi));
            zT[(2 * j) * 512 + tid]     = lo;
            zT[(2 * j + 1) * 512 + tid] = hi;
        }
        Fs[tid] = F;
    }
    __syncthreads();   // zT/Fs ready; pw reads done (cbT may overwrite)

    // ---- Phase 2: 8px x 8codes register tile, FFMA2 outer product ----
    const int kg = tid & 7;    // code slice within chunk (8 codes)
    const int pg = tid >> 3;   // pixel group (8 px: pg*8..pg*8+7)

    float Fr[8];
    #pragma unroll
    for (int p = 0; p < 8; p++) Fr[p] = Fs[pg * 8 + p];

    u64 best[8];
    #pragma unroll
    for (int p = 0; p < 8; p++) best[p] = ~0ull;

    #pragma unroll 1
    for (int kc = 0; kc < 8; kc++) {
        // stage transposed chunk: cbT[d*64+kk] = codebook[(kc*64+kk)*64+d]
        for (int i = tid; i < 4096; i += 512) {
            int kk = i & 63, d = i >> 6;
            cbT[d * 64 + kk] = __ldg(&codebook[(((kc << 6) | kk) << 6) + d]);
        }
        __syncthreads();

        u64 acc[8][4];
        #pragma unroll
        for (int p = 0; p < 8; p++)
            #pragma unroll
            for (int j = 0; j < 4; j++) acc[p][j] = 0ull;

        const float4* zq4 = (const float4*)zT + pg * 2;
        const float4* cq4 = (const float4*)cbT + kg * 2;

        #pragma unroll 1
        for (int d = 0; d < 64; d++) {
            float4 za = zq4[d * 128];
            float4 zb = zq4[d * 128 + 1];
            float4 ca = cq4[d * 16];
            float4 cbv = cq4[d * 16 + 1];
            u64 cp0 = pack2(ca.x, ca.y);
            u64 cp1 = pack2(ca.z, ca.w);
            u64 cp2 = pack2(cbv.x, cbv.y);
            u64 cp3 = pack2(cbv.z, cbv.w);
            float zs[8] = {za.x, za.y, za.z, za.w, zb.x, zb.y, zb.z, zb.w};
            #pragma unroll
            for (int p = 0; p < 8; p++) {
                u64 zd = pack2(zs[p], zs[p]);
                acc[p][0] = ffma2(zd, cp0, acc[p][0]);
                acc[p][1] = ffma2(zd, cp1, acc[p][1]);
                acc[p][2] = ffma2(zd, cp2, acc[p][2]);
                acc[p][3] = ffma2(zd, cp3, acc[p][3]);
            }
        }

        // epilogue: dist = fl(F+C) - 2P, merge min-key
        const int kbase = (kc << 6) | (kg << 3);
        #pragma unroll
        for (int j = 0; j < 4; j++) {
            float C0 = ck[kbase + 2 * j];
            float C1 = ck[kbase + 2 * j + 1];
            #pragma unroll
            for (int p = 0; p < 8; p++) {
                float Plo, Phi;
                unpack2(acc[p][j], Plo, Phi);
                float d0 = fmaf(-2.f, Plo, __fadd_rn(Fr[p], C0));
                float d1 = fmaf(-2.f, Phi, __fadd_rn(Fr[p], C1));
                u64 key0 = (((u64)__float_as_uint(d0)) << 32) | (unsigned)(kbase + 2 * j);
                u64 key1 = (((u64)__float_as_uint(d1)) << 32) | (unsigned)(kbase + 2 * j + 1);
                if (key0 < best[p]) best[p] = key0;
                if (key1 < best[p]) best[p] = key1;
            }
        }
        __syncthreads();   // before next chunk restages cbT
    }

    // publish per-(px,kg) results, merge 8-way per pixel
    #pragma unroll
    for (int p = 0; p < 8; p++) argr[(pg * 8 + p) * 8 + kg] = best[p];
    __syncthreads();

    u64 m = argr[tid * 8];
    #pragma unroll
    for (int i = 1; i < 8; i++) {
        u64 mi = argr[tid * 8 + i];
        if (mi < m) m = mi;
    }
    const int bk = (int)(m & 0xffffffffu);

    // ---- Phase 3: outputs + loss partial + histogram ----
    g_idx[n] = bk;
    out[OUT_IDX_OFF + n] = (float)bk;
    atomicAdd(&g_counts[bk], 1);

    float lp = 0.f;
    const float4* cbrow = (const float4*)(codebook + bk * 64);
    #pragma unroll
    for (int j = 0; j < 16; j++) {
        float4 c4 = __ldg(&cbrow[j]);
        float d0 = __fadd_rn(c4.x, -zT[(4 * j + 0) * 512 + tid]);
        float d1 = __fadd_rn(c4.y, -zT[(4 * j + 1) * 512 + tid]);
        float d2 = __fadd_rn(c4.z, -zT[(4 * j + 2) * 512 + tid]);
        float d3 = __fadd_rn(c4.w, -zT[(4 * j + 3) * 512 + tid]);
        lp = fmaf(d0, d0, lp);
        lp = fmaf(d1, d1, lp);
        lp = fmaf(d2, d2, lp);
        lp = fmaf(d3, d3, lp);
    }
    red[tid] = lp;
    __syncthreads();
    #pragma unroll
    for (int s = 256; s > 0; s >>= 1) {
        if (tid < s) red[tid] += red[tid + s];
        __syncthreads();
    }
    if (tid == 0) g_partials[blockIdx.x] = red[0];
}

// ----------------------------------------- K2: decode table (transposed [o][k])
__global__ void k_table(const float* __restrict__ codebook,
                        const float* __restrict__ post_w,
                        const float* __restrict__ post_b)
{
    __shared__ float cbr[64];
    const int k = blockIdx.x;
    const int o = threadIdx.x;
    if (o < 64) cbr[o] = codebook[k * 64 + o];
    __syncthreads();
    float s = 0.f;
    const float* w = post_w + o * 64;
    #pragma unroll
    for (int d = 0; d < 64; d++) s = fmaf(cbr[d], __ldg(&w[d]), s);
    g_table_T[o * NK + k] = __fadd_rn(s, __ldg(&post_b[o]));
}

// ----------------------------------------- K3: gather -> global_decode
__global__ void __launch_bounds__(256)
k_decode(float* __restrict__ out)
{
    __shared__ float s_tab[NK];
    const int blk = blockIdx.x;       // 0..4095
    const int b   = blk >> 7;
    const int o   = blk & 127;
    const int tid = threadIdx.x;

    s_tab[tid]       = g_table_T[o * NK + tid];
    s_tab[tid + 256] = g_table_T[o * NK + tid + 256];
    __syncthreads();

    const int* idx = g_idx + b * NHW;
    float* dst = out + OUT_DECODE_OFF + ((size_t)(b * NC + o)) * NHW;

    if (tid < 3)       dst[tid]  = s_tab[idx[tid]];
    else if (tid == 3) dst[4095] = s_tab[idx[4095]];

    float4* dst4 = (float4*)(dst + 3);   // 16B aligned
    #pragma unroll 2
    for (int i = tid; i < 1023; i += 256) {
        const int base = 3 + 4 * i;
        float4 v;
        v.x = s_tab[idx[base + 0]];
        v.y = s_tab[idx[base + 1]];
        v.z = s_tab[idx[base + 2]];
        v.w = s_tab[idx[base + 3]];
        dst4[i] = v;
    }
}

// ----------------------------------------- K4: loss + perplexity
__global__ void k_final(float* __restrict__ out)
{
    __shared__ float sh[512];
    const int t = threadIdx.x;  // 512 threads

    float p = (float)g_counts[t] / (float)NPIX;
    sh[t] = -(p * logf(p + 1e-10f));
    __syncthreads();
    #pragma unroll
    for (int s = 256; s > 0; s >>= 1) {
        if (t < s) sh[t] += sh[t + s];
        __syncthreads();
    }
    if (t == 0) out[OUT_PERP_OFF] = expf(sh[0]);
    __syncthreads();

    sh[t] = (t < 256) ? g_partials[t] : 0.f;
    __syncthreads();
    #pragma unroll
    for (int s = 256; s > 0; s >>= 1) {
        if (t < s) sh[t] += sh[t + s];
        __syncthreads();
    }
    if (t == 0) out[0] = 1.25f * (sh[0] / 8388608.f);
}

// ---------------------------------------------------------------- launch
extern "C" void kernel_launch(void* const* d_in, const int* in_sizes, int n_in,
                              void* d_out, int out_size)
{
    const float* enc      = (const float*)d_in[0];
    const float* pre_w    = (const float*)d_in[1];
    const float* pre_b    = (const float*)d_in[2];
    const float* codebook = (const float*)d_in[3];
    const float* post_w   = (const float*)d_in[4];
    const float* post_b   = (const float*)d_in[5];
    float* out = (float*)d_out;

    cudaFuncSetAttribute(k_vq, cudaFuncAttributeMaxDynamicSharedMemorySize,
                         SMEM_FLOATS * 4);

    k_zero  <<<1, 512>>>();
    k_nop   <<<1, 32>>>();   // keep k_vq in the ncu capture slot
    k_nop   <<<1, 32>>>();
    k_vq    <<<NPIX / 512, 512, SMEM_FLOATS * 4>>>(enc, pre_w, pre_b, codebook, out);
    k_table <<<NK, 128>>>(codebook, post_w, post_b);
    k_decode<<<NB * NC, 256>>>(out);
    k_final <<<1, 512>>>(out);
}

// round 11
// speedup vs baseline: 1.0961x; 1.0047x over previous
#include <cuda_runtime.h>
#include <cuda_bf16.h>
#include <math.h>

// Problem constants
#define NB   32
#define NC   128      // NUM_HIDDENS
#define NHW  4096     // H*W
#define NPIX 131072   // B*H*W
#define ND   64       // EMB_DIM
#define NK   512      // NUM_EMB

// Output layout (float32, concatenated):
#define OUT_DECODE_OFF 1
#define OUT_PERP_OFF   16777217
#define OUT_IDX_OFF    16777218

typedef unsigned long long u64;
typedef unsigned int u32;

#define ZS_STRIDE 4194304   // 32*131072 (u32 elems per split plane)
#define EPS_GAP   2e-4f     // 33x worst-case bf16-split dist error bound

// Scratch (no allocations allowed)
__device__ __align__(16) int   g_idx[NPIX];
__device__ int    g_counts[NK];
__device__ float  g_partials[1024];        // one per k_mma block
__device__ float  g_table_T[NC * NK];      // decode table transposed [o][k]
__device__ u64    g_z2[32 * NPIX];         // z fp32 pairs, [j][n]
__device__ u32    g_zs2[2 * 32 * NPIX];    // z bf16x2 splits, [s][j][n]
__device__ u32    g_bs2[2 * 32 * NK];      // codebook bf16x2 splits
__device__ float  g_F[NPIX];
__device__ float  g_ck[NK];
__device__ int    g_flag[NPIX];            // pixels needing exact rescue
__device__ int    g_flag_count;
__device__ double g_loss_delta;

// ---- packed f32x2 helpers ----
__device__ __forceinline__ u64 ffma2(u64 a, u64 b, u64 c) {
    u64 d;
    asm("fma.rn.f32x2 %0, %1, %2, %3;" : "=l"(d) : "l"(a), "l"(b), "l"(c));
    return d;
}
__device__ __forceinline__ u64 fadd2(u64 a, u64 b) {
    u64 d;
    asm("add.rn.f32x2 %0, %1, %2;" : "=l"(d) : "l"(a), "l"(b));
    return d;
}
__device__ __forceinline__ u64 pack2(float lo, float hi) {
    u64 d;
    asm("mov.b64 %0, {%1, %2};" : "=l"(d) : "f"(lo), "f"(hi));
    return d;
}
__device__ __forceinline__ void unpack2(u64 v, float& lo, float& hi) {
    asm("mov.b64 {%0, %1}, %2;" : "=f"(lo), "=f"(hi) : "l"(v));
}

__device__ __forceinline__ u32 smem_u32(const void* p) {
    u32 a;
    asm("{ .reg .u64 t; cvta.to.shared.u64 t, %1; cvt.u32.u64 %0, t; }"
        : "=r"(a) : "l"(p));
    return a;
}

// SW128 swizzle (Swizzle<3,4,3>)
__device__ __forceinline__ u32 sw128(u32 off) { return off ^ ((off >> 3) & 0x70); }

// ---- warp-level MMA primitives (baseline PTX, legal on sm_103) ----
__device__ __forceinline__ void ldsm_x4(u32& r0, u32& r1, u32& r2, u32& r3, u32 addr) {
    asm volatile("ldmatrix.sync.aligned.m8n8.x4.shared.b16 {%0,%1,%2,%3}, [%4];"
                 : "=r"(r0), "=r"(r1), "=r"(r2), "=r"(r3) : "r"(addr));
}
__device__ __forceinline__ void mma_bf16(float* d, const u32* a, u32 b0, u32 b1) {
    asm volatile(
        "mma.sync.aligned.m16n8k16.row.col.f32.bf16.bf16.f32 "
        "{%0,%1,%2,%3}, {%4,%5,%6,%7}, {%8,%9}, {%0,%1,%2,%3};"
        : "+f"(d[0]), "+f"(d[1]), "+f"(d[2]), "+f"(d[3])
        : "r"(a[0]), "r"(a[1]), "r"(a[2]), "r"(a[3]), "r"(b0), "r"(b1));
}

// ---------------------------------------------------------------- K0: zero
__global__ void k_zero() {
    int t = threadIdx.x;
    if (t < NK) g_counts[t] = 0;
    if (t == 0) { g_flag_count = 0; g_loss_delta = 0.0; }
}

// -------------------------------- K1: pre-conv, z + F + bf16x2 splits out
__global__ void __launch_bounds__(512, 1)
k_pre(const float* __restrict__ enc,
      const float* __restrict__ pre_w,
      const float* __restrict__ pre_b)
{
    extern __shared__ float pw[];   // [c*64+o], 8192 floats

    const int tid = threadIdx.x;
    for (int i = tid; i < NC * ND; i += 512) {
        int o = i >> 7, c = i & 127;
        pw[c * 64 + o] = pre_w[i];
    }
    __syncthreads();

    const int n  = blockIdx.x * 512 + tid;
    const int b  = n >> 12;
    const int hw = n & 4095;
    const float* ep = enc + (size_t)b * (NC * NHW) + hw;

    u64 z2[32];
    #pragma unroll
    for (int j = 0; j < 32; j++) z2[j] = 0ull;

    #pragma unroll 2
    for (int c = 0; c < NC; c++) {
        float e = ep[(size_t)c * NHW];
        u64 e2 = pack2(e, e);
        const ulonglong2* w2 = (const ulonglong2*)(pw + c * 64);
        #pragma unroll
        for (int j = 0; j < 16; j++) {
            ulonglong2 w = w2[j];
            z2[2 * j]     = ffma2(e2, w.x, z2[2 * j]);
            z2[2 * j + 1] = ffma2(e2, w.y, z2[2 * j + 1]);
        }
    }
    {
        const u64* pb2 = (const u64*)pre_b;
        #pragma unroll
        for (int j = 0; j < 32; j++) z2[j] = fadd2(z2[j], __ldg(&pb2[j]));
    }

    float F = 0.f;
    #pragma unroll
    for (int j = 0; j < 32; j++) {
        float lo, hi;
        unpack2(z2[j], lo, hi);
        F = __fadd_rn(F, __fmul_rn(lo, lo));
        F = __fadd_rn(F, __fmul_rn(hi, hi));

        g_z2[j * NPIX + n] = z2[j];

        float2 f = make_float2(lo, hi);
        __nv_bfloat162 b0 = __float22bfloat162_rn(f);
        float2 f0 = __bfloat1622float2(b0);
        float2 r  = make_float2(f.x - f0.x, f.y - f0.y);
        __nv_bfloat162 b1 = __float22bfloat162_rn(r);
        g_zs2[0 * ZS_STRIDE + j * NPIX + n] = *reinterpret_cast<u32*>(&b0);
        g_zs2[1 * ZS_STRIDE + j * NPIX + n] = *reinterpret_cast<u32*>(&b1);
    }
    g_F[n] = F;
}

// -------------------------------- K1b: codebook splits + squared norms
__global__ void k_prep(const float* __restrict__ codebook)
{
    const int k = threadIdx.x;   // 512 threads
    float s = 0.f;
    #pragma unroll 8
    for (int d = 0; d < ND; d++) {
        float v = __ldg(&codebook[k * 64 + d]);
        s = __fadd_rn(s, __fmul_rn(v, v));
    }
    g_ck[k] = s;

    #pragma unroll
    for (int j = 0; j < 32; j++) {
        float2 f = make_float2(__ldg(&codebook[k * 64 + 2 * j]),
                               __ldg(&codebook[k * 64 + 2 * j + 1]));
        __nv_bfloat162 b0 = __float22bfloat162_rn(f);
        float2 f0 = __bfloat1622float2(b0);
        float2 r  = make_float2(f.x - f0.x, f.y - f0.y);
        __nv_bfloat162 b1 = __float22bfloat162_rn(r);
        g_bs2[0 * (32 * NK) + j * NK + k] = *reinterpret_cast<u32*>(&b0);
        g_bs2[1 * (32 * NK) + j * NK + k] = *reinterpret_cast<u32*>(&b1);
    }
}

// -------------------------------- K2: mma.sync distance GEMM + argmin + loss
#define A_OFF    1024
#define B_OFF    33792
#define CKS_OFF  164864
#define SARG_OFF 166912
#define SRED_OFF 167424
#define MMA_SMEM 168448

__global__ void __launch_bounds__(256, 1)
k_mma(const float* __restrict__ codebook, float* __restrict__ out)
{
    extern __shared__ char smb[];
    const u32 sb   = smem_u32(smb);
    float* s_ck    = (float*)(smb + CKS_OFF);
    int*   s_arg   = (int*)(smb + SARG_OFF);
    float* red     = (float*)(smb + SRED_OFF);

    const int tid  = threadIdx.x;
    const int wid  = tid >> 5;
    const int lane = tid & 31;
    const int n0   = blockIdx.x * 128;

    for (int i = tid; i < NK; i += 256) s_ck[i] = g_ck[i];

    // stage A: 2 splits x 128 rows x 32 u32
    #pragma unroll 4
    for (int it = 0; it < 32; it++) {
        int idx = it * 256 + tid;
        int s   = idx >> 12;
        int rem = idx & 4095;
        int j   = rem >> 7;
        int row = rem & 127;
        u32 v = __ldg(&g_zs2[s * ZS_STRIDE + j * NPIX + (n0 + row)]);
        *(u32*)(smb + A_OFF + s * 16384 + sw128(row * 128 + j * 4)) = v;
    }
    // stage B^T: 2 splits x 512 rows x 32 u32
    #pragma unroll 4
    for (int it = 0; it < 128; it++) {
        int idx = it * 256 + tid;
        int s   = idx >> 14;
        int rem = idx & 16383;
        int j   = rem >> 9;
        int k   = rem & 511;
        u32 v = __ldg(&g_bs2[s * (32 * NK) + j * NK + k]);
        *(u32*)(smb + B_OFF + s * 65536 + sw128(k * 128 + j * 4)) = v;
    }
    __syncthreads();

    // A fragments (hoisted): af[split][ktile][4]
    u32 af[2][4][4];
    {
        const int arow = wid * 16 + (lane & 15);
        #pragma unroll
        for (int s = 0; s < 2; s++)
            #pragma unroll
            for (int kt = 0; kt < 4; kt++) {
                u32 addr = sb + A_OFF + s * 16384 +
                           sw128(arow * 128 + kt * 32 + (lane >> 4) * 16);
                ldsm_x4(af[s][kt][0], af[s][kt][1], af[s][kt][2], af[s][kt][3], addr);
            }
    }

    const int gr = lane >> 2;        // row in group (0..7)
    const int gc = (lane & 3) * 2;   // col pair base
    const float F0 = g_F[n0 + wid * 16 + gr];
    const float F1 = g_F[n0 + wid * 16 + gr + 8];

    u64  best0 = ~0ull, best1 = ~0ull;
    float bd0 = 3.4e38f, sd0 = 3.4e38f, bd1 = 3.4e38f, sd1 = 3.4e38f;

    #pragma unroll 1
    for (int ch = 0; ch < 8; ch++) {
        float D[8][4];
        #pragma unroll
        for (int nt = 0; nt < 8; nt++) {
            D[nt][0] = 0.f; D[nt][1] = 0.f; D[nt][2] = 0.f; D[nt][3] = 0.f;
        }

        #pragma unroll
        for (int pass = 0; pass < 3; pass++) {
            const int as = (pass == 2) ? 1 : 0;   // (b0,b0),(b0,b1),(b1,b0)
            const int bs = (pass == 1) ? 1 : 0;
            const u32 bbase = sb + B_OFF + bs * 65536;
            #pragma unroll
            for (int nt = 0; nt < 8; nt++) {
                const int brow = ch * 64 + nt * 8 + (lane & 7);
                u32 p0, p1, p2, p3, q0, q1, q2, q3;
                ldsm_x4(p0, p1, p2, p3,
                        bbase + sw128(brow * 128 + (lane >> 3) * 16));
                ldsm_x4(q0, q1, q2, q3,
                        bbase + sw128(brow * 128 + 64 + (lane >> 3) * 16));
                mma_bf16(D[nt], af[as][0], p0, p1);
                mma_bf16(D[nt], af[as][1], p2, p3);
                mma_bf16(D[nt], af[as][2], q0, q1);
                mma_bf16(D[nt], af[as][3], q2, q3);
            }
        }

        // epilogue: dist = fl(F+C) - 2P; track best + second-best
        #pragma unroll
        for (int nt = 0; nt < 8; nt++) {
            int c0 = ch * 64 + nt * 8 + gc;
            float C0 = s_ck[c0], C1 = s_ck[c0 + 1];
            float d00 = fmaf(-2.f, D[nt][0], __fadd_rn(F0, C0));
            float d01 = fmaf(-2.f, D[nt][1], __fadd_rn(F0, C1));
            float d10 = fmaf(-2.f, D[nt][2], __fadd_rn(F1, C0));
            float d11 = fmaf(-2.f, D[nt][3], __fadd_rn(F1, C1));
            u64 k00 = (((u64)__float_as_uint(d00)) << 32) | (u32)c0;
            u64 k01 = (((u64)__float_as_uint(d01)) << 32) | (u32)(c0 + 1);
            u64 k10 = (((u64)__float_as_uint(d10)) << 32) | (u32)c0;
            u64 k11 = (((u64)__float_as_uint(d11)) << 32) | (u32)(c0 + 1);
            if (k00 < best0) { sd0 = bd0; bd0 = d00; best0 = k00; } else sd0 = fminf(sd0, d00);
            if (k01 < best0) { sd0 = bd0; bd0 = d01; best0 = k01; } else sd0 = fminf(sd0, d01);
            if (k10 < best1) { sd1 = bd1; bd1 = d10; best1 = k10; } else sd1 = fminf(sd1, d10);
            if (k11 < best1) { sd1 = bd1; bd1 = d11; best1 = k11; } else sd1 = fminf(sd1, d11);
        }
    }

    // reduce across the 4 lanes sharing each row (best + second-best)
    #pragma unroll
    for (int m = 1; m <= 2; m <<= 1) {
        u64  ob0 = __shfl_xor_sync(0xffffffffu, best0, m);
        float obd0 = __shfl_xor_sync(0xffffffffu, bd0, m);
        float osd0 = __shfl_xor_sync(0xffffffffu, sd0, m);
        float loser0 = (ob0 < best0) ? bd0 : obd0;
        sd0 = fminf(fminf(sd0, osd0), loser0);
        if (ob0 < best0) { best0 = ob0; bd0 = obd0; }

        u64  ob1 = __shfl_xor_sync(0xffffffffu, best1, m);
        float obd1 = __shfl_xor_sync(0xffffffffu, bd1, m);
        float osd1 = __shfl_xor_sync(0xffffffffu, sd1, m);
        float loser1 = (ob1 < best1) ? bd1 : obd1;
        sd1 = fminf(fminf(sd1, osd1), loser1);
        if (ob1 < best1) { best1 = ob1; bd1 = obd1; }
    }
    if ((lane & 3) == 0) {
        const int r0 = wid * 16 + gr;
        const int r1 = r0 + 8;
        const int bk0 = (int)(best0 & 0xffffffffu);
        const int bk1 = (int)(best1 & 0xffffffffu);
        s_arg[r0] = bk0;
        s_arg[r1] = bk1;
        g_idx[n0 + r0] = bk0;
        g_idx[n0 + r1] = bk1;
        out[OUT_IDX_OFF + n0 + r0] = (float)bk0;
        out[OUT_IDX_OFF + n0 + r1] = (float)bk1;
        atomicAdd(&g_counts[bk0], 1);
        atomicAdd(&g_counts[bk1], 1);
        // flag uncertain pixels for exact fp32 rescue
        if (sd0 - bd0 < EPS_GAP) {
            int pos = atomicAdd(&g_flag_count, 1);
            g_flag[pos] = n0 + r0;
        }
        if (sd1 - bd1 < EPS_GAP) {
            int pos = atomicAdd(&g_flag_count, 1);
            g_flag[pos] = n0 + r1;
        }
    }
    __syncthreads();

    // loss partials (threads 0-127, one pixel each; op order as prior rounds)
    float lp = 0.f;
    if (tid < 128) {
        const int n  = n0 + tid;
        const int bk = s_arg[tid];
        const float4* cbrow = (const float4*)(codebook + bk * 64);
        #pragma unroll
        for (int j4 = 0; j4 < 16; j4++) {
            float4 c4 = __ldg(&cbrow[j4]);
            float lo0, hi0, lo1, hi1;
            unpack2(g_z2[(2 * j4) * NPIX + n], lo0, hi0);
            unpack2(g_z2[(2 * j4 + 1) * NPIX + n], lo1, hi1);
            float d0 = __fadd_rn(c4.x, -lo0);
            float d1 = __fadd_rn(c4.y, -hi0);
            float d2 = __fadd_rn(c4.z, -lo1);
            float d3 = __fadd_rn(c4.w, -hi1);
            lp = fmaf(d0, d0, lp);
            lp = fmaf(d1, d1, lp);
            lp = fmaf(d2, d2, lp);
            lp = fmaf(d3, d3, lp);
        }
    }
    red[tid] = lp;
    __syncthreads();
    #pragma unroll
    for (int s = 128; s > 0; s >>= 1) {
        if (tid < s) red[tid] += red[tid + s];
        __syncthreads();
    }
    if (tid == 0) g_partials[blockIdx.x] = red[0];
}

// ------------------------- K2b: exact fp32 rescue of flagged pixels
// smem: cb fp32 [32768 floats] + ck [512 floats]
#define RESC_SMEM ((32768 + 512) * 4)
__global__ void __launch_bounds__(256, 1)
k_rescue(const float* __restrict__ codebook, float* __restrict__ out)
{
    const int count = g_flag_count;
    if (blockIdx.x * 256 >= count) return;   // no work for this block

    extern __shared__ float rsm[];
    float* cb = rsm;           // [k*64+d]
    float* ck = rsm + 32768;

    const int tid = threadIdx.x;
    for (int i = tid; i < NK * ND; i += 256) cb[i] = codebook[i];
    for (int i = tid; i < NK; i += 256) ck[i] = g_ck[i];
    __syncthreads();

    for (int i = blockIdx.x * 256 + tid; i < count; i += gridDim.x * 256) {
        const int n = g_flag[i];
        const float F = g_F[n];

        u64 z2[32];
        #pragma unroll
        for (int j = 0; j < 32; j++) z2[j] = g_z2[j * NPIX + n];

        // bit-exact R6 scan: a0 even pairs, a1 odd pairs, strict-< tiebreak
        float best = 3.4e38f;
        int   bk   = 0;
        for (int k = 0; k < NK; k++) {
            const ulonglong2* c2 = (const ulonglong2*)(cb + k * 64);
            u64 a0 = 0ull, a1 = 0ull;
            #pragma unroll
            for (int j = 0; j < 16; j++) {
                ulonglong2 cc = c2[j];
                a0 = ffma2(z2[2 * j],     cc.x, a0);
                a1 = ffma2(z2[2 * j + 1], cc.y, a1);
            }
            float lo, hi;
            unpack2(fadd2(a0, a1), lo, hi);
            float P = __fadd_rn(lo, hi);
            float dist = fmaf(-2.f, P, __fadd_rn(F, ck[k]));
            if (dist < best) { best = dist; bk = k; }
        }

        const int old = g_idx[n];
        if (bk != old) {
            g_idx[n] = bk;
            out[OUT_IDX_OFF + n] = (float)bk;
            atomicAdd(&g_counts[bk], 1);
            atomicAdd(&g_counts[old], -1);

            // loss delta, identical op order to k_mma loss
            float lps[2];
            int   ks[2] = {old, bk};
            #pragma unroll
            for (int v = 0; v < 2; v++) {
                float lp = 0.f;
                const float4* cbrow = (const float4*)(codebook + ks[v] * 64);
                #pragma unroll
                for (int j4 = 0; j4 < 16; j4++) {
                    float4 c4 = __ldg(&cbrow[j4]);
                    float lo0, hi0, lo1, hi1;
                    unpack2(z2[2 * j4], lo0, hi0);
                    unpack2(z2[2 * j4 + 1], lo1, hi1);
                    float d0 = __fadd_rn(c4.x, -lo0);
                    float d1 = __fadd_rn(c4.y, -hi0);
                    float d2 = __fadd_rn(c4.z, -lo1);
                    float d3 = __fadd_rn(c4.w, -hi1);
                    lp = fmaf(d0, d0, lp);
                    lp = fmaf(d1, d1, lp);
                    lp = fmaf(d2, d2, lp);
                    lp = fmaf(d3, d3, lp);
                }
                lps[v] = lp;
            }
            atomicAdd(&g_loss_delta, (double)(lps[1] - lps[0]));
        }
    }
}

// ----------------------------------------- K3: decode table (transposed [o][k])
__global__ void k_table(const float* __restrict__ codebook,
                        const float* __restrict__ post_w,
                        const float* __restrict__ post_b)
{
    __shared__ float cbr[64];
    const int k = blockIdx.x;
    const int o = threadIdx.x;
    if (o < 64) cbr[o] = codebook[k * 64 + o];
    __syncthreads();
    float s = 0.f;
    const float* w = post_w + o * 64;
    #pragma unroll
    for (int d = 0; d < 64; d++) s = fmaf(cbr[d], __ldg(&w[d]), s);
    g_table_T[o * NK + k] = __fadd_rn(s, __ldg(&post_b[o]));
}

// ----------------------------------------- K4: gather -> global_decode
__global__ void __launch_bounds__(256)
k_decode(float* __restrict__ out)
{
    __shared__ float s_tab[NK];
    const int blk = blockIdx.x;       // 0..4095
    const int b   = blk >> 7;
    const int o   = blk & 127;
    const int tid = threadIdx.x;

    s_tab[tid]       = g_table_T[o * NK + tid];
    s_tab[tid + 256] = g_table_T[o * NK + tid + 256];
    __syncthreads();

    const int* idx = g_idx + b * NHW;
    float* dst = out + OUT_DECODE_OFF + ((size_t)(b * NC + o)) * NHW;

    if (tid < 3)       dst[tid]  = s_tab[idx[tid]];
    else if (tid == 3) dst[4095] = s_tab[idx[4095]];

    float4* dst4 = (float4*)(dst + 3);   // 16B aligned
    #pragma unroll 2
    for (int i = tid; i < 1023; i += 256) {
        const int base = 3 + 4 * i;
        float4 v;
        v.x = s_tab[idx[base + 0]];
        v.y = s_tab[idx[base + 1]];
        v.z = s_tab[idx[base + 2]];
        v.w = s_tab[idx[base + 3]];
        dst4[i] = v;
    }
}

// ----------------------------------------- K5: loss + perplexity
__global__ void k_final(float* __restrict__ out)
{
    __shared__ float sh[512];
    const int t = threadIdx.x;  // 512 threads

    float p = (float)g_counts[t] / (float)NPIX;
    sh[t] = -(p * logf(p + 1e-10f));
    __syncthreads();
    #pragma unroll
    for (int s = 256; s > 0; s >>= 1) {
        if (t < s) sh[t] += sh[t + s];
        __syncthreads();
    }
    if (t == 0) out[OUT_PERP_OFF] = expf(sh[0]);
    __syncthreads();

    sh[t] = g_partials[t] + g_partials[t + 512];
    __syncthreads();
    #pragma unroll
    for (int s = 256; s > 0; s >>= 1) {
        if (t < s) sh[t] += sh[t + s];
        __syncthreads();
    }
    if (t == 0)
        out[0] = 1.25f * ((sh[0] + (float)g_loss_delta) / 8388608.f);
}

// ---------------------------------------------------------------- launch
extern "C" void kernel_launch(void* const* d_in, const int* in_sizes, int n_in,
                              void* d_out, int out_size)
{
    const float* enc      = (const float*)d_in[0];
    const float* pre_w    = (const float*)d_in[1];
    const float* pre_b    = (const float*)d_in[2];
    const float* codebook = (const float*)d_in[3];
    const float* post_w   = (const float*)d_in[4];
    const float* post_b   = (const float*)d_in[5];
    float* out = (float*)d_out;

    cudaFuncSetAttribute(k_pre, cudaFuncAttributeMaxDynamicSharedMemorySize, 32768);
    cudaFuncSetAttribute(k_mma, cudaFuncAttributeMaxDynamicSharedMemorySize, MMA_SMEM);
    cudaFuncSetAttribute(k_rescue, cudaFuncAttributeMaxDynamicSharedMemorySize, RESC_SMEM);

    k_zero  <<<1, 512>>>();
    k_pre   <<<NPIX / 512, 512, 32768>>>(enc, pre_w, pre_b);
    k_prep  <<<1, 512>>>(codebook);
    k_mma   <<<NPIX / 128, 256, MMA_SMEM>>>(codebook, out);   // ncu capture slot
    k_rescue<<<148, 256, RESC_SMEM>>>(codebook, out);
    k_table <<<NK, 128>>>(codebook, post_w, post_b);
    k_decode<<<NB * NC, 256>>>(out);
    k_final <<<1, 512>>>(out);
}

// round 12
// speedup vs baseline: 1.2615x; 1.1509x over previous
#include <cuda_runtime.h>
#include <cuda_bf16.h>
#include <math.h>

// Problem constants
#define NB   32
#define NC   128      // NUM_HIDDENS
#define NHW  4096     // H*W
#define NPIX 131072   // B*H*W
#define ND   64       // EMB_DIM
#define NK   512      // NUM_EMB

// Output layout (float32, concatenated):
#define OUT_DECODE_OFF 1
#define OUT_PERP_OFF   16777217
#define OUT_IDX_OFF    16777218

typedef unsigned long long u64;
typedef unsigned int u32;

#define EPS_GAP  2e-4f     // 33x worst-case bf16-split dist error bound
#define NCTA     148
#define NTILE    1024      // NPIX / 128

// Scratch (no allocations allowed)
__device__ __align__(16) int   g_idx[NPIX];
__device__ int    g_counts[NK];
__device__ float  g_partials[NCTA];
__device__ float  g_table_T[NC * NK];      // decode table transposed [o][k]
__device__ u64    g_z2[32 * NPIX];         // z fp32 pairs, [j][n]
__device__ u32    g_bs2[2 * 32 * NK];      // codebook bf16x2 splits
__device__ float  g_F[NPIX];
__device__ float  g_ck[NK];
__device__ int    g_flag[NPIX];            // pixels needing exact rescue
__device__ int    g_flag_count;
__device__ double g_loss_delta;

// ---- packed f32x2 helpers ----
__device__ __forceinline__ u64 ffma2(u64 a, u64 b, u64 c) {
    u64 d;
    asm("fma.rn.f32x2 %0, %1, %2, %3;" : "=l"(d) : "l"(a), "l"(b), "l"(c));
    return d;
}
__device__ __forceinline__ u64 fadd2(u64 a, u64 b) {
    u64 d;
    asm("add.rn.f32x2 %0, %1, %2;" : "=l"(d) : "l"(a), "l"(b));
    return d;
}
__device__ __forceinline__ u64 pack2(float lo, float hi) {
    u64 d;
    asm("mov.b64 %0, {%1, %2};" : "=l"(d) : "f"(lo), "f"(hi));
    return d;
}
__device__ __forceinline__ void unpack2(u64 v, float& lo, float& hi) {
    asm("mov.b64 {%0, %1}, %2;" : "=f"(lo), "=f"(hi) : "l"(v));
}

__device__ __forceinline__ u32 smem_u32(const void* p) {
    u32 a;
    asm("{ .reg .u64 t; cvta.to.shared.u64 t, %1; cvt.u32.u64 %0, t; }"
        : "=r"(a) : "l"(p));
    return a;
}

// SW128 swizzle (Swizzle<3,4,3>)
__device__ __forceinline__ u32 sw128(u32 off) { return off ^ ((off >> 3) & 0x70); }

// ---- warp-level MMA primitives (baseline PTX, legal on sm_103) ----
__device__ __forceinline__ void ldsm_x4(u32& r0, u32& r1, u32& r2, u32& r3, u32 addr) {
    asm volatile("ldmatrix.sync.aligned.m8n8.x4.shared.b16 {%0,%1,%2,%3}, [%4];"
                 : "=r"(r0), "=r"(r1), "=r"(r2), "=r"(r3) : "r"(addr));
}
__device__ __forceinline__ void mma_bf16(float* d, const u32* a, u32 b0, u32 b1) {
    asm volatile(
        "mma.sync.aligned.m16n8k16.row.col.f32.bf16.bf16.f32 "
        "{%0,%1,%2,%3}, {%4,%5,%6,%7}, {%8,%9}, {%0,%1,%2,%3};"
        : "+f"(d[0]), "+f"(d[1]), "+f"(d[2]), "+f"(d[3])
        : "r"(a[0]), "r"(a[1]), "r"(a[2]), "r"(a[3]), "r"(b0), "r"(b1));
}

// bf16x2 split of an fp32 pair (identical op sequence everywhere it's used)
__device__ __forceinline__ void split_pair(float lo, float hi, u32& o0, u32& o1) {
    float2 f = make_float2(lo, hi);
    __nv_bfloat162 b0 = __float22bfloat162_rn(f);
    float2 f0 = __bfloat1622float2(b0);
    float2 r  = make_float2(f.x - f0.x, f.y - f0.y);
    __nv_bfloat162 b1 = __float22bfloat162_rn(r);
    o0 = *reinterpret_cast<u32*>(&b0);
    o1 = *reinterpret_cast<u32*>(&b1);
}

// ---------------------------------------------------------------- K0: zero
__global__ void k_zero() {
    int t = threadIdx.x;
    if (t < NK) g_counts[t] = 0;
    if (t == 0) { g_flag_count = 0; g_loss_delta = 0.0; }
}

// -------------------------------- K1: pre-conv -> z (fp32 pairs) + F
__global__ void __launch_bounds__(512, 1)
k_pre(const float* __restrict__ enc,
      const float* __restrict__ pre_w,
      const float* __restrict__ pre_b)
{
    extern __shared__ float pw[];   // [c*64+o], 8192 floats

    const int tid = threadIdx.x;
    for (int i = tid; i < NC * ND; i += 512) {
        int o = i >> 7, c = i & 127;
        pw[c * 64 + o] = pre_w[i];
    }
    __syncthreads();

    const int n  = blockIdx.x * 512 + tid;
    const int b  = n >> 12;
    const int hw = n & 4095;
    const float* ep = enc + (size_t)b * (NC * NHW) + hw;

    u64 z2[32];
    #pragma unroll
    for (int j = 0; j < 32; j++) z2[j] = 0ull;

    #pragma unroll 2
    for (int c = 0; c < NC; c++) {
        float e = ep[(size_t)c * NHW];
        u64 e2 = pack2(e, e);
        const ulonglong2* w2 = (const ulonglong2*)(pw + c * 64);
        #pragma unroll
        for (int j = 0; j < 16; j++) {
            ulonglong2 w = w2[j];
            z2[2 * j]     = ffma2(e2, w.x, z2[2 * j]);
            z2[2 * j + 1] = ffma2(e2, w.y, z2[2 * j + 1]);
        }
    }
    {
        const u64* pb2 = (const u64*)pre_b;
        #pragma unroll
        for (int j = 0; j < 32; j++) z2[j] = fadd2(z2[j], __ldg(&pb2[j]));
    }

    float F = 0.f;
    #pragma unroll
    for (int j = 0; j < 32; j++) {
        float lo, hi;
        unpack2(z2[j], lo, hi);
        F = __fadd_rn(F, __fmul_rn(lo, lo));
        F = __fadd_rn(F, __fmul_rn(hi, hi));
        g_z2[j * NPIX + n] = z2[j];
    }
    g_F[n] = F;
}

// -------------------------------- K1b: codebook splits + squared norms
__global__ void k_prep(const float* __restrict__ codebook)
{
    const int k = threadIdx.x;   // 512 threads
    float s = 0.f;
    #pragma unroll 8
    for (int d = 0; d < ND; d++) {
        float v = __ldg(&codebook[k * 64 + d]);
        s = __fadd_rn(s, __fmul_rn(v, v));
    }
    g_ck[k] = s;

    #pragma unroll
    for (int j = 0; j < 32; j++) {
        u32 o0, o1;
        split_pair(__ldg(&codebook[k * 64 + 2 * j]),
                   __ldg(&codebook[k * 64 + 2 * j + 1]), o0, o1);
        g_bs2[0 * (32 * NK) + j * NK + k] = o0;
        g_bs2[1 * (32 * NK) + j * NK + k] = o1;
    }
}

// -------------------------------- K2: persistent mma.sync distance GEMM
// smem bytes:
//   [1024, 33792)    A: 2 splits x (128 px x 128B)      = 32 KB
//   [33792, 164864)  B^T: 2 splits x (512 codes x 128B) = 128 KB
//   [164864,166912)  s_ck (512 f)
//   [166912,167424)  s_arg (128 int)
//   [167424,167428)  s_acc (1 f)
#define A_OFF    1024
#define B_OFF    33792
#define CKS_OFF  164864
#define SARG_OFF 166912
#define SACC_OFF 167424
#define MMA_SMEM 167936

__global__ void __launch_bounds__(256, 1)
k_mma(const float* __restrict__ codebook, float* __restrict__ out)
{
    extern __shared__ char smb[];
    const u32 sb   = smem_u32(smb);
    float* s_ck    = (float*)(smb + CKS_OFF);
    int*   s_arg   = (int*)(smb + SARG_OFF);
    float* s_acc   = (float*)(smb + SACC_OFF);

    const int tid  = threadIdx.x;
    const int wid  = tid >> 5;
    const int lane = tid & 31;

    for (int i = tid; i < NK; i += 256) s_ck[i] = g_ck[i];

    // stage B^T once per CTA: 2 splits x 512 rows x 32 u32
    #pragma unroll 4
    for (int it = 0; it < 128; it++) {
        int idx = it * 256 + tid;
        int s   = idx >> 14;
        int rem = idx & 16383;
        int j   = rem >> 9;
        int k   = rem & 511;
        u32 v = __ldg(&g_bs2[s * (32 * NK) + j * NK + k]);
        *(u32*)(smb + B_OFF + s * 65536 + sw128(k * 128 + j * 4)) = v;
    }

    const int gr = lane >> 2;        // row in group (0..7)
    const int gc = (lane & 3) * 2;   // col pair base
    float lsum = 0.f;

    for (int tile = blockIdx.x; tile < NTILE; tile += NCTA) {
        const int n0 = tile * 128;

        // stage A with on-the-fly bf16 split (16 u64 loads/thread)
        #pragma unroll 4
        for (int it = 0; it < 16; it++) {
            int idx = it * 256 + tid;
            int j   = idx >> 7;
            int row = idx & 127;
            float lo, hi;
            unpack2(__ldg(&g_z2[j * NPIX + (n0 + row)]), lo, hi);
            u32 o0, o1;
            split_pair(lo, hi, o0, o1);
            u32 off = sw128(row * 128 + j * 4);
            *(u32*)(smb + A_OFF + off)         = o0;
            *(u32*)(smb + A_OFF + 16384 + off) = o1;
        }
        if (tid == 0) s_acc[0] = 0.f;
        __syncthreads();

        // A fragments: af[split][ktile][4]
        u32 af[2][4][4];
        {
            const int arow = wid * 16 + (lane & 15);
            #pragma unroll
            for (int s = 0; s < 2; s++)
                #pragma unroll
                for (int kt = 0; kt < 4; kt++) {
                    u32 addr = sb + A_OFF + s * 16384 +
                               sw128(arow * 128 + kt * 32 + (lane >> 4) * 16);
                    ldsm_x4(af[s][kt][0], af[s][kt][1], af[s][kt][2], af[s][kt][3], addr);
                }
        }

        const float F0 = g_F[n0 + wid * 16 + gr];
        const float F1 = g_F[n0 + wid * 16 + gr + 8];

        u64  best0 = ~0ull, best1 = ~0ull;
        float bd0 = 3.4e38f, sd0 = 3.4e38f, bd1 = 3.4e38f, sd1 = 3.4e38f;

        #pragma unroll 1
        for (int ch = 0; ch < 8; ch++) {
            // hoist swizzled B offsets (reused across 3 passes)
            u32 ba[8][2];
            #pragma unroll
            for (int nt = 0; nt < 8; nt++) {
                const int brow = ch * 64 + nt * 8 + (lane & 7);
                ba[nt][0] = sw128(brow * 128 + (lane >> 3) * 16);
                ba[nt][1] = sw128(brow * 128 + 64 + (lane >> 3) * 16);
            }

            float D[8][4];
            #pragma unroll
            for (int nt = 0; nt < 8; nt++) {
                D[nt][0] = 0.f; D[nt][1] = 0.f; D[nt][2] = 0.f; D[nt][3] = 0.f;
            }

            #pragma unroll
            for (int pass = 0; pass < 3; pass++) {
                const int as = (pass == 2) ? 1 : 0;   // (b0,b0),(b0,b1),(b1,b0)
                const int bs = (pass == 1) ? 1 : 0;
                const u32 bbase = sb + B_OFF + bs * 65536;
                #pragma unroll
                for (int nt = 0; nt < 8; nt++) {
                    u32 p0, p1, p2, p3, q0, q1, q2, q3;
                    ldsm_x4(p0, p1, p2, p3, bbase + ba[nt][0]);
                    ldsm_x4(q0, q1, q2, q3, bbase + ba[nt][1]);
                    mma_bf16(D[nt], af[as][0], p0, p1);
                    mma_bf16(D[nt], af[as][1], p2, p3);
                    mma_bf16(D[nt], af[as][2], q0, q1);
                    mma_bf16(D[nt], af[as][3], q2, q3);
                }
            }

            // epilogue: dist = fl(F+C) - 2P; best + second-best
            #pragma unroll
            for (int nt = 0; nt < 8; nt++) {
                int c0 = ch * 64 + nt * 8 + gc;
                float C0 = s_ck[c0], C1 = s_ck[c0 + 1];
                float d00 = fmaf(-2.f, D[nt][0], __fadd_rn(F0, C0));
                float d01 = fmaf(-2.f, D[nt][1], __fadd_rn(F0, C1));
                float d10 = fmaf(-2.f, D[nt][2], __fadd_rn(F1, C0));
                float d11 = fmaf(-2.f, D[nt][3], __fadd_rn(F1, C1));
                u64 k00 = (((u64)__float_as_uint(d00)) << 32) | (u32)c0;
                u64 k01 = (((u64)__float_as_uint(d01)) << 32) | (u32)(c0 + 1);
                u64 k10 = (((u64)__float_as_uint(d10)) << 32) | (u32)c0;
                u64 k11 = (((u64)__float_as_uint(d11)) << 32) | (u32)(c0 + 1);
                if (k00 < best0) { sd0 = bd0; bd0 = d00; best0 = k00; } else sd0 = fminf(sd0, d00);
                if (k01 < best0) { sd0 = bd0; bd0 = d01; best0 = k01; } else sd0 = fminf(sd0, d01);
                if (k10 < best1) { sd1 = bd1; bd1 = d10; best1 = k10; } else sd1 = fminf(sd1, d10);
                if (k11 < best1) { sd1 = bd1; bd1 = d11; best1 = k11; } else sd1 = fminf(sd1, d11);
            }
        }

        // reduce across the 4 lanes sharing each row (best + second-best)
        #pragma unroll
        for (int m = 1; m <= 2; m <<= 1) {
            u64  ob0 = __shfl_xor_sync(0xffffffffu, best0, m);
            float obd0 = __shfl_xor_sync(0xffffffffu, bd0, m);
            float osd0 = __shfl_xor_sync(0xffffffffu, sd0, m);
            float loser0 = (ob0 < best0) ? bd0 : obd0;
            sd0 = fminf(fminf(sd0, osd0), loser0);
            if (ob0 < best0) { best0 = ob0; bd0 = obd0; }

            u64  ob1 = __shfl_xor_sync(0xffffffffu, best1, m);
            float obd1 = __shfl_xor_sync(0xffffffffu, bd1, m);
            float osd1 = __shfl_xor_sync(0xffffffffu, sd1, m);
            float loser1 = (ob1 < best1) ? bd1 : obd1;
            sd1 = fminf(fminf(sd1, osd1), loser1);
            if (ob1 < best1) { best1 = ob1; bd1 = obd1; }
        }
        if ((lane & 3) == 0) {
            const int r0 = wid * 16 + gr;
            const int r1 = r0 + 8;
            const int bk0 = (int)(best0 & 0xffffffffu);
            const int bk1 = (int)(best1 & 0xffffffffu);
            s_arg[r0] = bk0;
            s_arg[r1] = bk1;
            g_idx[n0 + r0] = bk0;
            g_idx[n0 + r1] = bk1;
            out[OUT_IDX_OFF + n0 + r0] = (float)bk0;
            out[OUT_IDX_OFF + n0 + r1] = (float)bk1;
            atomicAdd(&g_counts[bk0], 1);
            atomicAdd(&g_counts[bk1], 1);
            if (sd0 - bd0 < EPS_GAP) {
                int pos = atomicAdd(&g_flag_count, 1);
                g_flag[pos] = n0 + r0;
            }
            if (sd1 - bd1 < EPS_GAP) {
                int pos = atomicAdd(&g_flag_count, 1);
                g_flag[pos] = n0 + r1;
            }
        }
        __syncthreads();   // s_arg + s_acc=0 visible

        // loss partials (threads 0-127, one pixel each; op order as prior rounds)
        float lp = 0.f;
        if (tid < 128) {
            const int n  = n0 + tid;
            const int bk = s_arg[tid];
            const float4* cbrow = (const float4*)(codebook + bk * 64);
            #pragma unroll
            for (int j4 = 0; j4 < 16; j4++) {
                float4 c4 = __ldg(&cbrow[j4]);
                float lo0, hi0, lo1, hi1;
                unpack2(g_z2[(2 * j4) * NPIX + n], lo0, hi0);
                unpack2(g_z2[(2 * j4 + 1) * NPIX + n], lo1, hi1);
                float d0 = __fadd_rn(c4.x, -lo0);
                float d1 = __fadd_rn(c4.y, -hi0);
                float d2 = __fadd_rn(c4.z, -lo1);
                float d3 = __fadd_rn(c4.w, -hi1);
                lp = fmaf(d0, d0, lp);
                lp = fmaf(d1, d1, lp);
                lp = fmaf(d2, d2, lp);
                lp = fmaf(d3, d3, lp);
            }
        }
        #pragma unroll
        for (int m = 16; m > 0; m >>= 1)
            lp += __shfl_xor_sync(0xffffffffu, lp, m);
        if (lane == 0 && wid < 4) atomicAdd(s_acc, lp);
        __syncthreads();   // s_acc complete; next tile may restage A/s_arg

        if (tid == 0) lsum += s_acc[0];
    }

    if (tid == 0) g_partials[blockIdx.x] = lsum;
}

// ------------------------- K2b: exact fp32 rescue of flagged pixels
#define RESC_SMEM ((32768 + 512) * 4)
__global__ void __launch_bounds__(256, 1)
k_rescue(const float* __restrict__ codebook, float* __restrict__ out)
{
    const int count = g_flag_count;
    if (blockIdx.x * 256 >= count) return;

    extern __shared__ float rsm[];
    float* cb = rsm;           // [k*64+d]
    float* ck = rsm + 32768;

    const int tid = threadIdx.x;
    for (int i = tid; i < NK * ND; i += 256) cb[i] = codebook[i];
    for (int i = tid; i < NK; i += 256) ck[i] = g_ck[i];
    __syncthreads();

    for (int i = blockIdx.x * 256 + tid; i < count; i += gridDim.x * 256) {
        const int n = g_flag[i];
        const float F = g_F[n];

        u64 z2[32];
        #pragma unroll
        for (int j = 0; j < 32; j++) z2[j] = g_z2[j * NPIX + n];

        // bit-exact R6 scan: a0 even pairs, a1 odd pairs, strict-< tiebreak
        float best = 3.4e38f;
        int   bk   = 0;
        for (int k = 0; k < NK; k++) {
            const ulonglong2* c2 = (const ulonglong2*)(cb + k * 64);
            u64 a0 = 0ull, a1 = 0ull;
            #pragma unroll
            for (int j = 0; j < 16; j++) {
                ulonglong2 cc = c2[j];
                a0 = ffma2(z2[2 * j],     cc.x, a0);
                a1 = ffma2(z2[2 * j + 1], cc.y, a1);
            }
            float lo, hi;
            unpack2(fadd2(a0, a1), lo, hi);
            float P = __fadd_rn(lo, hi);
            float dist = fmaf(-2.f, P, __fadd_rn(F, ck[k]));
            if (dist < best) { best = dist; bk = k; }
        }

        const int old = g_idx[n];
        if (bk != old) {
            g_idx[n] = bk;
            out[OUT_IDX_OFF + n] = (float)bk;
            atomicAdd(&g_counts[bk], 1);
            atomicAdd(&g_counts[old], -1);

            float lps[2];
            int   ks[2] = {old, bk};
            #pragma unroll
            for (int v = 0; v < 2; v++) {
                float lp = 0.f;
                const float4* cbrow = (const float4*)(codebook + ks[v] * 64);
                #pragma unroll
                for (int j4 = 0; j4 < 16; j4++) {
                    float4 c4 = __ldg(&cbrow[j4]);
                    float lo0, hi0, lo1, hi1;
                    unpack2(z2[2 * j4], lo0, hi0);
                    unpack2(z2[2 * j4 + 1], lo1, hi1);
                    float d0 = __fadd_rn(c4.x, -lo0);
                    float d1 = __fadd_rn(c4.y, -hi0);
                    float d2 = __fadd_rn(c4.z, -lo1);
                    float d3 = __fadd_rn(c4.w, -hi1);
                    lp = fmaf(d0, d0, lp);
                    lp = fmaf(d1, d1, lp);
                    lp = fmaf(d2, d2, lp);
                    lp = fmaf(d3, d3, lp);
                }
                lps[v] = lp;
            }
            atomicAdd(&g_loss_delta, (double)(lps[1] - lps[0]));
        }
    }
}

// ----------------------------------------- K3: decode table (transposed [o][k])
__global__ void k_table(const float* __restrict__ codebook,
                        const float* __restrict__ post_w,
                        const float* __restrict__ post_b)
{
    __shared__ float cbr[64];
    const int k = blockIdx.x;
    const int o = threadIdx.x;
    if (o < 64) cbr[o] = codebook[k * 64 + o];
    __syncthreads();
    float s = 0.f;
    const float* w = post_w + o * 64;
    #pragma unroll
    for (int d = 0; d < 64; d++) s = fmaf(cbr[d], __ldg(&w[d]), s);
    g_table_T[o * NK + k] = __fadd_rn(s, __ldg(&post_b[o]));
}

// ----------------------------------------- K4: gather -> global_decode
__global__ void __launch_bounds__(256)
k_decode(float* __restrict__ out)
{
    __shared__ float s_tab[NK];
    const int blk = blockIdx.x;       // 0..4095
    const int b   = blk >> 7;
    const int o   = blk & 127;
    const int tid = threadIdx.x;

    s_tab[tid]       = g_table_T[o * NK + tid];
    s_tab[tid + 256] = g_table_T[o * NK + tid + 256];
    __syncthreads();

    const int* idx = g_idx + b * NHW;
    float* dst = out + OUT_DECODE_OFF + ((size_t)(b * NC + o)) * NHW;

    if (tid < 3)       dst[tid]  = s_tab[idx[tid]];
    else if (tid == 3) dst[4095] = s_tab[idx[4095]];

    float4* dst4 = (float4*)(dst + 3);   // 16B aligned
    #pragma unroll 2
    for (int i = tid; i < 1023; i += 256) {
        const int base = 3 + 4 * i;
        float4 v;
        v.x = s_tab[idx[base + 0]];
        v.y = s_tab[idx[base + 1]];
        v.z = s_tab[idx[base + 2]];
        v.w = s_tab[idx[base + 3]];
        dst4[i] = v;
    }
}

// ----------------------------------------- K5: loss + perplexity
__global__ void k_final(float* __restrict__ out)
{
    __shared__ float sh[512];
    const int t = threadIdx.x;  // 512 threads

    float p = (float)g_counts[t] / (float)NPIX;
    sh[t] = -(p * logf(p + 1e-10f));
    __syncthreads();
    #pragma unroll
    for (int s = 256; s > 0; s >>= 1) {
        if (t < s) sh[t] += sh[t + s];
        __syncthreads();
    }
    if (t == 0) out[OUT_PERP_OFF] = expf(sh[0]);
    __syncthreads();

    sh[t] = (t < NCTA) ? g_partials[t] : 0.f;
    __syncthreads();
    #pragma unroll
    for (int s = 256; s > 0; s >>= 1) {
        if (t < s) sh[t] += sh[t + s];
        __syncthreads();
    }
    if (t == 0)
        out[0] = 1.25f * ((sh[0] + (float)g_loss_delta) / 8388608.f);
}

// ---------------------------------------------------------------- launch
extern "C" void kernel_launch(void* const* d_in, const int* in_sizes, int n_in,
                              void* d_out, int out_size)
{
    const float* enc      = (const float*)d_in[0];
    const float* pre_w    = (const float*)d_in[1];
    const float* pre_b    = (const float*)d_in[2];
    const float* codebook = (const float*)d_in[3];
    const float* post_w   = (const float*)d_in[4];
    const float* post_b   = (const float*)d_in[5];
    float* out = (float*)d_out;

    cudaFuncSetAttribute(k_pre, cudaFuncAttributeMaxDynamicSharedMemorySize, 32768);
    cudaFuncSetAttribute(k_mma, cudaFuncAttributeMaxDynamicSharedMemorySize, MMA_SMEM);
    cudaFuncSetAttribute(k_rescue, cudaFuncAttributeMaxDynamicSharedMemorySize, RESC_SMEM);

    k_zero  <<<1, 512>>>();
    k_pre   <<<NPIX / 512, 512, 32768>>>(enc, pre_w, pre_b);
    k_prep  <<<1, 512>>>(codebook);
    k_mma   <<<NCTA, 256, MMA_SMEM>>>(codebook, out);   // ncu capture slot
    k_rescue<<<NCTA, 256, RESC_SMEM>>>(codebook, out);
    k_table <<<NK, 128>>>(codebook, post_w, post_b);
    k_decode<<<NB * NC, 256>>>(out);
    k_final <<<1, 512>>>(out);
}

// round 13
// speedup vs baseline: 1.2767x; 1.0121x over previous
#include <cuda_runtime.h>
#include <cuda_bf16.h>
#include <math.h>

// Problem constants
#define NB   32
#define NC   128      // NUM_HIDDENS
#define NHW  4096     // H*W
#define NPIX 131072   // B*H*W
#define ND   64       // EMB_DIM
#define NK   512      // NUM_EMB

// Output layout (float32, concatenated):
#define OUT_DECODE_OFF 1
#define OUT_PERP_OFF   16777217
#define OUT_IDX_OFF    16777218

typedef unsigned long long u64;
typedef unsigned int u32;

// R10 measured worst-case approx-dist error ~1e-6 (2-3 flips at gaps that
// scale). 3e-5 keeps 30x margin while unflagging the ~1e-4-gap bulk.
#define EPS_GAP  3e-5f
#define NCTA     148
#define NTILE    1024      // NPIX / 128

// Scratch (no allocations allowed)
__device__ __align__(16) int   g_idx[NPIX];
__device__ int    g_counts[NK];
__device__ float  g_partials[NCTA];
__device__ float  g_table_T[NC * NK];      // decode table transposed [o][k]
__device__ u64    g_z2[32 * NPIX];         // z fp32 pairs, [j][n]
__device__ u32    g_bs2[2 * 32 * NK];      // codebook bf16x2 splits
__device__ float  g_F[NPIX];
__device__ float  g_ck[NK];
__device__ int    g_flag[NPIX];            // pixels needing exact rescue
__device__ int    g_flag_count;
__device__ double g_loss_delta;

// ---- packed f32x2 helpers ----
__device__ __forceinline__ u64 ffma2(u64 a, u64 b, u64 c) {
    u64 d;
    asm("fma.rn.f32x2 %0, %1, %2, %3;" : "=l"(d) : "l"(a), "l"(b), "l"(c));
    return d;
}
__device__ __forceinline__ u64 fadd2(u64 a, u64 b) {
    u64 d;
    asm("add.rn.f32x2 %0, %1, %2;" : "=l"(d) : "l"(a), "l"(b));
    return d;
}
__device__ __forceinline__ u64 pack2(float lo, float hi) {
    u64 d;
    asm("mov.b64 %0, {%1, %2};" : "=l"(d) : "f"(lo), "f"(hi));
    return d;
}
__device__ __forceinline__ void unpack2(u64 v, float& lo, float& hi) {
    asm("mov.b64 {%0, %1}, %2;" : "=f"(lo), "=f"(hi) : "l"(v));
}

__device__ __forceinline__ u32 smem_u32(const void* p) {
    u32 a;
    asm("{ .reg .u64 t; cvta.to.shared.u64 t, %1; cvt.u32.u64 %0, t; }"
        : "=r"(a) : "l"(p));
    return a;
}

// SW128 swizzle (Swizzle<3,4,3>)
__device__ __forceinline__ u32 sw128(u32 off) { return off ^ ((off >> 3) & 0x70); }

// ---- warp-level MMA primitives (baseline PTX, legal on sm_103) ----
__device__ __forceinline__ void ldsm_x4(u32& r0, u32& r1, u32& r2, u32& r3, u32 addr) {
    asm volatile("ldmatrix.sync.aligned.m8n8.x4.shared.b16 {%0,%1,%2,%3}, [%4];"
                 : "=r"(r0), "=r"(r1), "=r"(r2), "=r"(r3) : "r"(addr));
}
__device__ __forceinline__ void mma_bf16(float* d, const u32* a, u32 b0, u32 b1) {
    asm volatile(
        "mma.sync.aligned.m16n8k16.row.col.f32.bf16.bf16.f32 "
        "{%0,%1,%2,%3}, {%4,%5,%6,%7}, {%8,%9}, {%0,%1,%2,%3};"
        : "+f"(d[0]), "+f"(d[1]), "+f"(d[2]), "+f"(d[3])
        : "r"(a[0]), "r"(a[1]), "r"(a[2]), "r"(a[3]), "r"(b0), "r"(b1));
}

// bf16x2 split of an fp32 pair (identical op sequence everywhere it's used)
__device__ __forceinline__ void split_pair(float lo, float hi, u32& o0, u32& o1) {
    float2 f = make_float2(lo, hi);
    __nv_bfloat162 b0 = __float22bfloat162_rn(f);
    float2 f0 = __bfloat1622float2(b0);
    float2 r  = make_float2(f.x - f0.x, f.y - f0.y);
    __nv_bfloat162 b1 = __float22bfloat162_rn(r);
    o0 = *reinterpret_cast<u32*>(&b0);
    o1 = *reinterpret_cast<u32*>(&b1);
}

// ---------------------------------------------------------------- K0: zero
__global__ void k_zero() {
    int t = threadIdx.x;
    if (t < NK) g_counts[t] = 0;
    if (t == 0) { g_flag_count = 0; g_loss_delta = 0.0; }
}

// --------------------------------- nops: shift ncu capture onto k_pre
__global__ void k_nop() {}

// -------------------------------- K1: pre-conv -> z (fp32 pairs) + F
__global__ void __launch_bounds__(512, 1)
k_pre(const float* __restrict__ enc,
      const float* __restrict__ pre_w,
      const float* __restrict__ pre_b)
{
    extern __shared__ float pw[];   // [c*64+o], 8192 floats

    const int tid = threadIdx.x;
    for (int i = tid; i < NC * ND; i += 512) {
        int o = i >> 7, c = i & 127;
        pw[c * 64 + o] = pre_w[i];
    }
    __syncthreads();

    const int n  = blockIdx.x * 512 + tid;
    const int b  = n >> 12;
    const int hw = n & 4095;
    const float* ep = enc + (size_t)b * (NC * NHW) + hw;

    u64 z2[32];
    #pragma unroll
    for (int j = 0; j < 32; j++) z2[j] = 0ull;

    #pragma unroll 2
    for (int c = 0; c < NC; c++) {
        float e = ep[(size_t)c * NHW];
        u64 e2 = pack2(e, e);
        const ulonglong2* w2 = (const ulonglong2*)(pw + c * 64);
        #pragma unroll
        for (int j = 0; j < 16; j++) {
            ulonglong2 w = w2[j];
            z2[2 * j]     = ffma2(e2, w.x, z2[2 * j]);
            z2[2 * j + 1] = ffma2(e2, w.y, z2[2 * j + 1]);
        }
    }
    {
        const u64* pb2 = (const u64*)pre_b;
        #pragma unroll
        for (int j = 0; j < 32; j++) z2[j] = fadd2(z2[j], __ldg(&pb2[j]));
    }

    float F = 0.f;
    #pragma unroll
    for (int j = 0; j < 32; j++) {
        float lo, hi;
        unpack2(z2[j], lo, hi);
        F = __fadd_rn(F, __fmul_rn(lo, lo));
        F = __fadd_rn(F, __fmul_rn(hi, hi));
        g_z2[j * NPIX + n] = z2[j];
    }
    g_F[n] = F;
}

// -------------------------------- K1b: codebook splits + squared norms
__global__ void k_prep(const float* __restrict__ codebook)
{
    const int k = threadIdx.x;   // 512 threads
    float s = 0.f;
    #pragma unroll 8
    for (int d = 0; d < ND; d++) {
        float v = __ldg(&codebook[k * 64 + d]);
        s = __fadd_rn(s, __fmul_rn(v, v));
    }
    g_ck[k] = s;

    #pragma unroll
    for (int j = 0; j < 32; j++) {
        u32 o0, o1;
        split_pair(__ldg(&codebook[k * 64 + 2 * j]),
                   __ldg(&codebook[k * 64 + 2 * j + 1]), o0, o1);
        g_bs2[0 * (32 * NK) + j * NK + k] = o0;
        g_bs2[1 * (32 * NK) + j * NK + k] = o1;
    }
}

// -------------------------------- K2: persistent mma.sync distance GEMM
#define A_OFF    1024
#define B_OFF    33792
#define CKS_OFF  164864
#define SARG_OFF 166912
#define SACC_OFF 167424
#define MMA_SMEM 167936

__global__ void __launch_bounds__(256, 1)
k_mma(const float* __restrict__ codebook, float* __restrict__ out)
{
    extern __shared__ char smb[];
    const u32 sb   = smem_u32(smb);
    float* s_ck    = (float*)(smb + CKS_OFF);
    int*   s_arg   = (int*)(smb + SARG_OFF);
    float* s_acc   = (float*)(smb + SACC_OFF);

    const int tid  = threadIdx.x;
    const int wid  = tid >> 5;
    const int lane = tid & 31;

    for (int i = tid; i < NK; i += 256) s_ck[i] = g_ck[i];

    // stage B^T once per CTA: 2 splits x 512 rows x 32 u32
    #pragma unroll 4
    for (int it = 0; it < 128; it++) {
        int idx = it * 256 + tid;
        int s   = idx >> 14;
        int rem = idx & 16383;
        int j   = rem >> 9;
        int k   = rem & 511;
        u32 v = __ldg(&g_bs2[s * (32 * NK) + j * NK + k]);
        *(u32*)(smb + B_OFF + s * 65536 + sw128(k * 128 + j * 4)) = v;
    }

    const int gr = lane >> 2;        // row in group (0..7)
    const int gc = (lane & 3) * 2;   // col pair base

    // hoist swizzled B offsets ONCE (chunk stride 8192 commutes with sw128:
    // 8192 has no bits in [4,10), so sw128(x+ch*8192) == sw128(x)+ch*8192)
    u32 ba0[8][2];
    #pragma unroll
    for (int nt = 0; nt < 8; nt++) {
        const int brow = nt * 8 + (lane & 7);
        ba0[nt][0] = sw128(brow * 128 + (lane >> 3) * 16);
        ba0[nt][1] = sw128(brow * 128 + 64 + (lane >> 3) * 16);
    }

    float lsum = 0.f;

    for (int tile = blockIdx.x; tile < NTILE; tile += NCTA) {
        const int n0 = tile * 128;

        // stage A with on-the-fly bf16 split (16 u64 loads/thread)
        #pragma unroll 4
        for (int it = 0; it < 16; it++) {
            int idx = it * 256 + tid;
            int j   = idx >> 7;
            int row = idx & 127;
            float lo, hi;
            unpack2(__ldg(&g_z2[j * NPIX + (n0 + row)]), lo, hi);
            u32 o0, o1;
            split_pair(lo, hi, o0, o1);
            u32 off = sw128(row * 128 + j * 4);
            *(u32*)(smb + A_OFF + off)         = o0;
            *(u32*)(smb + A_OFF + 16384 + off) = o1;
        }
        if (tid == 0) s_acc[0] = 0.f;
        __syncthreads();

        // A fragments: af[split][ktile][4]
        u32 af[2][4][4];
        {
            const int arow = wid * 16 + (lane & 15);
            #pragma unroll
            for (int s = 0; s < 2; s++)
                #pragma unroll
                for (int kt = 0; kt < 4; kt++) {
                    u32 addr = sb + A_OFF + s * 16384 +
                               sw128(arow * 128 + kt * 32 + (lane >> 4) * 16);
                    ldsm_x4(af[s][kt][0], af[s][kt][1], af[s][kt][2], af[s][kt][3], addr);
                }
        }

        const float F0 = g_F[n0 + wid * 16 + gr];
        const float F1 = g_F[n0 + wid * 16 + gr + 8];

        u64  best0 = ~0ull, best1 = ~0ull;
        float bd0 = 3.4e38f, sd0 = 3.4e38f, bd1 = 3.4e38f, sd1 = 3.4e38f;

        #pragma unroll 1
        for (int ch = 0; ch < 8; ch++) {
            const u32 choff = ch * 8192;

            float D[8][4];
            #pragma unroll
            for (int nt = 0; nt < 8; nt++) {
                D[nt][0] = 0.f; D[nt][1] = 0.f; D[nt][2] = 0.f; D[nt][3] = 0.f;
            }

            #pragma unroll
            for (int pass = 0; pass < 3; pass++) {
                const int as = (pass == 2) ? 1 : 0;   // (b0,b0),(b0,b1),(b1,b0)
                const int bs = (pass == 1) ? 1 : 0;
                const u32 bb = sb + B_OFF + bs * 65536 + choff;
                #pragma unroll
                for (int nt = 0; nt < 8; nt++) {
                    u32 p0, p1, p2, p3, q0, q1, q2, q3;
                    ldsm_x4(p0, p1, p2, p3, bb + ba0[nt][0]);
                    ldsm_x4(q0, q1, q2, q3, bb + ba0[nt][1]);
                    mma_bf16(D[nt], af[as][0], p0, p1);
                    mma_bf16(D[nt], af[as][1], p2, p3);
                    mma_bf16(D[nt], af[as][2], q0, q1);
                    mma_bf16(D[nt], af[as][3], q2, q3);
                }
            }

            // epilogue: dist = fl(F+C) - 2P; best + second-best
            #pragma unroll
            for (int nt = 0; nt < 8; nt++) {
                int c0 = ch * 64 + nt * 8 + gc;
                float C0 = s_ck[c0], C1 = s_ck[c0 + 1];
                float d00 = fmaf(-2.f, D[nt][0], __fadd_rn(F0, C0));
                float d01 = fmaf(-2.f, D[nt][1], __fadd_rn(F0, C1));
                float d10 = fmaf(-2.f, D[nt][2], __fadd_rn(F1, C0));
                float d11 = fmaf(-2.f, D[nt][3], __fadd_rn(F1, C1));
                u64 k00 = (((u64)__float_as_uint(d00)) << 32) | (u32)c0;
                u64 k01 = (((u64)__float_as_uint(d01)) << 32) | (u32)(c0 + 1);
                u64 k10 = (((u64)__float_as_uint(d10)) << 32) | (u32)c0;
                u64 k11 = (((u64)__float_as_uint(d11)) << 32) | (u32)(c0 + 1);
                if (k00 < best0) { sd0 = bd0; bd0 = d00; best0 = k00; } else sd0 = fminf(sd0, d00);
                if (k01 < best0) { sd0 = bd0; bd0 = d01; best0 = k01; } else sd0 = fminf(sd0, d01);
                if (k10 < best1) { sd1 = bd1; bd1 = d10; best1 = k10; } else sd1 = fminf(sd1, d10);
                if (k11 < best1) { sd1 = bd1; bd1 = d11; best1 = k11; } else sd1 = fminf(sd1, d11);
            }
        }

        // reduce across the 4 lanes sharing each row (best + second-best)
        #pragma unroll
        for (int m = 1; m <= 2; m <<= 1) {
            u64  ob0 = __shfl_xor_sync(0xffffffffu, best0, m);
            float obd0 = __shfl_xor_sync(0xffffffffu, bd0, m);
            float osd0 = __shfl_xor_sync(0xffffffffu, sd0, m);
            float loser0 = (ob0 < best0) ? bd0 : obd0;
            sd0 = fminf(fminf(sd0, osd0), loser0);
            if (ob0 < best0) { best0 = ob0; bd0 = obd0; }

            u64  ob1 = __shfl_xor_sync(0xffffffffu, best1, m);
            float obd1 = __shfl_xor_sync(0xffffffffu, bd1, m);
            float osd1 = __shfl_xor_sync(0xffffffffu, sd1, m);
            float loser1 = (ob1 < best1) ? bd1 : obd1;
            sd1 = fminf(fminf(sd1, osd1), loser1);
            if (ob1 < best1) { best1 = ob1; bd1 = obd1; }
        }
        if ((lane & 3) == 0) {
            const int r0 = wid * 16 + gr;
            const int r1 = r0 + 8;
            const int bk0 = (int)(best0 & 0xffffffffu);
            const int bk1 = (int)(best1 & 0xffffffffu);
            s_arg[r0] = bk0;
            s_arg[r1] = bk1;
            g_idx[n0 + r0] = bk0;
            g_idx[n0 + r1] = bk1;
            out[OUT_IDX_OFF + n0 + r0] = (float)bk0;
            out[OUT_IDX_OFF + n0 + r1] = (float)bk1;
            atomicAdd(&g_counts[bk0], 1);
            atomicAdd(&g_counts[bk1], 1);
            if (sd0 - bd0 < EPS_GAP) {
                int pos = atomicAdd(&g_flag_count, 1);
                g_flag[pos] = n0 + r0;
            }
            if (sd1 - bd1 < EPS_GAP) {
                int pos = atomicAdd(&g_flag_count, 1);
                g_flag[pos] = n0 + r1;
            }
        }
        __syncthreads();   // s_arg + s_acc=0 visible

        // loss partials (threads 0-127, one pixel each; op order as prior rounds)
        float lp = 0.f;
        if (tid < 128) {
            const int n  = n0 + tid;
            const int bk = s_arg[tid];
            const float4* cbrow = (const float4*)(codebook + bk * 64);
            #pragma unroll
            for (int j4 = 0; j4 < 16; j4++) {
                float4 c4 = __ldg(&cbrow[j4]);
                float lo0, hi0, lo1, hi1;
                unpack2(g_z2[(2 * j4) * NPIX + n], lo0, hi0);
                unpack2(g_z2[(2 * j4 + 1) * NPIX + n], lo1, hi1);
                float d0 = __fadd_rn(c4.x, -lo0);
                float d1 = __fadd_rn(c4.y, -hi0);
                float d2 = __fadd_rn(c4.z, -lo1);
                float d3 = __fadd_rn(c4.w, -hi1);
                lp = fmaf(d0, d0, lp);
                lp = fmaf(d1, d1, lp);
                lp = fmaf(d2, d2, lp);
                lp = fmaf(d3, d3, lp);
            }
        }
        #pragma unroll
        for (int m = 16; m > 0; m >>= 1)
            lp += __shfl_xor_sync(0xffffffffu, lp, m);
        if (lane == 0 && wid < 4) atomicAdd(s_acc, lp);
        __syncthreads();   // s_acc complete; next tile may restage A/s_arg

        if (tid == 0) lsum += s_acc[0];
    }

    if (tid == 0) g_partials[blockIdx.x] = lsum;
}

// ------------------------- K2b: exact fp32 rescue of flagged pixels
#define RESC_SMEM ((32768 + 512) * 4)
__global__ void __launch_bounds__(256, 1)
k_rescue(const float* __restrict__ codebook, float* __restrict__ out)
{
    const int count = g_flag_count;
    if (blockIdx.x * 256 >= count) return;

    extern __shared__ float rsm[];
    float* cb = rsm;           // [k*64+d]
    float* ck = rsm + 32768;

    const int tid = threadIdx.x;
    for (int i = tid; i < NK * ND; i += 256) cb[i] = codebook[i];
    for (int i = tid; i < NK; i += 256) ck[i] = g_ck[i];
    __syncthreads();

    for (int i = blockIdx.x * 256 + tid; i < count; i += gridDim.x * 256) {
        const int n = g_flag[i];
        const float F = g_F[n];

        u64 z2[32];
        #pragma unroll
        for (int j = 0; j < 32; j++) z2[j] = g_z2[j * NPIX + n];

        // bit-exact R6 scan: a0 even pairs, a1 odd pairs, strict-< tiebreak
        float best = 3.4e38f;
        int   bk   = 0;
        for (int k = 0; k < NK; k++) {
            const ulonglong2* c2 = (const ulonglong2*)(cb + k * 64);
            u64 a0 = 0ull, a1 = 0ull;
            #pragma unroll
            for (int j = 0; j < 16; j++) {
                ulonglong2 cc = c2[j];
                a0 = ffma2(z2[2 * j],     cc.x, a0);
                a1 = ffma2(z2[2 * j + 1], cc.y, a1);
            }
            float lo, hi;
            unpack2(fadd2(a0, a1), lo, hi);
            float P = __fadd_rn(lo, hi);
            float dist = fmaf(-2.f, P, __fadd_rn(F, ck[k]));
            if (dist < best) { best = dist; bk = k; }
        }

        const int old = g_idx[n];
        if (bk != old) {
            g_idx[n] = bk;
            out[OUT_IDX_OFF + n] = (float)bk;
            atomicAdd(&g_counts[bk], 1);
            atomicAdd(&g_counts[old], -1);

            float lps[2];
            int   ks[2] = {old, bk};
            #pragma unroll
            for (int v = 0; v < 2; v++) {
                float lp = 0.f;
                const float4* cbrow = (const float4*)(codebook + ks[v] * 64);
                #pragma unroll
                for (int j4 = 0; j4 < 16; j4++) {
                    float4 c4 = __ldg(&cbrow[j4]);
                    float lo0, hi0, lo1, hi1;
                    unpack2(z2[2 * j4], lo0, hi0);
                    unpack2(z2[2 * j4 + 1], lo1, hi1);
                    float d0 = __fadd_rn(c4.x, -lo0);
                    float d1 = __fadd_rn(c4.y, -hi0);
                    float d2 = __fadd_rn(c4.z, -lo1);
                    float d3 = __fadd_rn(c4.w, -hi1);
                    lp = fmaf(d0, d0, lp);
                    lp = fmaf(d1, d1, lp);
                    lp = fmaf(d2, d2, lp);
                    lp = fmaf(d3, d3, lp);
                }
                lps[v] = lp;
            }
            atomicAdd(&g_loss_delta, (double)(lps[1] - lps[0]));
        }
    }
}

// ----------------------------------------- K3: decode table (transposed [o][k])
__global__ void k_table(const float* __restrict__ codebook,
                        const float* __restrict__ post_w,
                        const float* __restrict__ post_b)
{
    __shared__ float cbr[64];
    const int k = blockIdx.x;
    const int o = threadIdx.x;
    if (o < 64) cbr[o] = codebook[k * 64 + o];
    __syncthreads();
    float s = 0.f;
    const float* w = post_w + o * 64;
    #pragma unroll
    for (int d = 0; d < 64; d++) s = fmaf(cbr[d], __ldg(&w[d]), s);
    g_table_T[o * NK + k] = __fadd_rn(s, __ldg(&post_b[o]));
}

// ----------------------------------------- K4: gather -> global_decode
__global__ void __launch_bounds__(256)
k_decode(float* __restrict__ out)
{
    __shared__ float s_tab[NK];
    const int blk = blockIdx.x;       // 0..4095
    const int b   = blk >> 7;
    const int o   = blk & 127;
    const int tid = threadIdx.x;

    s_tab[tid]       = g_table_T[o * NK + tid];
    s_tab[tid + 256] = g_table_T[o * NK + tid + 256];
    __syncthreads();

    const int* idx = g_idx + b * NHW;
    float* dst = out + OUT_DECODE_OFF + ((size_t)(b * NC + o)) * NHW;

    if (tid < 3)       dst[tid]  = s_tab[idx[tid]];
    else if (tid == 3) dst[4095] = s_tab[idx[4095]];

    float4* dst4 = (float4*)(dst + 3);   // 16B aligned
    #pragma unroll 2
    for (int i = tid; i < 1023; i += 256) {
        const int base = 3 + 4 * i;
        float4 v;
        v.x = s_tab[idx[base + 0]];
        v.y = s_tab[idx[base + 1]];
        v.z = s_tab[idx[base + 2]];
        v.w = s_tab[idx[base + 3]];
        dst4[i] = v;
    }
}

// ----------------------------------------- K5: loss + perplexity
__global__ void k_final(float* __restrict__ out)
{
    __shared__ float sh[512];
    const int t = threadIdx.x;  // 512 threads

    float p = (float)g_counts[t] / (float)NPIX;
    sh[t] = -(p * logf(p + 1e-10f));
    __syncthreads();
    #pragma unroll
    for (int s = 256; s > 0; s >>= 1) {
        if (t < s) sh[t] += sh[t + s];
        __syncthreads();
    }
    if (t == 0) out[OUT_PERP_OFF] = expf(sh[0]);
    __syncthreads();

    sh[t] = (t < NCTA) ? g_partials[t] : 0.f;
    __syncthreads();
    #pragma unroll
    for (int s = 256; s > 0; s >>= 1) {
        if (t < s) sh[t] += sh[t + s];
        __syncthreads();
    }
    if (t == 0)
        out[0] = 1.25f * ((sh[0] + (float)g_loss_delta) / 8388608.f);
}

// ---------------------------------------------------------------- launch
extern "C" void kernel_launch(void* const* d_in, const int* in_sizes, int n_in,
                              void* d_out, int out_size)
{
    const float* enc      = (const float*)d_in[0];
    const float* pre_w    = (const float*)d_in[1];
    const float* pre_b    = (const float*)d_in[2];
    const float* codebook = (const float*)d_in[3];
    const float* post_w   = (const float*)d_in[4];
    const float* post_b   = (const float*)d_in[5];
    float* out = (float*)d_out;

    cudaFuncSetAttribute(k_pre, cudaFuncAttributeMaxDynamicSharedMemorySize, 32768);
    cudaFuncSetAttribute(k_mma, cudaFuncAttributeMaxDynamicSharedMemorySize, MMA_SMEM);
    cudaFuncSetAttribute(k_rescue, cudaFuncAttributeMaxDynamicSharedMemorySize, RESC_SMEM);

    k_zero  <<<1, 512>>>();
    k_nop   <<<1, 32>>>();   // shift ncu capture slot onto k_pre
    k_nop   <<<1, 32>>>();
    k_pre   <<<NPIX / 512, 512, 32768>>>(enc, pre_w, pre_b);   // ncu capture slot
    k_prep  <<<1, 512>>>(codebook);
    k_mma   <<<NCTA, 256, MMA_SMEM>>>(codebook, out);
    k_rescue<<<NCTA, 256, RESC_SMEM>>>(codebook, out);
    k_table <<<NK, 128>>>(codebook, post_w, post_b);
    k_decode<<<NB * NC, 256>>>(out);
    k_final <<<1, 512>>>(out);
}

// round 14
// speedup vs baseline: 1.3051x; 1.0222x over previous
#include <cuda_runtime.h>
#include <cuda_bf16.h>
#include <math.h>

// Problem constants
#define NB   32
#define NC   128      // NUM_HIDDENS
#define NHW  4096     // H*W
#define NPIX 131072   // B*H*W
#define ND   64       // EMB_DIM
#define NK   512      // NUM_EMB

// Output layout (float32, concatenated):
#define OUT_DECODE_OFF 1
#define OUT_PERP_OFF   16777217
#define OUT_IDX_OFF    16777218

typedef unsigned long long u64;
typedef unsigned int u32;

#define EPS_GAP  3e-5f
#define NCTA     148
#define NTILE    1024      // NPIX / 128

// Scratch (no allocations allowed)
__device__ __align__(16) int   g_idx[NPIX];
__device__ int    g_counts[NK];
__device__ float  g_partials[NCTA];
__device__ float  g_table_T[NC * NK];      // decode table transposed [o][k]
__device__ u64    g_z2[32 * NPIX];         // z fp32 pairs, [j][n]
__device__ u32    g_bs2[2 * 32 * NK];      // codebook bf16x2 splits
__device__ float  g_F[NPIX];
__device__ float  g_ck[NK];
__device__ int    g_flag[NPIX];            // pixels needing exact rescue
__device__ int    g_flag_count;
__device__ double g_loss_delta;

// ---- packed f32x2 helpers ----
__device__ __forceinline__ u64 ffma2(u64 a, u64 b, u64 c) {
    u64 d;
    asm("fma.rn.f32x2 %0, %1, %2, %3;" : "=l"(d) : "l"(a), "l"(b), "l"(c));
    return d;
}
__device__ __forceinline__ u64 fadd2(u64 a, u64 b) {
    u64 d;
    asm("add.rn.f32x2 %0, %1, %2;" : "=l"(d) : "l"(a), "l"(b));
    return d;
}
__device__ __forceinline__ u64 pack2(float lo, float hi) {
    u64 d;
    asm("mov.b64 %0, {%1, %2};" : "=l"(d) : "f"(lo), "f"(hi));
    return d;
}
__device__ __forceinline__ void unpack2(u64 v, float& lo, float& hi) {
    asm("mov.b64 {%0, %1}, %2;" : "=f"(lo), "=f"(hi) : "l"(v));
}

__device__ __forceinline__ u32 smem_u32(const void* p) {
    u32 a;
    asm("{ .reg .u64 t; cvta.to.shared.u64 t, %1; cvt.u32.u64 %0, t; }"
        : "=r"(a) : "l"(p));
    return a;
}

// SW128 swizzle (Swizzle<3,4,3>)
__device__ __forceinline__ u32 sw128(u32 off) { return off ^ ((off >> 3) & 0x70); }

// ---- warp-level MMA primitives (baseline PTX, legal on sm_103) ----
__device__ __forceinline__ void ldsm_x4(u32& r0, u32& r1, u32& r2, u32& r3, u32 addr) {
    asm volatile("ldmatrix.sync.aligned.m8n8.x4.shared.b16 {%0,%1,%2,%3}, [%4];"
                 : "=r"(r0), "=r"(r1), "=r"(r2), "=r"(r3) : "r"(addr));
}
__device__ __forceinline__ void mma_bf16(float* d, const u32* a, u32 b0, u32 b1) {
    asm volatile(
        "mma.sync.aligned.m16n8k16.row.col.f32.bf16.bf16.f32 "
        "{%0,%1,%2,%3}, {%4,%5,%6,%7}, {%8,%9}, {%0,%1,%2,%3};"
        : "+f"(d[0]), "+f"(d[1]), "+f"(d[2]), "+f"(d[3])
        : "r"(a[0]), "r"(a[1]), "r"(a[2]), "r"(a[3]), "r"(b0), "r"(b1));
}

// bf16x2 split of an fp32 pair (identical op sequence everywhere it's used)
__device__ __forceinline__ void split_pair(float lo, float hi, u32& o0, u32& o1) {
    float2 f = make_float2(lo, hi);
    __nv_bfloat162 b0 = __float22bfloat162_rn(f);
    float2 f0 = __bfloat1622float2(b0);
    float2 r  = make_float2(f.x - f0.x, f.y - f0.y);
    __nv_bfloat162 b1 = __float22bfloat162_rn(r);
    o0 = *reinterpret_cast<u32*>(&b0);
    o1 = *reinterpret_cast<u32*>(&b1);
}

// ------------------------- K0: zero + codebook prep (merged, 512 threads)
__global__ void k_zero(const float* __restrict__ codebook) {
    const int k = threadIdx.x;
    g_counts[k] = 0;
    if (k == 0) { g_flag_count = 0; g_loss_delta = 0.0; }

    float s = 0.f;
    #pragma unroll 8
    for (int d = 0; d < ND; d++) {
        float v = __ldg(&codebook[k * 64 + d]);
        s = __fadd_rn(s, __fmul_rn(v, v));
    }
    g_ck[k] = s;

    #pragma unroll
    for (int j = 0; j < 32; j++) {
        u32 o0, o1;
        split_pair(__ldg(&codebook[k * 64 + 2 * j]),
                   __ldg(&codebook[k * 64 + 2 * j + 1]), o0, o1);
        g_bs2[0 * (32 * NK) + j * NK + k] = o0;
        g_bs2[1 * (32 * NK) + j * NK + k] = o1;
    }
}

// -------------------------------- K1: pre-conv -> z (fp32 pairs) + F
// 256 thr x 512 blocks, 2 CTAs/SM: memory-latency bound -> double occupancy,
// batch loads 4-wide for MLP. Per-pixel ffma2 order per z2[j] unchanged.
__global__ void __launch_bounds__(256, 2)
k_pre(const float* __restrict__ enc,
      const float* __restrict__ pre_w,
      const float* __restrict__ pre_b)
{
    extern __shared__ float pw[];   // [c*64+o], 8192 floats

    const int tid = threadIdx.x;
    for (int i = tid; i < NC * ND; i += 256) {
        int o = i >> 7, c = i & 127;
        pw[c * 64 + o] = pre_w[i];
    }
    __syncthreads();

    const int n  = blockIdx.x * 256 + tid;
    const int b  = n >> 12;
    const int hw = n & 4095;
    const float* ep = enc + (size_t)b * (NC * NHW) + hw;

    u64 z2[32];
    #pragma unroll
    for (int j = 0; j < 32; j++) z2[j] = 0ull;

    #pragma unroll 1
    for (int c = 0; c < NC; c += 4) {
        // batch 4 independent global loads (MLP)
        float e0 = ep[(size_t)(c + 0) * NHW];
        float e1 = ep[(size_t)(c + 1) * NHW];
        float e2 = ep[(size_t)(c + 2) * NHW];
        float e3 = ep[(size_t)(c + 3) * NHW];
        u64 ee0 = pack2(e0, e0), ee1 = pack2(e1, e1);
        u64 ee2 = pack2(e2, e2), ee3 = pack2(e3, e3);
        const ulonglong2* w0 = (const ulonglong2*)(pw + (c + 0) * 64);
        const ulonglong2* w1 = (const ulonglong2*)(pw + (c + 1) * 64);
        const ulonglong2* w2 = (const ulonglong2*)(pw + (c + 2) * 64);
        const ulonglong2* w3 = (const ulonglong2*)(pw + (c + 3) * 64);
        #pragma unroll
        for (int j = 0; j < 16; j++) {
            ulonglong2 a0 = w0[j];
            z2[2 * j]     = ffma2(ee0, a0.x, z2[2 * j]);
            z2[2 * j + 1] = ffma2(ee0, a0.y, z2[2 * j + 1]);
            ulonglong2 a1 = w1[j];
            z2[2 * j]     = ffma2(ee1, a1.x, z2[2 * j]);
            z2[2 * j + 1] = ffma2(ee1, a1.y, z2[2 * j + 1]);
            ulonglong2 a2 = w2[j];
            z2[2 * j]     = ffma2(ee2, a2.x, z2[2 * j]);
            z2[2 * j + 1] = ffma2(ee2, a2.y, z2[2 * j + 1]);
            ulonglong2 a3 = w3[j];
            z2[2 * j]     = ffma2(ee3, a3.x, z2[2 * j]);
            z2[2 * j + 1] = ffma2(ee3, a3.y, z2[2 * j + 1]);
        }
    }
    {
        const u64* pb2 = (const u64*)pre_b;
        #pragma unroll
        for (int j = 0; j < 32; j++) z2[j] = fadd2(z2[j], __ldg(&pb2[j]));
    }

    float F = 0.f;
    #pragma unroll
    for (int j = 0; j < 32; j++) {
        float lo, hi;
        unpack2(z2[j], lo, hi);
        F = __fadd_rn(F, __fmul_rn(lo, lo));
        F = __fadd_rn(F, __fmul_rn(hi, hi));
        g_z2[j * NPIX + n] = z2[j];
    }
    g_F[n] = F;
}

// -------------------------------- K2: persistent mma.sync distance GEMM
#define A_OFF    1024
#define B_OFF    33792
#define CKS_OFF  164864
#define SARG_OFF 166912
#define SACC_OFF 167424
#define MMA_SMEM 167936

__global__ void __launch_bounds__(256, 1)
k_mma(const float* __restrict__ codebook, float* __restrict__ out)
{
    extern __shared__ char smb[];
    const u32 sb   = smem_u32(smb);
    float* s_ck    = (float*)(smb + CKS_OFF);
    int*   s_arg   = (int*)(smb + SARG_OFF);
    float* s_acc   = (float*)(smb + SACC_OFF);

    const int tid  = threadIdx.x;
    const int wid  = tid >> 5;
    const int lane = tid & 31;

    for (int i = tid; i < NK; i += 256) s_ck[i] = g_ck[i];

    // stage B^T once per CTA: 2 splits x 512 rows x 32 u32
    #pragma unroll 4
    for (int it = 0; it < 128; it++) {
        int idx = it * 256 + tid;
        int s   = idx >> 14;
        int rem = idx & 16383;
        int j   = rem >> 9;
        int k   = rem & 511;
        u32 v = __ldg(&g_bs2[s * (32 * NK) + j * NK + k]);
        *(u32*)(smb + B_OFF + s * 65536 + sw128(k * 128 + j * 4)) = v;
    }

    const int gr = lane >> 2;        // row in group (0..7)
    const int gc = (lane & 3) * 2;   // col pair base

    // hoist swizzled B offsets ONCE (chunk stride 8192 commutes with sw128)
    u32 ba0[8][2];
    #pragma unroll
    for (int nt = 0; nt < 8; nt++) {
        const int brow = nt * 8 + (lane & 7);
        ba0[nt][0] = sw128(brow * 128 + (lane >> 3) * 16);
        ba0[nt][1] = sw128(brow * 128 + 64 + (lane >> 3) * 16);
    }

    float lsum = 0.f;

    for (int tile = blockIdx.x; tile < NTILE; tile += NCTA) {
        const int n0 = tile * 128;

        // stage A with on-the-fly bf16 split (16 u64 loads/thread)
        #pragma unroll 4
        for (int it = 0; it < 16; it++) {
            int idx = it * 256 + tid;
            int j   = idx >> 7;
            int row = idx & 127;
            float lo, hi;
            unpack2(__ldg(&g_z2[j * NPIX + (n0 + row)]), lo, hi);
            u32 o0, o1;
            split_pair(lo, hi, o0, o1);
            u32 off = sw128(row * 128 + j * 4);
            *(u32*)(smb + A_OFF + off)         = o0;
            *(u32*)(smb + A_OFF + 16384 + off) = o1;
        }
        if (tid == 0) s_acc[0] = 0.f;
        __syncthreads();

        // A fragments: af[split][ktile][4]
        u32 af[2][4][4];
        {
            const int arow = wid * 16 + (lane & 15);
            #pragma unroll
            for (int s = 0; s < 2; s++)
                #pragma unroll
                for (int kt = 0; kt < 4; kt++) {
                    u32 addr = sb + A_OFF + s * 16384 +
                               sw128(arow * 128 + kt * 32 + (lane >> 4) * 16);
                    ldsm_x4(af[s][kt][0], af[s][kt][1], af[s][kt][2], af[s][kt][3], addr);
                }
        }

        const float F0 = g_F[n0 + wid * 16 + gr];
        const float F1 = g_F[n0 + wid * 16 + gr + 8];

        u64  best0 = ~0ull, best1 = ~0ull;
        float bd0 = 3.4e38f, sd0 = 3.4e38f, bd1 = 3.4e38f, sd1 = 3.4e38f;

        #pragma unroll 1
        for (int ch = 0; ch < 8; ch++) {
            const u32 choff = ch * 8192;

            float D[8][4];
            #pragma unroll
            for (int nt = 0; nt < 8; nt++) {
                D[nt][0] = 0.f; D[nt][1] = 0.f; D[nt][2] = 0.f; D[nt][3] = 0.f;
            }

            #pragma unroll
            for (int pass = 0; pass < 3; pass++) {
                const int as = (pass == 2) ? 1 : 0;   // (b0,b0),(b0,b1),(b1,b0)
                const int bs = (pass == 1) ? 1 : 0;
                const u32 bb = sb + B_OFF + bs * 65536 + choff;
                #pragma unroll
                for (int nt = 0; nt < 8; nt++) {
                    u32 p0, p1, p2, p3, q0, q1, q2, q3;
                    ldsm_x4(p0, p1, p2, p3, bb + ba0[nt][0]);
                    ldsm_x4(q0, q1, q2, q3, bb + ba0[nt][1]);
                    mma_bf16(D[nt], af[as][0], p0, p1);
                    mma_bf16(D[nt], af[as][1], p2, p3);
                    mma_bf16(D[nt], af[as][2], q0, q1);
                    mma_bf16(D[nt], af[as][3], q2, q3);
                }
            }

            // epilogue: dist = fl(F+C) - 2P; best + second-best
            #pragma unroll
            for (int nt = 0; nt < 8; nt++) {
                int c0 = ch * 64 + nt * 8 + gc;
                float C0 = s_ck[c0], C1 = s_ck[c0 + 1];
                float d00 = fmaf(-2.f, D[nt][0], __fadd_rn(F0, C0));
                float d01 = fmaf(-2.f, D[nt][1], __fadd_rn(F0, C1));
                float d10 = fmaf(-2.f, D[nt][2], __fadd_rn(F1, C0));
                float d11 = fmaf(-2.f, D[nt][3], __fadd_rn(F1, C1));
                u64 k00 = (((u64)__float_as_uint(d00)) << 32) | (u32)c0;
                u64 k01 = (((u64)__float_as_uint(d01)) << 32) | (u32)(c0 + 1);
                u64 k10 = (((u64)__float_as_uint(d10)) << 32) | (u32)c0;
                u64 k11 = (((u64)__float_as_uint(d11)) << 32) | (u32)(c0 + 1);
                if (k00 < best0) { sd0 = bd0; bd0 = d00; best0 = k00; } else sd0 = fminf(sd0, d00);
                if (k01 < best0) { sd0 = bd0; bd0 = d01; best0 = k01; } else sd0 = fminf(sd0, d01);
                if (k10 < best1) { sd1 = bd1; bd1 = d10; best1 = k10; } else sd1 = fminf(sd1, d10);
                if (k11 < best1) { sd1 = bd1; bd1 = d11; best1 = k11; } else sd1 = fminf(sd1, d11);
            }
        }

        // reduce across the 4 lanes sharing each row (best + second-best)
        #pragma unroll
        for (int m = 1; m <= 2; m <<= 1) {
            u64  ob0 = __shfl_xor_sync(0xffffffffu, best0, m);
            float obd0 = __shfl_xor_sync(0xffffffffu, bd0, m);
            float osd0 = __shfl_xor_sync(0xffffffffu, sd0, m);
            float loser0 = (ob0 < best0) ? bd0 : obd0;
            sd0 = fminf(fminf(sd0, osd0), loser0);
            if (ob0 < best0) { best0 = ob0; bd0 = obd0; }

            u64  ob1 = __shfl_xor_sync(0xffffffffu, best1, m);
            float obd1 = __shfl_xor_sync(0xffffffffu, bd1, m);
            float osd1 = __shfl_xor_sync(0xffffffffu, sd1, m);
            float loser1 = (ob1 < best1) ? bd1 : obd1;
            sd1 = fminf(fminf(sd1, osd1), loser1);
            if (ob1 < best1) { best1 = ob1; bd1 = obd1; }
        }
        if ((lane & 3) == 0) {
            const int r0 = wid * 16 + gr;
            const int r1 = r0 + 8;
            const int bk0 = (int)(best0 & 0xffffffffu);
            const int bk1 = (int)(best1 & 0xffffffffu);
            s_arg[r0] = bk0;
            s_arg[r1] = bk1;
            g_idx[n0 + r0] = bk0;
            g_idx[n0 + r1] = bk1;
            out[OUT_IDX_OFF + n0 + r0] = (float)bk0;
            out[OUT_IDX_OFF + n0 + r1] = (float)bk1;
            atomicAdd(&g_counts[bk0], 1);
            atomicAdd(&g_counts[bk1], 1);
            if (sd0 - bd0 < EPS_GAP) {
                int pos = atomicAdd(&g_flag_count, 1);
                g_flag[pos] = n0 + r0;
            }
            if (sd1 - bd1 < EPS_GAP) {
                int pos = atomicAdd(&g_flag_count, 1);
                g_flag[pos] = n0 + r1;
            }
        }
        __syncthreads();   // s_arg + s_acc=0 visible

        // loss partials (threads 0-127, one pixel each; op order as prior rounds)
        float lp = 0.f;
        if (tid < 128) {
            const int n  = n0 + tid;
            const int bk = s_arg[tid];
            const float4* cbrow = (const float4*)(codebook + bk * 64);
            #pragma unroll
            for (int j4 = 0; j4 < 16; j4++) {
                float4 c4 = __ldg(&cbrow[j4]);
                float lo0, hi0, lo1, hi1;
                unpack2(g_z2[(2 * j4) * NPIX + n], lo0, hi0);
                unpack2(g_z2[(2 * j4 + 1) * NPIX + n], lo1, hi1);
                float d0 = __fadd_rn(c4.x, -lo0);
                float d1 = __fadd_rn(c4.y, -hi0);
                float d2 = __fadd_rn(c4.z, -lo1);
                float d3 = __fadd_rn(c4.w, -hi1);
                lp = fmaf(d0, d0, lp);
                lp = fmaf(d1, d1, lp);
                lp = fmaf(d2, d2, lp);
                lp = fmaf(d3, d3, lp);
            }
        }
        #pragma unroll
        for (int m = 16; m > 0; m >>= 1)
            lp += __shfl_xor_sync(0xffffffffu, lp, m);
        if (lane == 0 && wid < 4) atomicAdd(s_acc, lp);
        __syncthreads();   // s_acc complete; next tile may restage A/s_arg

        if (tid == 0) lsum += s_acc[0];
    }

    if (tid == 0) g_partials[blockIdx.x] = lsum;
}

// ------------------------- K2b: exact fp32 rescue of flagged pixels
#define RESC_SMEM ((32768 + 512) * 4)
__global__ void __launch_bounds__(256, 1)
k_rescue(const float* __restrict__ codebook, float* __restrict__ out)
{
    const int count = g_flag_count;
    if (blockIdx.x * 256 >= count) return;

    extern __shared__ float rsm[];
    float* cb = rsm;           // [k*64+d]
    float* ck = rsm + 32768;

    const int tid = threadIdx.x;
    for (int i = tid; i < NK * ND; i += 256) cb[i] = codebook[i];
    for (int i = tid; i < NK; i += 256) ck[i] = g_ck[i];
    __syncthreads();

    for (int i = blockIdx.x * 256 + tid; i < count; i += gridDim.x * 256) {
        const int n = g_flag[i];
        const float F = g_F[n];

        u64 z2[32];
        #pragma unroll
        for (int j = 0; j < 32; j++) z2[j] = g_z2[j * NPIX + n];

        // bit-exact R6 scan: a0 even pairs, a1 odd pairs, strict-< tiebreak
        float best = 3.4e38f;
        int   bk   = 0;
        for (int k = 0; k < NK; k++) {
            const ulonglong2* c2 = (const ulonglong2*)(cb + k * 64);
            u64 a0 = 0ull, a1 = 0ull;
            #pragma unroll
            for (int j = 0; j < 16; j++) {
                ulonglong2 cc = c2[j];
                a0 = ffma2(z2[2 * j],     cc.x, a0);
                a1 = ffma2(z2[2 * j + 1], cc.y, a1);
            }
            float lo, hi;
            unpack2(fadd2(a0, a1), lo, hi);
            float P = __fadd_rn(lo, hi);
            float dist = fmaf(-2.f, P, __fadd_rn(F, ck[k]));
            if (dist < best) { best = dist; bk = k; }
        }

        const int old = g_idx[n];
        if (bk != old) {
            g_idx[n] = bk;
            out[OUT_IDX_OFF + n] = (float)bk;
            atomicAdd(&g_counts[bk], 1);
            atomicAdd(&g_counts[old], -1);

            float lps[2];
            int   ks[2] = {old, bk};
            #pragma unroll
            for (int v = 0; v < 2; v++) {
                float lp = 0.f;
                const float4* cbrow = (const float4*)(codebook + ks[v] * 64);
                #pragma unroll
                for (int j4 = 0; j4 < 16; j4++) {
                    float4 c4 = __ldg(&cbrow[j4]);
                    float lo0, hi0, lo1, hi1;
                    unpack2(z2[2 * j4], lo0, hi0);
                    unpack2(z2[2 * j4 + 1], lo1, hi1);
                    float d0 = __fadd_rn(c4.x, -lo0);
                    float d1 = __fadd_rn(c4.y, -hi0);
                    float d2 = __fadd_rn(c4.z, -lo1);
                    float d3 = __fadd_rn(c4.w, -hi1);
                    lp = fmaf(d0, d0, lp);
                    lp = fmaf(d1, d1, lp);
                    lp = fmaf(d2, d2, lp);
                    lp = fmaf(d3, d3, lp);
                }
                lps[v] = lp;
            }
            atomicAdd(&g_loss_delta, (double)(lps[1] - lps[0]));
        }
    }
}

// ----------------------------------------- K3: decode table (transposed [o][k])
__global__ void k_table(const float* __restrict__ codebook,
                        const float* __restrict__ post_w,
                        const float* __restrict__ post_b)
{
    __shared__ float cbr[64];
    const int k = blockIdx.x;
    const int o = threadIdx.x;
    if (o < 64) cbr[o] = codebook[k * 64 + o];
    __syncthreads();
    float s = 0.f;
    const float* w = post_w + o * 64;
    #pragma unroll
    for (int d = 0; d < 64; d++) s = fmaf(cbr[d], __ldg(&w[d]), s);
    g_table_T[o * NK + k] = __fadd_rn(s, __ldg(&post_b[o]));
}

// ----------------------------------------- K4: gather -> global_decode
__global__ void __launch_bounds__(256)
k_decode(float* __restrict__ out)
{
    __shared__ float s_tab[NK];
    const int blk = blockIdx.x;       // 0..4095
    const int b   = blk >> 7;
    const int o   = blk & 127;
    const int tid = threadIdx.x;

    s_tab[tid]       = g_table_T[o * NK + tid];
    s_tab[tid + 256] = g_table_T[o * NK + tid + 256];
    __syncthreads();

    const int* idx = g_idx + b * NHW;
    float* dst = out + OUT_DECODE_OFF + ((size_t)(b * NC + o)) * NHW;

    if (tid < 3)       dst[tid]  = s_tab[idx[tid]];
    else if (tid == 3) dst[4095] = s_tab[idx[4095]];

    float4* dst4 = (float4*)(dst + 3);   // 16B aligned
    #pragma unroll 2
    for (int i = tid; i < 1023; i += 256) {
        const int base = 3 + 4 * i;
        float4 v;
        v.x = s_tab[idx[base + 0]];
        v.y = s_tab[idx[base + 1]];
        v.z = s_tab[idx[base + 2]];
        v.w = s_tab[idx[base + 3]];
        dst4[i] = v;
    }
}

// ----------------------------------------- K5: loss + perplexity
__global__ void k_final(float* __restrict__ out)
{
    __shared__ float sh[512];
    const int t = threadIdx.x;  // 512 threads

    float p = (float)g_counts[t] / (float)NPIX;
    sh[t] = -(p * logf(p + 1e-10f));
    __syncthreads();
    #pragma unroll
    for (int s = 256; s > 0; s >>= 1) {
        if (t < s) sh[t] += sh[t + s];
        __syncthreads();
    }
    if (t == 0) out[OUT_PERP_OFF] = expf(sh[0]);
    __syncthreads();

    sh[t] = (t < NCTA) ? g_partials[t] : 0.f;
    __syncthreads();
    #pragma unroll
    for (int s = 256; s > 0; s >>= 1) {
        if (t < s) sh[t] += sh[t + s];
        __syncthreads();
    }
    if (t == 0)
        out[0] = 1.25f * ((sh[0] + (float)g_loss_delta) / 8388608.f);
}

// ---------------------------------------------------------------- launch
extern "C" void kernel_launch(void* const* d_in, const int* in_sizes, int n_in,
                              void* d_out, int out_size)
{
    const float* enc      = (const float*)d_in[0];
    const float* pre_w    = (const float*)d_in[1];
    const float* pre_b    = (const float*)d_in[2];
    const float* codebook = (const float*)d_in[3];
    const float* post_w   = (const float*)d_in[4];
    const float* post_b   = (const float*)d_in[5];
    float* out = (float*)d_out;

    cudaFuncSetAttribute(k_pre, cudaFuncAttributeMaxDynamicSharedMemorySize, 32768);
    cudaFuncSetAttribute(k_mma, cudaFuncAttributeMaxDynamicSharedMemorySize, MMA_SMEM);
    cudaFuncSetAttribute(k_rescue, cudaFuncAttributeMaxDynamicSharedMemorySize, RESC_SMEM);

    k_zero  <<<1, 512>>>(codebook);                            // + codebook prep
    k_pre   <<<NPIX / 256, 256, 32768>>>(enc, pre_w, pre_b);   // 2 CTAs/SM
    k_mma   <<<NCTA, 256, MMA_SMEM>>>(codebook, out);
    k_rescue<<<NCTA, 256, RESC_SMEM>>>(codebook, out);         // ncu capture slot
    k_table <<<NK, 128>>>(codebook, post_w, post_b);
    k_decode<<<NB * NC, 256>>>(out);
    k_final <<<1, 512>>>(out);
}

// round 15
// speedup vs baseline: 1.4452x; 1.1074x over previous
#include <cuda_runtime.h>
#include <cuda_bf16.h>
#include <math.h>

// Problem constants
#define NB   32
#define NC   128      // NUM_HIDDENS
#define NHW  4096     // H*W
#define NPIX 131072   // B*H*W
#define ND   64       // EMB_DIM
#define NK   512      // NUM_EMB

// Output layout (float32, concatenated):
#define OUT_DECODE_OFF 1
#define OUT_PERP_OFF   16777217
#define OUT_IDX_OFF    16777218

typedef unsigned long long u64;
typedef unsigned int u32;

#define EPS_GAP  3e-5f
#define NCTA     148
#define NTILE    1024      // NPIX / 128

// Scratch (no allocations allowed)
__device__ __align__(16) int   g_idx[NPIX];
__device__ int    g_counts[NK];
__device__ float  g_partials[NCTA];
__device__ float  g_table_T[NC * NK];      // decode table transposed [o][k]
__device__ u64    g_z2[32 * NPIX];         // z fp32 pairs, [j][n]
__device__ u32    g_bs2[2 * 32 * NK];      // codebook bf16x2 splits
__device__ float  g_F[NPIX];
__device__ float  g_ck[NK];
__device__ int    g_flag[NPIX];            // pixels needing exact rescue
__device__ int    g_flag_count;
__device__ double g_loss_delta;

// ---- packed f32x2 helpers ----
__device__ __forceinline__ u64 ffma2(u64 a, u64 b, u64 c) {
    u64 d;
    asm("fma.rn.f32x2 %0, %1, %2, %3;" : "=l"(d) : "l"(a), "l"(b), "l"(c));
    return d;
}
__device__ __forceinline__ u64 fadd2(u64 a, u64 b) {
    u64 d;
    asm("add.rn.f32x2 %0, %1, %2;" : "=l"(d) : "l"(a), "l"(b));
    return d;
}
__device__ __forceinline__ u64 pack2(float lo, float hi) {
    u64 d;
    asm("mov.b64 %0, {%1, %2};" : "=l"(d) : "f"(lo), "f"(hi));
    return d;
}
__device__ __forceinline__ void unpack2(u64 v, float& lo, float& hi) {
    asm("mov.b64 {%0, %1}, %2;" : "=f"(lo), "=f"(hi) : "l"(v));
}

__device__ __forceinline__ u32 smem_u32(const void* p) {
    u32 a;
    asm("{ .reg .u64 t; cvta.to.shared.u64 t, %1; cvt.u32.u64 %0, t; }"
        : "=r"(a) : "l"(p));
    return a;
}

// SW128 swizzle (Swizzle<3,4,3>)
__device__ __forceinline__ u32 sw128(u32 off) { return off ^ ((off >> 3) & 0x70); }

// ---- warp-level MMA primitives (baseline PTX, legal on sm_103) ----
__device__ __forceinline__ void ldsm_x4(u32& r0, u32& r1, u32& r2, u32& r3, u32 addr) {
    asm volatile("ldmatrix.sync.aligned.m8n8.x4.shared.b16 {%0,%1,%2,%3}, [%4];"
                 : "=r"(r0), "=r"(r1), "=r"(r2), "=r"(r3) : "r"(addr));
}
__device__ __forceinline__ void mma_bf16(float* d, const u32* a, u32 b0, u32 b1) {
    asm volatile(
        "mma.sync.aligned.m16n8k16.row.col.f32.bf16.bf16.f32 "
        "{%0,%1,%2,%3}, {%4,%5,%6,%7}, {%8,%9}, {%0,%1,%2,%3};"
        : "+f"(d[0]), "+f"(d[1]), "+f"(d[2]), "+f"(d[3])
        : "r"(a[0]), "r"(a[1]), "r"(a[2]), "r"(a[3]), "r"(b0), "r"(b1));
}

// bf16x2 split of an fp32 pair (identical op sequence everywhere it's used)
__device__ __forceinline__ void split_pair(float lo, float hi, u32& o0, u32& o1) {
    float2 f = make_float2(lo, hi);
    __nv_bfloat162 b0 = __float22bfloat162_rn(f);
    float2 f0 = __bfloat1622float2(b0);
    float2 r  = make_float2(f.x - f0.x, f.y - f0.y);
    __nv_bfloat162 b1 = __float22bfloat162_rn(r);
    o0 = *reinterpret_cast<u32*>(&b0);
    o1 = *reinterpret_cast<u32*>(&b1);
}

// ------------------------- K0: zero + codebook prep (merged, 512 threads)
__global__ void k_zero(const float* __restrict__ codebook) {
    const int k = threadIdx.x;
    g_counts[k] = 0;
    if (k == 0) { g_flag_count = 0; g_loss_delta = 0.0; }

    float s = 0.f;
    #pragma unroll 8
    for (int d = 0; d < ND; d++) {
        float v = __ldg(&codebook[k * 64 + d]);
        s = __fadd_rn(s, __fmul_rn(v, v));
    }
    g_ck[k] = s;

    #pragma unroll
    for (int j = 0; j < 32; j++) {
        u32 o0, o1;
        split_pair(__ldg(&codebook[k * 64 + 2 * j]),
                   __ldg(&codebook[k * 64 + 2 * j + 1]), o0, o1);
        g_bs2[0 * (32 * NK) + j * NK + k] = o0;
        g_bs2[1 * (32 * NK) + j * NK + k] = o1;
    }
}

// --------------------------------- nops: aim ncu capture at k_pre
__global__ void k_nop() {}

// -------------------------------- K1: pre-conv -> z (fp32 pairs) + F
__global__ void __launch_bounds__(256, 2)
k_pre(const float* __restrict__ enc,
      const float* __restrict__ pre_w,
      const float* __restrict__ pre_b)
{
    extern __shared__ float pw[];   // [c*64+o], 8192 floats

    const int tid = threadIdx.x;
    for (int i = tid; i < NC * ND; i += 256) {
        int o = i >> 7, c = i & 127;
        pw[c * 64 + o] = pre_w[i];
    }
    __syncthreads();

    const int n  = blockIdx.x * 256 + tid;
    const int b  = n >> 12;
    const int hw = n & 4095;
    const float* ep = enc + (size_t)b * (NC * NHW) + hw;

    u64 z2[32];
    #pragma unroll
    for (int j = 0; j < 32; j++) z2[j] = 0ull;

    #pragma unroll 1
    for (int c = 0; c < NC; c += 4) {
        float e0 = ep[(size_t)(c + 0) * NHW];
        float e1 = ep[(size_t)(c + 1) * NHW];
        float e2 = ep[(size_t)(c + 2) * NHW];
        float e3 = ep[(size_t)(c + 3) * NHW];
        u64 ee0 = pack2(e0, e0), ee1 = pack2(e1, e1);
        u64 ee2 = pack2(e2, e2), ee3 = pack2(e3, e3);
        const ulonglong2* w0 = (const ulonglong2*)(pw + (c + 0) * 64);
        const ulonglong2* w1 = (const ulonglong2*)(pw + (c + 1) * 64);
        const ulonglong2* w2 = (const ulonglong2*)(pw + (c + 2) * 64);
        const ulonglong2* w3 = (const ulonglong2*)(pw + (c + 3) * 64);
        #pragma unroll
        for (int j = 0; j < 16; j++) {
            ulonglong2 a0 = w0[j];
            z2[2 * j]     = ffma2(ee0, a0.x, z2[2 * j]);
            z2[2 * j + 1] = ffma2(ee0, a0.y, z2[2 * j + 1]);
            ulonglong2 a1 = w1[j];
            z2[2 * j]     = ffma2(ee1, a1.x, z2[2 * j]);
            z2[2 * j + 1] = ffma2(ee1, a1.y, z2[2 * j + 1]);
            ulonglong2 a2 = w2[j];
            z2[2 * j]     = ffma2(ee2, a2.x, z2[2 * j]);
            z2[2 * j + 1] = ffma2(ee2, a2.y, z2[2 * j + 1]);
            ulonglong2 a3 = w3[j];
            z2[2 * j]     = ffma2(ee3, a3.x, z2[2 * j]);
            z2[2 * j + 1] = ffma2(ee3, a3.y, z2[2 * j + 1]);
        }
    }
    {
        const u64* pb2 = (const u64*)pre_b;
        #pragma unroll
        for (int j = 0; j < 32; j++) z2[j] = fadd2(z2[j], __ldg(&pb2[j]));
    }

    float F = 0.f;
    #pragma unroll
    for (int j = 0; j < 32; j++) {
        float lo, hi;
        unpack2(z2[j], lo, hi);
        F = __fadd_rn(F, __fmul_rn(lo, lo));
        F = __fadd_rn(F, __fmul_rn(hi, hi));
        g_z2[j * NPIX + n] = z2[j];
    }
    g_F[n] = F;
}

// -------------------------------- K2: persistent mma.sync distance GEMM
#define A_OFF    1024
#define B_OFF    33792
#define CKS_OFF  164864
#define SARG_OFF 166912
#define SACC_OFF 167424
#define MMA_SMEM 167936

__global__ void __launch_bounds__(256, 1)
k_mma(const float* __restrict__ codebook, float* __restrict__ out)
{
    extern __shared__ char smb[];
    const u32 sb   = smem_u32(smb);
    float* s_ck    = (float*)(smb + CKS_OFF);
    int*   s_arg   = (int*)(smb + SARG_OFF);
    float* s_acc   = (float*)(smb + SACC_OFF);

    const int tid  = threadIdx.x;
    const int wid  = tid >> 5;
    const int lane = tid & 31;

    for (int i = tid; i < NK; i += 256) s_ck[i] = g_ck[i];

    // stage B^T once per CTA: 2 splits x 512 rows x 32 u32
    #pragma unroll 4
    for (int it = 0; it < 128; it++) {
        int idx = it * 256 + tid;
        int s   = idx >> 14;
        int rem = idx & 16383;
        int j   = rem >> 9;
        int k   = rem & 511;
        u32 v = __ldg(&g_bs2[s * (32 * NK) + j * NK + k]);
        *(u32*)(smb + B_OFF + s * 65536 + sw128(k * 128 + j * 4)) = v;
    }

    const int gr = lane >> 2;        // row in group (0..7)
    const int gc = (lane & 3) * 2;   // col pair base

    u32 ba0[8][2];
    #pragma unroll
    for (int nt = 0; nt < 8; nt++) {
        const int brow = nt * 8 + (lane & 7);
        ba0[nt][0] = sw128(brow * 128 + (lane >> 3) * 16);
        ba0[nt][1] = sw128(brow * 128 + 64 + (lane >> 3) * 16);
    }

    float lsum = 0.f;

    for (int tile = blockIdx.x; tile < NTILE; tile += NCTA) {
        const int n0 = tile * 128;

        // stage A with on-the-fly bf16 split (16 u64 loads/thread)
        #pragma unroll 4
        for (int it = 0; it < 16; it++) {
            int idx = it * 256 + tid;
            int j   = idx >> 7;
            int row = idx & 127;
            float lo, hi;
            unpack2(__ldg(&g_z2[j * NPIX + (n0 + row)]), lo, hi);
            u32 o0, o1;
            split_pair(lo, hi, o0, o1);
            u32 off = sw128(row * 128 + j * 4);
            *(u32*)(smb + A_OFF + off)         = o0;
            *(u32*)(smb + A_OFF + 16384 + off) = o1;
        }
        if (tid == 0) s_acc[0] = 0.f;
        __syncthreads();

        // A fragments: af[split][ktile][4]
        u32 af[2][4][4];
        {
            const int arow = wid * 16 + (lane & 15);
            #pragma unroll
            for (int s = 0; s < 2; s++)
                #pragma unroll
                for (int kt = 0; kt < 4; kt++) {
                    u32 addr = sb + A_OFF + s * 16384 +
                               sw128(arow * 128 + kt * 32 + (lane >> 4) * 16);
                    ldsm_x4(af[s][kt][0], af[s][kt][1], af[s][kt][2], af[s][kt][3], addr);
                }
        }

        const float F0 = g_F[n0 + wid * 16 + gr];
        const float F1 = g_F[n0 + wid * 16 + gr + 8];

        u64  best0 = ~0ull, best1 = ~0ull;
        float bd0 = 3.4e38f, sd0 = 3.4e38f, bd1 = 3.4e38f, sd1 = 3.4e38f;

        #pragma unroll 1
        for (int ch = 0; ch < 8; ch++) {
            const u32 choff = ch * 8192;

            float D[8][4];
            #pragma unroll
            for (int nt = 0; nt < 8; nt++) {
                D[nt][0] = 0.f; D[nt][1] = 0.f; D[nt][2] = 0.f; D[nt][3] = 0.f;
            }

            #pragma unroll
            for (int pass = 0; pass < 3; pass++) {
                const int as = (pass == 2) ? 1 : 0;
                const int bs = (pass == 1) ? 1 : 0;
                const u32 bb = sb + B_OFF + bs * 65536 + choff;
                #pragma unroll
                for (int nt = 0; nt < 8; nt++) {
                    u32 p0, p1, p2, p3, q0, q1, q2, q3;
                    ldsm_x4(p0, p1, p2, p3, bb + ba0[nt][0]);
                    ldsm_x4(q0, q1, q2, q3, bb + ba0[nt][1]);
                    mma_bf16(D[nt], af[as][0], p0, p1);
                    mma_bf16(D[nt], af[as][1], p2, p3);
                    mma_bf16(D[nt], af[as][2], q0, q1);
                    mma_bf16(D[nt], af[as][3], q2, q3);
                }
            }

            #pragma unroll
            for (int nt = 0; nt < 8; nt++) {
                int c0 = ch * 64 + nt * 8 + gc;
                float C0 = s_ck[c0], C1 = s_ck[c0 + 1];
                float d00 = fmaf(-2.f, D[nt][0], __fadd_rn(F0, C0));
                float d01 = fmaf(-2.f, D[nt][1], __fadd_rn(F0, C1));
                float d10 = fmaf(-2.f, D[nt][2], __fadd_rn(F1, C0));
                float d11 = fmaf(-2.f, D[nt][3], __fadd_rn(F1, C1));
                u64 k00 = (((u64)__float_as_uint(d00)) << 32) | (u32)c0;
                u64 k01 = (((u64)__float_as_uint(d01)) << 32) | (u32)(c0 + 1);
                u64 k10 = (((u64)__float_as_uint(d10)) << 32) | (u32)c0;
                u64 k11 = (((u64)__float_as_uint(d11)) << 32) | (u32)(c0 + 1);
                if (k00 < best0) { sd0 = bd0; bd0 = d00; best0 = k00; } else sd0 = fminf(sd0, d00);
                if (k01 < best0) { sd0 = bd0; bd0 = d01; best0 = k01; } else sd0 = fminf(sd0, d01);
                if (k10 < best1) { sd1 = bd1; bd1 = d10; best1 = k10; } else sd1 = fminf(sd1, d10);
                if (k11 < best1) { sd1 = bd1; bd1 = d11; best1 = k11; } else sd1 = fminf(sd1, d11);
            }
        }

        #pragma unroll
        for (int m = 1; m <= 2; m <<= 1) {
            u64  ob0 = __shfl_xor_sync(0xffffffffu, best0, m);
            float obd0 = __shfl_xor_sync(0xffffffffu, bd0, m);
            float osd0 = __shfl_xor_sync(0xffffffffu, sd0, m);
            float loser0 = (ob0 < best0) ? bd0 : obd0;
            sd0 = fminf(fminf(sd0, osd0), loser0);
            if (ob0 < best0) { best0 = ob0; bd0 = obd0; }

            u64  ob1 = __shfl_xor_sync(0xffffffffu, best1, m);
            float obd1 = __shfl_xor_sync(0xffffffffu, bd1, m);
            float osd1 = __shfl_xor_sync(0xffffffffu, sd1, m);
            float loser1 = (ob1 < best1) ? bd1 : obd1;
            sd1 = fminf(fminf(sd1, osd1), loser1);
            if (ob1 < best1) { best1 = ob1; bd1 = obd1; }
        }
        if ((lane & 3) == 0) {
            const int r0 = wid * 16 + gr;
            const int r1 = r0 + 8;
            const int bk0 = (int)(best0 & 0xffffffffu);
            const int bk1 = (int)(best1 & 0xffffffffu);
            s_arg[r0] = bk0;
            s_arg[r1] = bk1;
            g_idx[n0 + r0] = bk0;
            g_idx[n0 + r1] = bk1;
            out[OUT_IDX_OFF + n0 + r0] = (float)bk0;
            out[OUT_IDX_OFF + n0 + r1] = (float)bk1;
            atomicAdd(&g_counts[bk0], 1);
            atomicAdd(&g_counts[bk1], 1);
            if (sd0 - bd0 < EPS_GAP) {
                int pos = atomicAdd(&g_flag_count, 1);
                g_flag[pos] = n0 + r0;
            }
            if (sd1 - bd1 < EPS_GAP) {
                int pos = atomicAdd(&g_flag_count, 1);
                g_flag[pos] = n0 + r1;
            }
        }
        __syncthreads();

        float lp = 0.f;
        if (tid < 128) {
            const int n  = n0 + tid;
            const int bk = s_arg[tid];
            const float4* cbrow = (const float4*)(codebook + bk * 64);
            #pragma unroll
            for (int j4 = 0; j4 < 16; j4++) {
                float4 c4 = __ldg(&cbrow[j4]);
                float lo0, hi0, lo1, hi1;
                unpack2(g_z2[(2 * j4) * NPIX + n], lo0, hi0);
                unpack2(g_z2[(2 * j4 + 1) * NPIX + n], lo1, hi1);
                float d0 = __fadd_rn(c4.x, -lo0);
                float d1 = __fadd_rn(c4.y, -hi0);
                float d2 = __fadd_rn(c4.z, -lo1);
                float d3 = __fadd_rn(c4.w, -hi1);
                lp = fmaf(d0, d0, lp);
                lp = fmaf(d1, d1, lp);
                lp = fmaf(d2, d2, lp);
                lp = fmaf(d3, d3, lp);
            }
        }
        #pragma unroll
        for (int m = 16; m > 0; m >>= 1)
            lp += __shfl_xor_sync(0xffffffffu, lp, m);
        if (lane == 0 && wid < 4) atomicAdd(s_acc, lp);
        __syncthreads();

        if (tid == 0) lsum += s_acc[0];
    }

    if (tid == 0) g_partials[blockIdx.x] = lsum;
}

// ------------------------- K2b: exact fp32 rescue, WARP-per-pixel
// Each warp owns one flagged pixel; lane scans k in [lane*16, lane*16+16)
// with the bit-identical per-k arithmetic; min over u64 keys == sequential
// strict-< first-index argmin.
#define RESC_SMEM ((32768 + 512) * 4)
__global__ void __launch_bounds__(256, 1)
k_rescue(const float* __restrict__ codebook, float* __restrict__ out)
{
    const int count = g_flag_count;

    extern __shared__ float rsm[];
    float* cb = rsm;           // [k*64+d]
    float* ck = rsm + 32768;

    const int tid  = threadIdx.x;
    const int wid  = tid >> 5;
    const int lane = tid & 31;

    if (blockIdx.x * 8 >= count) return;   // whole block idle

    for (int i = tid; i < NK * ND; i += 256) cb[i] = codebook[i];
    for (int i = tid; i < NK; i += 256) ck[i] = g_ck[i];
    __syncthreads();

    const int gw = blockIdx.x * 8 + wid;   // global warp id
    for (int i = gw; i < count; i += NCTA * 8) {
        const int n = g_flag[i];
        const float F = g_F[n];

        u64 z2[32];
        #pragma unroll
        for (int j = 0; j < 32; j++) z2[j] = g_z2[j * NPIX + n];

        // lane scans its 16-code slice (bit-identical per-k arithmetic)
        u64 bestkey = ~0ull;
        const int kbase = lane * 16;
        #pragma unroll 1
        for (int kk = 0; kk < 16; kk++) {
            const int k = kbase + kk;
            const ulonglong2* c2 = (const ulonglong2*)(cb + k * 64);
            u64 a0 = 0ull, a1 = 0ull;
            #pragma unroll
            for (int j = 0; j < 16; j++) {
                ulonglong2 cc = c2[j];
                a0 = ffma2(z2[2 * j],     cc.x, a0);
                a1 = ffma2(z2[2 * j + 1], cc.y, a1);
            }
            float lo, hi;
            unpack2(fadd2(a0, a1), lo, hi);
            float P = __fadd_rn(lo, hi);
            float dist = fmaf(-2.f, P, __fadd_rn(F, ck[k]));
            u64 key = (((u64)__float_as_uint(dist)) << 32) | (u32)k;
            if (key < bestkey) bestkey = key;
        }
        #pragma unroll
        for (int m = 16; m > 0; m >>= 1) {
            u64 o = __shfl_xor_sync(0xffffffffu, bestkey, m);
            if (o < bestkey) bestkey = o;
        }
        const int bk = (int)(bestkey & 0xffffffffu);

        if (lane == 0) {
            const int old = g_idx[n];
            if (bk != old) {
                g_idx[n] = bk;
                out[OUT_IDX_OFF + n] = (float)bk;
                atomicAdd(&g_counts[bk], 1);
                atomicAdd(&g_counts[old], -1);

                float lps[2];
                int   ks[2] = {old, bk};
                #pragma unroll
                for (int v = 0; v < 2; v++) {
                    float lp = 0.f;
                    const float4* cbrow = (const float4*)(codebook + ks[v] * 64);
                    #pragma unroll
                    for (int j4 = 0; j4 < 16; j4++) {
                        float4 c4 = __ldg(&cbrow[j4]);
                        float lo0, hi0, lo1, hi1;
                        unpack2(z2[2 * j4], lo0, hi0);
                        unpack2(z2[2 * j4 + 1], lo1, hi1);
                        float d0 = __fadd_rn(c4.x, -lo0);
                        float d1 = __fadd_rn(c4.y, -hi0);
                        float d2 = __fadd_rn(c4.z, -lo1);
                        float d3 = __fadd_rn(c4.w, -hi1);
                        lp = fmaf(d0, d0, lp);
                        lp = fmaf(d1, d1, lp);
                        lp = fmaf(d2, d2, lp);
                        lp = fmaf(d3, d3, lp);
                    }
                    lps[v] = lp;
                }
                atomicAdd(&g_loss_delta, (double)(lps[1] - lps[0]));
            }
        }
    }
}

// ----------------------------------------- K3: decode table (transposed [o][k])
__global__ void k_table(const float* __restrict__ codebook,
                        const float* __restrict__ post_w,
                        const float* __restrict__ post_b)
{
    __shared__ float cbr[64];
    const int k = blockIdx.x;
    const int o = threadIdx.x;
    if (o < 64) cbr[o] = codebook[k * 64 + o];
    __syncthreads();
    float s = 0.f;
    const float* w = post_w + o * 64;
    #pragma unroll
    for (int d = 0; d < 64; d++) s = fmaf(cbr[d], __ldg(&w[d]), s);
    g_table_T[o * NK + k] = __fadd_rn(s, __ldg(&post_b[o]));
}

// ----------------------------------------- K4: gather -> global_decode
__global__ void __launch_bounds__(256)
k_decode(float* __restrict__ out)
{
    __shared__ float s_tab[NK];
    const int blk = blockIdx.x;       // 0..4095
    const int b   = blk >> 7;
    const int o   = blk & 127;
    const int tid = threadIdx.x;

    s_tab[tid]       = g_table_T[o * NK + tid];
    s_tab[tid + 256] = g_table_T[o * NK + tid + 256];
    __syncthreads();

    const int* idx = g_idx + b * NHW;
    float* dst = out + OUT_DECODE_OFF + ((size_t)(b * NC + o)) * NHW;

    if (tid < 3)       dst[tid]  = s_tab[idx[tid]];
    else if (tid == 3) dst[4095] = s_tab[idx[4095]];

    float4* dst4 = (float4*)(dst + 3);   // 16B aligned
    #pragma unroll 2
    for (int i = tid; i < 1023; i += 256) {
        const int base = 3 + 4 * i;
        float4 v;
        v.x = s_tab[idx[base + 0]];
        v.y = s_tab[idx[base + 1]];
        v.z = s_tab[idx[base + 2]];
        v.w = s_tab[idx[base + 3]];
        dst4[i] = v;
    }
}

// ----------------------------------------- K5: loss + perplexity
__global__ void k_final(float* __restrict__ out)
{
    __shared__ float sh[512];
    const int t = threadIdx.x;  // 512 threads

    float p = (float)g_counts[t] / (float)NPIX;
    sh[t] = -(p * logf(p + 1e-10f));
    __syncthreads();
    #pragma unroll
    for (int s = 256; s > 0; s >>= 1) {
        if (t < s) sh[t] += sh[t + s];
        __syncthreads();
    }
    if (t == 0) out[OUT_PERP_OFF] = expf(sh[0]);
    __syncthreads();

    sh[t] = (t < NCTA) ? g_partials[t] : 0.f;
    __syncthreads();
    #pragma unroll
    for (int s = 256; s > 0; s >>= 1) {
        if (t < s) sh[t] += sh[t + s];
        __syncthreads();
    }
    if (t == 0)
        out[0] = 1.25f * ((sh[0] + (float)g_loss_delta) / 8388608.f);
}

// ---------------------------------------------------------------- launch
extern "C" void kernel_launch(void* const* d_in, const int* in_sizes, int n_in,
                              void* d_out, int out_size)
{
    const float* enc      = (const float*)d_in[0];
    const float* pre_w    = (const float*)d_in[1];
    const float* pre_b    = (const float*)d_in[2];
    const float* codebook = (const float*)d_in[3];
    const float* post_w   = (const float*)d_in[4];
    const float* post_b   = (const float*)d_in[5];
    float* out = (float*)d_out;

    cudaFuncSetAttribute(k_pre, cudaFuncAttributeMaxDynamicSharedMemorySize, 32768);
    cudaFuncSetAttribute(k_mma, cudaFuncAttributeMaxDynamicSharedMemorySize, MMA_SMEM);
    cudaFuncSetAttribute(k_rescue, cudaFuncAttributeMaxDynamicSharedMemorySize, RESC_SMEM);

    k_zero  <<<1, 512>>>(codebook);
    k_nop   <<<1, 32>>>();   // aim ncu capture at k_pre
    k_nop   <<<1, 32>>>();
    k_pre   <<<NPIX / 256, 256, 32768>>>(enc, pre_w, pre_b);   // ncu capture slot
    k_mma   <<<NCTA, 256, MMA_SMEM>>>(codebook, out);
    k_rescue<<<NCTA, 256, RESC_SMEM>>>(codebook, out);
    k_table <<<NK, 128>>>(codebook, post_w, post_b);
    k_decode<<<NB * NC, 256>>>(out);
    k_final <<<1, 512>>>(out);
}

// round 16
// speedup vs baseline: 1.4893x; 1.0305x over previous
#include <cuda_runtime.h>
#include <cuda_bf16.h>
#include <math.h>

// Problem constants
#define NB   32
#define NC   128      // NUM_HIDDENS
#define NHW  4096     // H*W
#define NPIX 131072   // B*H*W
#define ND   64       // EMB_DIM
#define NK   512      // NUM_EMB

// Output layout (float32, concatenated):
#define OUT_DECODE_OFF 1
#define OUT_PERP_OFF   16777217
#define OUT_IDX_OFF    16777218

typedef unsigned long long u64;
typedef unsigned int u32;

#define EPS_GAP  3e-5f
#define NCTA     148
#define NTILE    1024      // NPIX / 128

// Scratch (no allocations allowed)
__device__ __align__(16) int   g_idx[NPIX];
__device__ int    g_counts[NK];
__device__ float  g_partials[NCTA];
__device__ float  g_table_T[NC * NK];      // decode table transposed [o][k]
__device__ u64    g_z2[32 * NPIX];         // z fp32 pairs, [j][n]
__device__ u32    g_bs2[2 * 32 * NK];      // codebook bf16x2 splits
__device__ float  g_F[NPIX];
__device__ float  g_ck[NK];
__device__ int    g_flag[NPIX];            // pixels needing exact rescue
__device__ int    g_flag_count;
__device__ double g_loss_delta;

// ---- packed f32x2 helpers ----
__device__ __forceinline__ u64 ffma2(u64 a, u64 b, u64 c) {
    u64 d;
    asm("fma.rn.f32x2 %0, %1, %2, %3;" : "=l"(d) : "l"(a), "l"(b), "l"(c));
    return d;
}
__device__ __forceinline__ u64 fadd2(u64 a, u64 b) {
    u64 d;
    asm("add.rn.f32x2 %0, %1, %2;" : "=l"(d) : "l"(a), "l"(b));
    return d;
}
__device__ __forceinline__ u64 pack2(float lo, float hi) {
    u64 d;
    asm("mov.b64 %0, {%1, %2};" : "=l"(d) : "f"(lo), "f"(hi));
    return d;
}
__device__ __forceinline__ void unpack2(u64 v, float& lo, float& hi) {
    asm("mov.b64 {%0, %1}, %2;" : "=f"(lo), "=f"(hi) : "l"(v));
}

__device__ __forceinline__ u32 smem_u32(const void* p) {
    u32 a;
    asm("{ .reg .u64 t; cvta.to.shared.u64 t, %1; cvt.u32.u64 %0, t; }"
        : "=r"(a) : "l"(p));
    return a;
}

// SW128 swizzle (Swizzle<3,4,3>)
__device__ __forceinline__ u32 sw128(u32 off) { return off ^ ((off >> 3) & 0x70); }

// ---- warp-level MMA primitives (baseline PTX, legal on sm_103) ----
__device__ __forceinline__ void ldsm_x4(u32& r0, u32& r1, u32& r2, u32& r3, u32 addr) {
    asm volatile("ldmatrix.sync.aligned.m8n8.x4.shared.b16 {%0,%1,%2,%3}, [%4];"
                 : "=r"(r0), "=r"(r1), "=r"(r2), "=r"(r3) : "r"(addr));
}
__device__ __forceinline__ void mma_bf16(float* d, const u32* a, u32 b0, u32 b1) {
    asm volatile(
        "mma.sync.aligned.m16n8k16.row.col.f32.bf16.bf16.f32 "
        "{%0,%1,%2,%3}, {%4,%5,%6,%7}, {%8,%9}, {%0,%1,%2,%3};"
        : "+f"(d[0]), "+f"(d[1]), "+f"(d[2]), "+f"(d[3])
        : "r"(a[0]), "r"(a[1]), "r"(a[2]), "r"(a[3]), "r"(b0), "r"(b1));
}

// bf16x2 split of an fp32 pair (identical op sequence everywhere it's used)
__device__ __forceinline__ void split_pair(float lo, float hi, u32& o0, u32& o1) {
    float2 f = make_float2(lo, hi);
    __nv_bfloat162 b0 = __float22bfloat162_rn(f);
    float2 f0 = __bfloat1622float2(b0);
    float2 r  = make_float2(f.x - f0.x, f.y - f0.y);
    __nv_bfloat162 b1 = __float22bfloat162_rn(r);
    o0 = *reinterpret_cast<u32*>(&b0);
    o1 = *reinterpret_cast<u32*>(&b1);
}

// ------------------------- K0: zero + codebook prep (merged, 512 threads)
__global__ void k_zero(const float* __restrict__ codebook) {
    const int k = threadIdx.x;
    g_counts[k] = 0;
    if (k == 0) { g_flag_count = 0; g_loss_delta = 0.0; }

    float s = 0.f;
    #pragma unroll 8
    for (int d = 0; d < ND; d++) {
        float v = __ldg(&codebook[k * 64 + d]);
        s = __fadd_rn(s, __fmul_rn(v, v));
    }
    g_ck[k] = s;

    #pragma unroll
    for (int j = 0; j < 32; j++) {
        u32 o0, o1;
        split_pair(__ldg(&codebook[k * 64 + 2 * j]),
                   __ldg(&codebook[k * 64 + 2 * j + 1]), o0, o1);
        g_bs2[0 * (32 * NK) + j * NK + k] = o0;
        g_bs2[1 * (32 * NK) + j * NK + k] = o1;
    }
}

// --------------------------------- nop: aim ncu capture at k_mma
__global__ void k_nop() {}

// -------------------------------- K1: pre-conv -> z (fp32 pairs) + F
// Software-pipelined enc loads: prefetch next 8-wide e-group before consuming
// the current one (DRAM latency overlaps the FFMA2 block). c-accumulation
// order into each z2[j] unchanged -> bit-identical z.
__global__ void __launch_bounds__(256, 2)
k_pre(const float* __restrict__ enc,
      const float* __restrict__ pre_w,
      const float* __restrict__ pre_b)
{
    extern __shared__ float pw[];   // [c*64+o], 8192 floats

    const int tid = threadIdx.x;
    for (int i = tid; i < NC * ND; i += 256) {
        int o = i >> 7, c = i & 127;
        pw[c * 64 + o] = pre_w[i];
    }
    __syncthreads();

    const int n  = blockIdx.x * 256 + tid;
    const int b  = n >> 12;
    const int hw = n & 4095;
    const float* ep = enc + (size_t)b * (NC * NHW) + hw;

    u64 z2[32];
    #pragma unroll
    for (int j = 0; j < 32; j++) z2[j] = 0ull;

    float eb[8];
    #pragma unroll
    for (int j = 0; j < 8; j++) eb[j] = ep[(size_t)j * NHW];

    #pragma unroll 1
    for (int c = 0; c < NC; c += 8) {
        // prefetch next group (overlaps with the FFMA2 block below)
        float en[8];
        if (c + 8 < NC) {
            #pragma unroll
            for (int j = 0; j < 8; j++) en[j] = ep[(size_t)(c + 8 + j) * NHW];
        }

        #pragma unroll
        for (int cc = 0; cc < 8; cc++) {
            u64 ee = pack2(eb[cc], eb[cc]);
            const ulonglong2* w2 = (const ulonglong2*)(pw + (c + cc) * 64);
            #pragma unroll
            for (int j = 0; j < 16; j++) {
                ulonglong2 w = w2[j];
                z2[2 * j]     = ffma2(ee, w.x, z2[2 * j]);
                z2[2 * j + 1] = ffma2(ee, w.y, z2[2 * j + 1]);
            }
        }

        #pragma unroll
        for (int j = 0; j < 8; j++) eb[j] = en[j];
    }
    {
        const u64* pb2 = (const u64*)pre_b;
        #pragma unroll
        for (int j = 0; j < 32; j++) z2[j] = fadd2(z2[j], __ldg(&pb2[j]));
    }

    float F = 0.f;
    #pragma unroll
    for (int j = 0; j < 32; j++) {
        float lo, hi;
        unpack2(z2[j], lo, hi);
        F = __fadd_rn(F, __fmul_rn(lo, lo));
        F = __fadd_rn(F, __fmul_rn(hi, hi));
        g_z2[j * NPIX + n] = z2[j];
    }
    g_F[n] = F;
}

// -------------------------------- K2: persistent mma.sync distance GEMM
#define A_OFF    1024
#define B_OFF    33792
#define CKS_OFF  164864
#define SARG_OFF 166912
#define SACC_OFF 167424
#define MMA_SMEM 167936

__global__ void __launch_bounds__(256, 1)
k_mma(const float* __restrict__ codebook, float* __restrict__ out)
{
    extern __shared__ char smb[];
    const u32 sb   = smem_u32(smb);
    float* s_ck    = (float*)(smb + CKS_OFF);
    int*   s_arg   = (int*)(smb + SARG_OFF);
    float* s_acc   = (float*)(smb + SACC_OFF);

    const int tid  = threadIdx.x;
    const int wid  = tid >> 5;
    const int lane = tid & 31;

    for (int i = tid; i < NK; i += 256) s_ck[i] = g_ck[i];

    // stage B^T once per CTA: 2 splits x 512 rows x 32 u32
    #pragma unroll 4
    for (int it = 0; it < 128; it++) {
        int idx = it * 256 + tid;
        int s   = idx >> 14;
        int rem = idx & 16383;
        int j   = rem >> 9;
        int k   = rem & 511;
        u32 v = __ldg(&g_bs2[s * (32 * NK) + j * NK + k]);
        *(u32*)(smb + B_OFF + s * 65536 + sw128(k * 128 + j * 4)) = v;
    }

    const int gr = lane >> 2;        // row in group (0..7)
    const int gc = (lane & 3) * 2;   // col pair base

    u32 ba0[8][2];
    #pragma unroll
    for (int nt = 0; nt < 8; nt++) {
        const int brow = nt * 8 + (lane & 7);
        ba0[nt][0] = sw128(brow * 128 + (lane >> 3) * 16);
        ba0[nt][1] = sw128(brow * 128 + 64 + (lane >> 3) * 16);
    }

    float lsum = 0.f;

    for (int tile = blockIdx.x; tile < NTILE; tile += NCTA) {
        const int n0 = tile * 128;

        // stage A with on-the-fly bf16 split (16 u64 loads/thread)
        #pragma unroll 4
        for (int it = 0; it < 16; it++) {
            int idx = it * 256 + tid;
            int j   = idx >> 7;
            int row = idx & 127;
            float lo, hi;
            unpack2(__ldg(&g_z2[j * NPIX + (n0 + row)]), lo, hi);
            u32 o0, o1;
            split_pair(lo, hi, o0, o1);
            u32 off = sw128(row * 128 + j * 4);
            *(u32*)(smb + A_OFF + off)         = o0;
            *(u32*)(smb + A_OFF + 16384 + off) = o1;
        }
        if (tid == 0) s_acc[0] = 0.f;
        __syncthreads();

        // A fragments: af[split][ktile][4]
        u32 af[2][4][4];
        {
            const int arow = wid * 16 + (lane & 15);
            #pragma unroll
            for (int s = 0; s < 2; s++)
                #pragma unroll
                for (int kt = 0; kt < 4; kt++) {
                    u32 addr = sb + A_OFF + s * 16384 +
                               sw128(arow * 128 + kt * 32 + (lane >> 4) * 16);
                    ldsm_x4(af[s][kt][0], af[s][kt][1], af[s][kt][2], af[s][kt][3], addr);
                }
        }

        const float F0 = g_F[n0 + wid * 16 + gr];
        const float F1 = g_F[n0 + wid * 16 + gr + 8];

        u64  best0 = ~0ull, best1 = ~0ull;
        float bd0 = 3.4e38f, sd0 = 3.4e38f, bd1 = 3.4e38f, sd1 = 3.4e38f;

        #pragma unroll 1
        for (int ch = 0; ch < 8; ch++) {
            const u32 choff = ch * 8192;

            float D[8][4];
            #pragma unroll
            for (int nt = 0; nt < 8; nt++) {
                D[nt][0] = 0.f; D[nt][1] = 0.f; D[nt][2] = 0.f; D[nt][3] = 0.f;
            }

            #pragma unroll
            for (int pass = 0; pass < 3; pass++) {
                const int as = (pass == 2) ? 1 : 0;
                const int bs = (pass == 1) ? 1 : 0;
                const u32 bb = sb + B_OFF + bs * 65536 + choff;
                #pragma unroll
                for (int nt = 0; nt < 8; nt++) {
                    u32 p0, p1, p2, p3, q0, q1, q2, q3;
                    ldsm_x4(p0, p1, p2, p3, bb + ba0[nt][0]);
                    ldsm_x4(q0, q1, q2, q3, bb + ba0[nt][1]);
                    mma_bf16(D[nt], af[as][0], p0, p1);
                    mma_bf16(D[nt], af[as][1], p2, p3);
                    mma_bf16(D[nt], af[as][2], q0, q1);
                    mma_bf16(D[nt], af[as][3], q2, q3);
                }
            }

            #pragma unroll
            for (int nt = 0; nt < 8; nt++) {
                int c0 = ch * 64 + nt * 8 + gc;
                float C0 = s_ck[c0], C1 = s_ck[c0 + 1];
                float d00 = fmaf(-2.f, D[nt][0], __fadd_rn(F0, C0));
                float d01 = fmaf(-2.f, D[nt][1], __fadd_rn(F0, C1));
                float d10 = fmaf(-2.f, D[nt][2], __fadd_rn(F1, C0));
                float d11 = fmaf(-2.f, D[nt][3], __fadd_rn(F1, C1));
                u64 k00 = (((u64)__float_as_uint(d00)) << 32) | (u32)c0;
                u64 k01 = (((u64)__float_as_uint(d01)) << 32) | (u32)(c0 + 1);
                u64 k10 = (((u64)__float_as_uint(d10)) << 32) | (u32)c0;
                u64 k11 = (((u64)__float_as_uint(d11)) << 32) | (u32)(c0 + 1);
                if (k00 < best0) { sd0 = bd0; bd0 = d00; best0 = k00; } else sd0 = fminf(sd0, d00);
                if (k01 < best0) { sd0 = bd0; bd0 = d01; best0 = k01; } else sd0 = fminf(sd0, d01);
                if (k10 < best1) { sd1 = bd1; bd1 = d10; best1 = k10; } else sd1 = fminf(sd1, d10);
                if (k11 < best1) { sd1 = bd1; bd1 = d11; best1 = k11; } else sd1 = fminf(sd1, d11);
            }
        }

        #pragma unroll
        for (int m = 1; m <= 2; m <<= 1) {
            u64  ob0 = __shfl_xor_sync(0xffffffffu, best0, m);
            float obd0 = __shfl_xor_sync(0xffffffffu, bd0, m);
            float osd0 = __shfl_xor_sync(0xffffffffu, sd0, m);
            float loser0 = (ob0 < best0) ? bd0 : obd0;
            sd0 = fminf(fminf(sd0, osd0), loser0);
            if (ob0 < best0) { best0 = ob0; bd0 = obd0; }

            u64  ob1 = __shfl_xor_sync(0xffffffffu, best1, m);
            float obd1 = __shfl_xor_sync(0xffffffffu, bd1, m);
            float osd1 = __shfl_xor_sync(0xffffffffu, sd1, m);
            float loser1 = (ob1 < best1) ? bd1 : obd1;
            sd1 = fminf(fminf(sd1, osd1), loser1);
            if (ob1 < best1) { best1 = ob1; bd1 = obd1; }
        }
        if ((lane & 3) == 0) {
            const int r0 = wid * 16 + gr;
            const int r1 = r0 + 8;
            const int bk0 = (int)(best0 & 0xffffffffu);
            const int bk1 = (int)(best1 & 0xffffffffu);
            s_arg[r0] = bk0;
            s_arg[r1] = bk1;
            g_idx[n0 + r0] = bk0;
            g_idx[n0 + r1] = bk1;
            out[OUT_IDX_OFF + n0 + r0] = (float)bk0;
            out[OUT_IDX_OFF + n0 + r1] = (float)bk1;
            atomicAdd(&g_counts[bk0], 1);
            atomicAdd(&g_counts[bk1], 1);
            if (sd0 - bd0 < EPS_GAP) {
                int pos = atomicAdd(&g_flag_count, 1);
                g_flag[pos] = n0 + r0;
            }
            if (sd1 - bd1 < EPS_GAP) {
                int pos = atomicAdd(&g_flag_count, 1);
                g_flag[pos] = n0 + r1;
            }
        }
        __syncthreads();

        float lp = 0.f;
        if (tid < 128) {
            const int n  = n0 + tid;
            const int bk = s_arg[tid];
            const float4* cbrow = (const float4*)(codebook + bk * 64);
            #pragma unroll
            for (int j4 = 0; j4 < 16; j4++) {
                float4 c4 = __ldg(&cbrow[j4]);
                float lo0, hi0, lo1, hi1;
                unpack2(g_z2[(2 * j4) * NPIX + n], lo0, hi0);
                unpack2(g_z2[(2 * j4 + 1) * NPIX + n], lo1, hi1);
                float d0 = __fadd_rn(c4.x, -lo0);
                float d1 = __fadd_rn(c4.y, -hi0);
                float d2 = __fadd_rn(c4.z, -lo1);
                float d3 = __fadd_rn(c4.w, -hi1);
                lp = fmaf(d0, d0, lp);
                lp = fmaf(d1, d1, lp);
                lp = fmaf(d2, d2, lp);
                lp = fmaf(d3, d3, lp);
            }
        }
        #pragma unroll
        for (int m = 16; m > 0; m >>= 1)
            lp += __shfl_xor_sync(0xffffffffu, lp, m);
        if (lane == 0 && wid < 4) atomicAdd(s_acc, lp);
        __syncthreads();

        if (tid == 0) lsum += s_acc[0];
    }

    if (tid == 0) g_partials[blockIdx.x] = lsum;
}

// ------------------------- K2b: exact fp32 rescue, WARP-per-pixel
#define RESC_SMEM ((32768 + 512) * 4)
__global__ void __launch_bounds__(256, 1)
k_rescue(const float* __restrict__ codebook, float* __restrict__ out)
{
    const int count = g_flag_count;

    extern __shared__ float rsm[];
    float* cb = rsm;           // [k*64+d]
    float* ck = rsm + 32768;

    const int tid  = threadIdx.x;
    const int wid  = tid >> 5;
    const int lane = tid & 31;

    if (blockIdx.x * 8 >= count) return;   // whole block idle

    for (int i = tid; i < NK * ND; i += 256) cb[i] = codebook[i];
    for (int i = tid; i < NK; i += 256) ck[i] = g_ck[i];
    __syncthreads();

    const int gw = blockIdx.x * 8 + wid;   // global warp id
    for (int i = gw; i < count; i += NCTA * 8) {
        const int n = g_flag[i];
        const float F = g_F[n];

        u64 z2[32];
        #pragma unroll
        for (int j = 0; j < 32; j++) z2[j] = g_z2[j * NPIX + n];

        u64 bestkey = ~0ull;
        const int kbase = lane * 16;
        #pragma unroll 1
        for (int kk = 0; kk < 16; kk++) {
            const int k = kbase + kk;
            const ulonglong2* c2 = (const ulonglong2*)(cb + k * 64);
            u64 a0 = 0ull, a1 = 0ull;
            #pragma unroll
            for (int j = 0; j < 16; j++) {
                ulonglong2 cc = c2[j];
                a0 = ffma2(z2[2 * j],     cc.x, a0);
                a1 = ffma2(z2[2 * j + 1], cc.y, a1);
            }
            float lo, hi;
            unpack2(fadd2(a0, a1), lo, hi);
            float P = __fadd_rn(lo, hi);
            float dist = fmaf(-2.f, P, __fadd_rn(F, ck[k]));
            u64 key = (((u64)__float_as_uint(dist)) << 32) | (u32)k;
            if (key < bestkey) bestkey = key;
        }
        #pragma unroll
        for (int m = 16; m > 0; m >>= 1) {
            u64 o = __shfl_xor_sync(0xffffffffu, bestkey, m);
            if (o < bestkey) bestkey = o;
        }
        const int bk = (int)(bestkey & 0xffffffffu);

        if (lane == 0) {
            const int old = g_idx[n];
            if (bk != old) {
                g_idx[n] = bk;
                out[OUT_IDX_OFF + n] = (float)bk;
                atomicAdd(&g_counts[bk], 1);
                atomicAdd(&g_counts[old], -1);

                float lps[2];
                int   ks[2] = {old, bk};
                #pragma unroll
                for (int v = 0; v < 2; v++) {
                    float lp = 0.f;
                    const float4* cbrow = (const float4*)(codebook + ks[v] * 64);
                    #pragma unroll
                    for (int j4 = 0; j4 < 16; j4++) {
                        float4 c4 = __ldg(&cbrow[j4]);
                        float lo0, hi0, lo1, hi1;
                        unpack2(z2[2 * j4], lo0, hi0);
                        unpack2(z2[2 * j4 + 1], lo1, hi1);
                        float d0 = __fadd_rn(c4.x, -lo0);
                        float d1 = __fadd_rn(c4.y, -hi0);
                        float d2 = __fadd_rn(c4.z, -lo1);
                        float d3 = __fadd_rn(c4.w, -hi1);
                        lp = fmaf(d0, d0, lp);
                        lp = fmaf(d1, d1, lp);
                        lp = fmaf(d2, d2, lp);
                        lp = fmaf(d3, d3, lp);
                    }
                    lps[v] = lp;
                }
                atomicAdd(&g_loss_delta, (double)(lps[1] - lps[0]));
            }
        }
    }
}

// ----------------------------------------- K3: decode table (transposed [o][k])
__global__ void k_table(const float* __restrict__ codebook,
                        const float* __restrict__ post_w,
                        const float* __restrict__ post_b)
{
    __shared__ float cbr[64];
    const int k = blockIdx.x;
    const int o = threadIdx.x;
    if (o < 64) cbr[o] = codebook[k * 64 + o];
    __syncthreads();
    float s = 0.f;
    const float* w = post_w + o * 64;
    #pragma unroll
    for (int d = 0; d < 64; d++) s = fmaf(cbr[d], __ldg(&w[d]), s);
    g_table_T[o * NK + k] = __fadd_rn(s, __ldg(&post_b[o]));
}

// ----------------------------------------- K4: gather -> global_decode
__global__ void __launch_bounds__(256)
k_decode(float* __restrict__ out)
{
    __shared__ float s_tab[NK];
    const int blk = blockIdx.x;       // 0..4095
    const int b   = blk >> 7;
    const int o   = blk & 127;
    const int tid = threadIdx.x;

    s_tab[tid]       = g_table_T[o * NK + tid];
    s_tab[tid + 256] = g_table_T[o * NK + tid + 256];
    __syncthreads();

    const int* idx = g_idx + b * NHW;
    float* dst = out + OUT_DECODE_OFF + ((size_t)(b * NC + o)) * NHW;

    if (tid < 3)       dst[tid]  = s_tab[idx[tid]];
    else if (tid == 3) dst[4095] = s_tab[idx[4095]];

    float4* dst4 = (float4*)(dst + 3);   // 16B aligned
    #pragma unroll 2
    for (int i = tid; i < 1023; i += 256) {
        const int base = 3 + 4 * i;
        float4 v;
        v.x = s_tab[idx[base + 0]];
        v.y = s_tab[idx[base + 1]];
        v.z = s_tab[idx[base + 2]];
        v.w = s_tab[idx[base + 3]];
        dst4[i] = v;
    }
}

// ----------------------------------------- K5: loss + perplexity
__global__ void k_final(float* __restrict__ out)
{
    __shared__ float sh[512];
    const int t = threadIdx.x;  // 512 threads

    float p = (float)g_counts[t] / (float)NPIX;
    sh[t] = -(p * logf(p + 1e-10f));
    __syncthreads();
    #pragma unroll
    for (int s = 256; s > 0; s >>= 1) {
        if (t < s) sh[t] += sh[t + s];
        __syncthreads();
    }
    if (t == 0) out[OUT_PERP_OFF] = expf(sh[0]);
    __syncthreads();

    sh[t] = (t < NCTA) ? g_partials[t] : 0.f;
    __syncthreads();
    #pragma unroll
    for (int s = 256; s > 0; s >>= 1) {
        if (t < s) sh[t] += sh[t + s];
        __syncthreads();
    }
    if (t == 0)
        out[0] = 1.25f * ((sh[0] + (float)g_loss_delta) / 8388608.f);
}

// ---------------------------------------------------------------- launch
extern "C" void kernel_launch(void* const* d_in, const int* in_sizes, int n_in,
                              void* d_out, int out_size)
{
    const float* enc      = (const float*)d_in[0];
    const float* pre_w    = (const float*)d_in[1];
    const float* pre_b    = (const float*)d_in[2];
    const float* codebook = (const float*)d_in[3];
    const float* post_w   = (const float*)d_in[4];
    const float* post_b   = (const float*)d_in[5];
    float* out = (float*)d_out;

    cudaFuncSetAttribute(k_pre, cudaFuncAttributeMaxDynamicSharedMemorySize, 32768);
    cudaFuncSetAttribute(k_mma, cudaFuncAttributeMaxDynamicSharedMemorySize, MMA_SMEM);
    cudaFuncSetAttribute(k_rescue, cudaFuncAttributeMaxDynamicSharedMemorySize, RESC_SMEM);

    k_zero  <<<1, 512>>>(codebook);
    k_nop   <<<1, 32>>>();   // aim ncu capture at k_mma
    k_pre   <<<NPIX / 256, 256, 32768>>>(enc, pre_w, pre_b);
    k_mma   <<<NCTA, 256, MMA_SMEM>>>(codebook, out);          // ncu capture slot
    k_rescue<<<NCTA, 256, RESC_SMEM>>>(codebook, out);
    k_table <<<NK, 128>>>(codebook, post_w, post_b);
    k_decode<<<NB * NC, 256>>>(out);
    k_final <<<1, 512>>>(out);
}